// round 3
// baseline (speedup 1.0000x reference)
#include <cuda_runtime.h>
#include <math.h>

// Problem constants (fixed by the dataset: B=256, D=H=512, lengths=128..383)
#define NN 65408      // total flat timesteps
#define BP 256        // persons
#define DD 512        // input dim
#define HH 512        // hidden dim
#define GG 2048       // 4*H gate dim
#define TT 383        // max sequence length

// ---------------- device scratch (static: no allocation in kernel_launch) ---
// 16B alignment is REQUIRED: these are accessed via float4.
__device__ __align__(16) float g_xW[(size_t)NN * GG];   // input contribution to gates
__device__ __align__(16) float g_flat[(size_t)NN * HH]; // flat valid LSTM outputs
__device__ __align__(16) float g_h[BP * HH];
__device__ __align__(16) float g_c[BP * HH];
__device__ __align__(16) float g_att[NN];
__device__ __align__(16) float g_seg[BP * HH];
__device__ int   g_off[BP];

__device__ __forceinline__ float sigf(float x) { return 1.0f / (1.0f + expf(-x)); }

// ---------------- init: zero states + exclusive-scan offsets ----------------
__global__ void k_init(const int* __restrict__ lengths) {
    int tid = blockIdx.x * blockDim.x + threadIdx.x;
    if (tid < BP * HH) { g_h[tid] = 0.f; g_c[tid] = 0.f; g_seg[tid] = 0.f; }
    if (blockIdx.x == 0 && threadIdx.x == 0) {
        int acc = 0;
        for (int b = 0; b < BP; b++) { g_off[b] = acc; acc += lengths[b]; }
    }
}

// ---------------- classic 128x128x8 fp32 SGEMM (NT): C = A @ B^T + bias -----
// A: [M,K] row-major, B: [Ncols,K] row-major. M = gridDim.y*128 (exact tiles).
__global__ void __launch_bounds__(256)
sgemm_nt(const float* __restrict__ A, const float* __restrict__ Bm,
         const float* __restrict__ bias1, const float* __restrict__ bias2,
         float* __restrict__ C, int Ncols, int K) {
    __shared__ __align__(16) float As[8][128];
    __shared__ __align__(16) float Bs[8][128];
    const int tid = threadIdx.x;
    const size_t m0 = (size_t)blockIdx.y * 128;
    const int    n0 = blockIdx.x * 128;
    const int aRow = tid >> 1;
    const int aCol = (tid & 1) * 4;
    const int ty = tid >> 4;   // 0..15
    const int tx = tid & 15;   // 0..15

    float acc[8][8];
#pragma unroll
    for (int i = 0; i < 8; i++)
#pragma unroll
        for (int j = 0; j < 8; j++) acc[i][j] = 0.f;

    for (int k0 = 0; k0 < K; k0 += 8) {
        float4 av = *(const float4*)&A[(m0 + aRow) * K + k0 + aCol];
        float4 bv = *(const float4*)&Bm[(size_t)(n0 + aRow) * K + k0 + aCol];
        __syncthreads();
        As[aCol + 0][aRow] = av.x; As[aCol + 1][aRow] = av.y;
        As[aCol + 2][aRow] = av.z; As[aCol + 3][aRow] = av.w;
        Bs[aCol + 0][aRow] = bv.x; Bs[aCol + 1][aRow] = bv.y;
        Bs[aCol + 2][aRow] = bv.z; Bs[aCol + 3][aRow] = bv.w;
        __syncthreads();
#pragma unroll
        for (int k = 0; k < 8; k++) {
            float rm[8], rn[8];
#pragma unroll
            for (int i = 0; i < 8; i++) rm[i] = As[k][ty * 8 + i];
#pragma unroll
            for (int j = 0; j < 8; j++) rn[j] = Bs[k][tx * 8 + j];
#pragma unroll
            for (int i = 0; i < 8; i++)
#pragma unroll
                for (int j = 0; j < 8; j++) acc[i][j] += rm[i] * rn[j];
        }
    }
#pragma unroll
    for (int i = 0; i < 8; i++) {
        size_t row = m0 + ty * 8 + i;
#pragma unroll
        for (int j = 0; j < 8; j += 4) {
            int col = n0 + tx * 8 + j;
            float4 v;
            float b0 = bias1[col + 0], b1 = bias1[col + 1],
                  b2 = bias1[col + 2], b3 = bias1[col + 3];
            if (bias2) {
                b0 += bias2[col + 0]; b1 += bias2[col + 1];
                b2 += bias2[col + 2]; b3 += bias2[col + 3];
            }
            v.x = acc[i][j + 0] + b0;
            v.y = acc[i][j + 1] + b1;
            v.z = acc[i][j + 2] + b2;
            v.w = acc[i][j + 3] + b3;
            *(float4*)&C[row * (size_t)Ncols + col] = v;
        }
    }
}

// ---------------- fused LSTM step: gates GEMM + nonlinearity + state update -
// Block: 16 persons x 64 h-cols (=> 4 gate groups x 64 gate cols). 256 thr.
// grid = (BP/16, HH/64)
__global__ void __launch_bounds__(256)
k_lstm_step(const float* __restrict__ W_hh, const int* __restrict__ lengths, int t) {
    __shared__ unsigned s_mask;
    __shared__ __align__(16) float Hs[16][16];
    __shared__ __align__(16) float Ws[16][260];   // [k][gatecol], padded (260*4 = 1040 = 16*65)

    const int tid = threadIdx.x;
    const int p0 = blockIdx.x * 16;
    const int c0 = blockIdx.y * 64;

    if (tid < 32) {
        bool act = (tid < 16) && (t < lengths[p0 + tid]);
        unsigned m = __ballot_sync(0xffffffffu, act);
        if (tid == 0) s_mask = m;
    }
    __syncthreads();
    const unsigned mask = s_mask;
    if (mask == 0) return;   // whole tile past its sequence ends

    const int trow = tid >> 4;   // person within tile
    const int tcol = tid & 15;   // 4 h-cols per thread
    const int p = p0 + trow;

    float4 acc0 = {0,0,0,0}, acc1 = {0,0,0,0}, acc2 = {0,0,0,0}, acc3 = {0,0,0,0};

    for (int k0 = 0; k0 < HH; k0 += 16) {
        float hval = g_h[(size_t)p * HH + k0 + tcol];
        float4 wv[4];
#pragma unroll
        for (int r = 0; r < 4; r++) {
            int lin = r * 256 + tid;
            int col = lin >> 2;        // 0..255 gate-col within tile
            int kq  = lin & 3;         // which float4 of the 16-k chunk
            int g   = col >> 6;        // gate group
            int c   = col & 63;        // h-col within group
            wv[r] = *(const float4*)&W_hh[(size_t)(g * HH + c0 + c) * HH + k0 + kq * 4];
        }
        __syncthreads();
        Hs[trow][tcol] = hval;
#pragma unroll
        for (int r = 0; r < 4; r++) {
            int lin = r * 256 + tid;
            int col = lin >> 2;
            int kq  = lin & 3;
            Ws[kq * 4 + 0][col] = wv[r].x;
            Ws[kq * 4 + 1][col] = wv[r].y;
            Ws[kq * 4 + 2][col] = wv[r].z;
            Ws[kq * 4 + 3][col] = wv[r].w;
        }
        __syncthreads();
#pragma unroll
        for (int k = 0; k < 16; k++) {
            float hv = Hs[trow][k];
            float4 w0 = *(const float4*)&Ws[k][0 * 64 + tcol * 4];
            float4 w1 = *(const float4*)&Ws[k][1 * 64 + tcol * 4];
            float4 w2 = *(const float4*)&Ws[k][2 * 64 + tcol * 4];
            float4 w3 = *(const float4*)&Ws[k][3 * 64 + tcol * 4];
            acc0.x += hv * w0.x; acc0.y += hv * w0.y; acc0.z += hv * w0.z; acc0.w += hv * w0.w;
            acc1.x += hv * w1.x; acc1.y += hv * w1.y; acc1.z += hv * w1.z; acc1.w += hv * w1.w;
            acc2.x += hv * w2.x; acc2.y += hv * w2.y; acc2.z += hv * w2.z; acc2.w += hv * w2.w;
            acc3.x += hv * w3.x; acc3.y += hv * w3.y; acc3.z += hv * w3.z; acc3.w += hv * w3.w;
        }
    }

    if (!((mask >> trow) & 1u)) return;

    const size_t fi = (size_t)(g_off[p] + t);
    const int colb = c0 + tcol * 4;

    float4 xi = *(const float4*)&g_xW[fi * GG + 0 * HH + colb];
    float4 xf = *(const float4*)&g_xW[fi * GG + 1 * HH + colb];
    float4 xg = *(const float4*)&g_xW[fi * GG + 2 * HH + colb];
    float4 xo = *(const float4*)&g_xW[fi * GG + 3 * HH + colb];

    float gi[4] = {acc0.x + xi.x, acc0.y + xi.y, acc0.z + xi.z, acc0.w + xi.w};
    float gf[4] = {acc1.x + xf.x, acc1.y + xf.y, acc1.z + xf.z, acc1.w + xf.w};
    float gg[4] = {acc2.x + xg.x, acc2.y + xg.y, acc2.z + xg.z, acc2.w + xg.w};
    float go[4] = {acc3.x + xo.x, acc3.y + xo.y, acc3.z + xo.z, acc3.w + xo.w};

    float4 cold = *(const float4*)&g_c[(size_t)p * HH + colb];
    float cv[4] = {cold.x, cold.y, cold.z, cold.w};
    float cn[4], hn[4];
#pragma unroll
    for (int ci = 0; ci < 4; ci++) {
        float iv = sigf(gi[ci]);
        float fv = sigf(gf[ci]);
        float gv = tanhf(gg[ci]);
        float ov = sigf(go[ci]);
        cn[ci] = fv * cv[ci] + iv * gv;
        hn[ci] = ov * tanhf(cn[ci]);
    }
    float4 cnew = {cn[0], cn[1], cn[2], cn[3]};
    float4 hnew = {hn[0], hn[1], hn[2], hn[3]};
    *(float4*)&g_c[(size_t)p * HH + colb] = cnew;
    *(float4*)&g_h[(size_t)p * HH + colb] = hnew;
    *(float4*)&g_flat[fi * HH + colb] = hnew;
}

// ---------------- attention logits + concrete-relaxation gate ---------------
__global__ void k_att(const float* __restrict__ passedZ,
                      const float* __restrict__ fc2_W, const float* __restrict__ fc2_b,
                      const float* __restrict__ eps_u) {
    int gwarp = (blockIdx.x * blockDim.x + threadIdx.x) >> 5;
    int lane = threadIdx.x & 31;
    if (gwarp >= NN) return;
    const float* row = passedZ + (size_t)gwarp * DD;
    float s = 0.f;
#pragma unroll
    for (int k = lane; k < DD; k += 32) s += row[k] * fc2_W[k];
#pragma unroll
    for (int o = 16; o; o >>= 1) s += __shfl_xor_sync(0xffffffffu, s, o);
    if (lane == 0) {
        float logit = s + fc2_b[0];
        float eu = eps_u[gwarp];
        // eps = (2*BIAS - 1)*u + (1 - BIAS), BIAS = 1e-4
        float eps = (2.0f * 1e-4f - 1.0f) * eu + (1.0f - 1e-4f);
        float gate = logf(eps) - logf(1.0f - eps) + logit;
        g_att[gwarp] = sigf(gate);
    }
}

// ---------------- gated segment sum: seg[b] = sum_n flat[n]*att[n] ----------
__global__ void k_seg(const int* __restrict__ lengths) {
    int b = blockIdx.x;
    int col = threadIdx.x;        // HH threads
    int off = g_off[b];
    int L = lengths[b];
    float acc = 0.f;
    for (int r = 0; r < L; r++) {
        int n = off + r;
        acc += g_flat[(size_t)n * HH + col] * g_att[n];
    }
    g_seg[(size_t)b * HH + col] = acc;
}

// ---------------- final tiny MLP: (seg @ mlp1^T + b1) @ mlp2^T + b2 ---------
__global__ void k_final(const float* __restrict__ mlp1_W, const float* __restrict__ mlp1_b,
                        const float* __restrict__ mlp2_W, const float* __restrict__ mlp2_b,
                        float* __restrict__ out) {
    __shared__ float hidden[16];
    int b = blockIdx.x;
    int tid = threadIdx.x;        // 512 threads = 16 warps
    int w = tid >> 5, lane = tid & 31;
    const float* seg = &g_seg[(size_t)b * HH];
    float s = 0.f;
#pragma unroll
    for (int k = lane; k < HH; k += 32) s += seg[k] * mlp1_W[(size_t)w * HH + k];
#pragma unroll
    for (int o = 16; o; o >>= 1) s += __shfl_xor_sync(0xffffffffu, s, o);
    if (lane == 0) hidden[w] = s + mlp1_b[w];
    __syncthreads();
    if (tid < 2) {
        float o = mlp2_b[tid];
#pragma unroll
        for (int j = 0; j < 16; j++) o += hidden[j] * mlp2_W[tid * 16 + j];
        out[b * 2 + tid] = o;
    }
}

// -----------------------------------------------------------------------------
extern "C" void kernel_launch(void* const* d_in, const int* in_sizes, int n_in,
                              void* d_out, int out_size) {
    const float* lstm_input = (const float*)d_in[0];
    const float* eps_u      = (const float*)d_in[1];
    const float* W_ih       = (const float*)d_in[2];
    const float* W_hh       = (const float*)d_in[3];
    const float* b_ih       = (const float*)d_in[4];
    const float* b_hh       = (const float*)d_in[5];
    const float* fc1_W      = (const float*)d_in[6];
    const float* fc1_b      = (const float*)d_in[7];
    const float* fc2_W      = (const float*)d_in[8];
    const float* fc2_b      = (const float*)d_in[9];
    const float* mlp1_W     = (const float*)d_in[10];
    const float* mlp1_b     = (const float*)d_in[11];
    const float* mlp2_W     = (const float*)d_in[12];
    const float* mlp2_b     = (const float*)d_in[13];
    const int*   lengths    = (const int*)d_in[14];

    float* out = (float*)d_out;
    float* passedZ = out + BP * 2;   // tuple order: final[256,2] then passed_Z[N,512]

    float *xw, *flat;
    cudaGetSymbolAddress((void**)&xw, g_xW);
    cudaGetSymbolAddress((void**)&flat, g_flat);

    // 1. init states/offsets
    k_init<<<(BP * HH + 255) / 256, 256>>>(lengths);

    // 2. xW = X @ W_ih^T + b_ih + b_hh   [65408 x 2048]
    sgemm_nt<<<dim3(GG / 128, NN / 128), 256>>>(lstm_input, W_ih, b_ih, b_hh, xw, GG, DD);

    // 3. sequential LSTM recurrence (ragged-aware early exit inside)
    for (int t = 0; t < TT; t++)
        k_lstm_step<<<dim3(BP / 16, HH / 64), 256>>>(W_hh, lengths, t);

    // 4. passed_Z = flat @ fc1_W^T + fc1_b  -> straight into d_out
    sgemm_nt<<<dim3(DD / 128, NN / 128), 256>>>(flat, fc1_W, fc1_b, nullptr, passedZ, DD, HH);

    // 5. attention gate per flat row
    k_att<<<(NN * 32 + 255) / 256, 256>>>(passedZ, fc2_W, fc2_b, eps_u);

    // 6. gated per-person segment sum
    k_seg<<<BP, HH>>>(lengths);

    // 7. final MLP -> out[0:512]
    k_final<<<BP, 512>>>(mlp1_W, mlp1_b, mlp2_W, mlp2_b, out);
}

// round 4
// speedup vs baseline: 1.6854x; 1.6854x over previous
#include <cuda_runtime.h>
#include <math.h>

// Problem constants (fixed by the dataset: B=256, D=H=512, lengths=128..383)
#define NN 65408      // total flat timesteps
#define BP 256        // persons
#define DD 512        // input dim
#define HH 512        // hidden dim
#define GG 2048       // 4*H gate dim
#define TT 383        // max sequence length

// ---------------- device scratch (static: no allocation in kernel_launch) ---
__device__ __align__(16) float g_xW[(size_t)NN * GG];   // input contribution to gates
__device__ __align__(16) float g_flat[(size_t)NN * HH]; // flat valid LSTM outputs
__device__ __align__(16) float g_h[BP * HH];
__device__ __align__(16) float g_c[BP * HH];
__device__ __align__(16) float g_att[NN];
__device__ __align__(16) float g_seg[BP * HH];
__device__ int   g_off[BP];

__device__ __forceinline__ float sigf(float x) { return 1.0f / (1.0f + expf(-x)); }

// ---------------- init: zero states + exclusive-scan offsets ----------------
__global__ void k_init(const int* __restrict__ lengths) {
    int tid = blockIdx.x * blockDim.x + threadIdx.x;
    if (tid < BP * HH) { g_h[tid] = 0.f; g_c[tid] = 0.f; g_seg[tid] = 0.f; }
    if (blockIdx.x == 0 && threadIdx.x == 0) {
        int acc = 0;
        for (int b = 0; b < BP; b++) { g_off[b] = acc; acc += lengths[b]; }
    }
}

// ---------------- classic 128x128x8 fp32 SGEMM (NT): C = A @ B^T + bias -----
__global__ void __launch_bounds__(256)
sgemm_nt(const float* __restrict__ A, const float* __restrict__ Bm,
         const float* __restrict__ bias1, const float* __restrict__ bias2,
         float* __restrict__ C, int Ncols, int K) {
    __shared__ __align__(16) float As[8][128];
    __shared__ __align__(16) float Bs[8][128];
    const int tid = threadIdx.x;
    const size_t m0 = (size_t)blockIdx.y * 128;
    const int    n0 = blockIdx.x * 128;
    const int aRow = tid >> 1;
    const int aCol = (tid & 1) * 4;
    const int ty = tid >> 4;
    const int tx = tid & 15;

    float acc[8][8];
#pragma unroll
    for (int i = 0; i < 8; i++)
#pragma unroll
        for (int j = 0; j < 8; j++) acc[i][j] = 0.f;

    for (int k0 = 0; k0 < K; k0 += 8) {
        float4 av = *(const float4*)&A[(m0 + aRow) * K + k0 + aCol];
        float4 bv = *(const float4*)&Bm[(size_t)(n0 + aRow) * K + k0 + aCol];
        __syncthreads();
        As[aCol + 0][aRow] = av.x; As[aCol + 1][aRow] = av.y;
        As[aCol + 2][aRow] = av.z; As[aCol + 3][aRow] = av.w;
        Bs[aCol + 0][aRow] = bv.x; Bs[aCol + 1][aRow] = bv.y;
        Bs[aCol + 2][aRow] = bv.z; Bs[aCol + 3][aRow] = bv.w;
        __syncthreads();
#pragma unroll
        for (int k = 0; k < 8; k++) {
            float rm[8], rn[8];
#pragma unroll
            for (int i = 0; i < 8; i++) rm[i] = As[k][ty * 8 + i];
#pragma unroll
            for (int j = 0; j < 8; j++) rn[j] = Bs[k][tx * 8 + j];
#pragma unroll
            for (int i = 0; i < 8; i++)
#pragma unroll
                for (int j = 0; j < 8; j++) acc[i][j] += rm[i] * rn[j];
        }
    }
#pragma unroll
    for (int i = 0; i < 8; i++) {
        size_t row = m0 + ty * 8 + i;
#pragma unroll
        for (int j = 0; j < 8; j += 4) {
            int col = n0 + tx * 8 + j;
            float4 v;
            float b0 = bias1[col + 0], b1 = bias1[col + 1],
                  b2 = bias1[col + 2], b3 = bias1[col + 3];
            if (bias2) {
                b0 += bias2[col + 0]; b1 += bias2[col + 1];
                b2 += bias2[col + 2]; b3 += bias2[col + 3];
            }
            v.x = acc[i][j + 0] + b0;
            v.y = acc[i][j + 1] + b1;
            v.z = acc[i][j + 2] + b2;
            v.w = acc[i][j + 3] + b3;
            *(float4*)&C[row * (size_t)Ncols + col] = v;
        }
    }
}

// ---------------- fused LSTM step v2: register-blocked 32x128 tile ----------
// Block tile: 32 persons x (32 h-cols x 4 gates) = 32 x 128 gate-cols.
// 256 threads, thread tile 4 persons x 4 cols (16 accums, 2B LDS per FMA).
// K-chunked (32) with register-staged prefetch. Epilogue fused via smem swap.
// grid = (BP/32, HH/32) = (8, 16) = 128 blocks.
__global__ void __launch_bounds__(256)
k_lstm_step(const float* __restrict__ W_hh, const int* __restrict__ lengths, int t) {
    __shared__ unsigned s_mask;
    __shared__ __align__(16) float Hs[32][36];    // [k][person], pitch 36 (144B, 16B-mult)
    __shared__ __align__(16) float Ws[32][132];   // [k][gatecol], pitch 132 (528B, 16B-mult)

    const int tid = threadIdx.x;
    const int p0  = blockIdx.x * 32;
    const int hc0 = blockIdx.y * 32;

    if (tid < 32) {
        bool act = (t < lengths[p0 + tid]);
        unsigned m = __ballot_sync(0xffffffffu, act);
        if (tid == 0) s_mask = m;
    }
    __syncthreads();
    const unsigned mask = s_mask;
    if (mask == 0) return;

    // ---- load-index mapping (coalesced: 8 consecutive lanes read 128B rows)
    const int lkq = tid & 7;          // k float4-group within 32-chunk
    const int lp  = tid >> 3;         // person 0..31  (for H loads)
    // W loads: 4 reps r cover cols c = lp + 32*r ; gate = c>>5, hcol = c&31
    int wrow[4];
#pragma unroll
    for (int r = 0; r < 4; r++) {
        int c = lp + 32 * r;
        wrow[r] = (c >> 5) * HH + hc0 + (c & 31);   // row in W_hh
    }

    // ---- compute-index mapping
    const int ty = tid >> 5;          // 0..7  -> persons 4*ty..4*ty+3
    const int tx = tid & 31;          // 0..31 -> cols   4*tx..4*tx+3

    float acc[4][4];
#pragma unroll
    for (int i = 0; i < 4; i++)
#pragma unroll
        for (int j = 0; j < 4; j++) acc[i][j] = 0.f;

    // prefetch chunk 0
    float4 hreg = *(const float4*)&g_h[(size_t)(p0 + lp) * HH + lkq * 4];
    float4 wreg[4];
#pragma unroll
    for (int r = 0; r < 4; r++)
        wreg[r] = *(const float4*)&W_hh[(size_t)wrow[r] * HH + lkq * 4];

    for (int chunk = 0; chunk < HH / 32; chunk++) {
        __syncthreads();
        // store staged regs to smem
        Hs[lkq * 4 + 0][lp] = hreg.x;
        Hs[lkq * 4 + 1][lp] = hreg.y;
        Hs[lkq * 4 + 2][lp] = hreg.z;
        Hs[lkq * 4 + 3][lp] = hreg.w;
#pragma unroll
        for (int r = 0; r < 4; r++) {
            int c = lp + 32 * r;
            Ws[lkq * 4 + 0][c] = wreg[r].x;
            Ws[lkq * 4 + 1][c] = wreg[r].y;
            Ws[lkq * 4 + 2][c] = wreg[r].z;
            Ws[lkq * 4 + 3][c] = wreg[r].w;
        }
        __syncthreads();
        // prefetch next chunk (overlaps compute below)
        if (chunk + 1 < HH / 32) {
            int k0 = (chunk + 1) * 32;
            hreg = *(const float4*)&g_h[(size_t)(p0 + lp) * HH + k0 + lkq * 4];
#pragma unroll
            for (int r = 0; r < 4; r++)
                wreg[r] = *(const float4*)&W_hh[(size_t)wrow[r] * HH + k0 + lkq * 4];
        }
        // compute 32 k-iterations
#pragma unroll
        for (int k = 0; k < 32; k++) {
            float4 a = *(const float4*)&Hs[k][ty * 4];   // warp-broadcast
            float4 b = *(const float4*)&Ws[k][tx * 4];
            acc[0][0] += a.x * b.x; acc[0][1] += a.x * b.y; acc[0][2] += a.x * b.z; acc[0][3] += a.x * b.w;
            acc[1][0] += a.y * b.x; acc[1][1] += a.y * b.y; acc[1][2] += a.y * b.z; acc[1][3] += a.y * b.w;
            acc[2][0] += a.z * b.x; acc[2][1] += a.z * b.y; acc[2][2] += a.z * b.z; acc[2][3] += a.z * b.w;
            acc[3][0] += a.w * b.x; acc[3][1] += a.w * b.y; acc[3][2] += a.w * b.z; acc[3][3] += a.w * b.w;
        }
    }

    // ---- gate exchange: reuse Ws as gates[person][gatecol]
    __syncthreads();
#pragma unroll
    for (int i = 0; i < 4; i++)
#pragma unroll
        for (int j = 0; j < 4; j++)
            Ws[ty * 4 + i][tx * 4 + j] = acc[i][j];
    __syncthreads();

    // ---- epilogue: 32 persons x 32 h-cols = 1024 outputs / 256 threads = 4 each
#pragma unroll
    for (int q = tid; q < 32 * 32; q += 256) {
        int p  = q >> 5;
        int hc = q & 31;
        if (!((mask >> p) & 1u)) continue;
        int pg = p0 + p;
        size_t fi = (size_t)(g_off[pg] + t);
        size_t xb = fi * GG + hc0 + hc;

        float gi = Ws[p][0 * 32 + hc] + g_xW[xb + 0 * HH];
        float gf = Ws[p][1 * 32 + hc] + g_xW[xb + 1 * HH];
        float gg = Ws[p][2 * 32 + hc] + g_xW[xb + 2 * HH];
        float go = Ws[p][3 * 32 + hc] + g_xW[xb + 3 * HH];

        size_t si = (size_t)pg * HH + hc0 + hc;
        float cv = g_c[si];
        float cn = sigf(gf) * cv + sigf(gi) * tanhf(gg);
        float hn = sigf(go) * tanhf(cn);
        g_c[si] = cn;
        g_h[si] = hn;
        g_flat[fi * HH + hc0 + hc] = hn;
    }
}

// ---------------- attention logits + concrete-relaxation gate ---------------
__global__ void k_att(const float* __restrict__ passedZ,
                      const float* __restrict__ fc2_W, const float* __restrict__ fc2_b,
                      const float* __restrict__ eps_u) {
    int gwarp = (blockIdx.x * blockDim.x + threadIdx.x) >> 5;
    int lane = threadIdx.x & 31;
    if (gwarp >= NN) return;
    const float* row = passedZ + (size_t)gwarp * DD;
    float s = 0.f;
#pragma unroll
    for (int k = lane; k < DD; k += 32) s += row[k] * fc2_W[k];
#pragma unroll
    for (int o = 16; o; o >>= 1) s += __shfl_xor_sync(0xffffffffu, s, o);
    if (lane == 0) {
        float logit = s + fc2_b[0];
        float eu = eps_u[gwarp];
        float eps = (2.0f * 1e-4f - 1.0f) * eu + (1.0f - 1e-4f);
        float gate = logf(eps) - logf(1.0f - eps) + logit;
        g_att[gwarp] = sigf(gate);
    }
}

// ---------------- gated segment sum: seg[b] = sum_n flat[n]*att[n] ----------
__global__ void k_seg(const int* __restrict__ lengths) {
    int b = blockIdx.x;
    int col = threadIdx.x;
    int off = g_off[b];
    int L = lengths[b];
    float acc = 0.f;
    for (int r = 0; r < L; r++) {
        int n = off + r;
        acc += g_flat[(size_t)n * HH + col] * g_att[n];
    }
    g_seg[(size_t)b * HH + col] = acc;
}

// ---------------- final tiny MLP ---------------------------------------------
__global__ void k_final(const float* __restrict__ mlp1_W, const float* __restrict__ mlp1_b,
                        const float* __restrict__ mlp2_W, const float* __restrict__ mlp2_b,
                        float* __restrict__ out) {
    __shared__ float hidden[16];
    int b = blockIdx.x;
    int tid = threadIdx.x;
    int w = tid >> 5, lane = tid & 31;
    const float* seg = &g_seg[(size_t)b * HH];
    float s = 0.f;
#pragma unroll
    for (int k = lane; k < HH; k += 32) s += seg[k] * mlp1_W[(size_t)w * HH + k];
#pragma unroll
    for (int o = 16; o; o >>= 1) s += __shfl_xor_sync(0xffffffffu, s, o);
    if (lane == 0) hidden[w] = s + mlp1_b[w];
    __syncthreads();
    if (tid < 2) {
        float o = mlp2_b[tid];
#pragma unroll
        for (int j = 0; j < 16; j++) o += hidden[j] * mlp2_W[tid * 16 + j];
        out[b * 2 + tid] = o;
    }
}

// -----------------------------------------------------------------------------
extern "C" void kernel_launch(void* const* d_in, const int* in_sizes, int n_in,
                              void* d_out, int out_size) {
    const float* lstm_input = (const float*)d_in[0];
    const float* eps_u      = (const float*)d_in[1];
    const float* W_ih       = (const float*)d_in[2];
    const float* W_hh       = (const float*)d_in[3];
    const float* b_ih       = (const float*)d_in[4];
    const float* b_hh       = (const float*)d_in[5];
    const float* fc1_W      = (const float*)d_in[6];
    const float* fc1_b      = (const float*)d_in[7];
    const float* fc2_W      = (const float*)d_in[8];
    const float* fc2_b      = (const float*)d_in[9];
    const float* mlp1_W     = (const float*)d_in[10];
    const float* mlp1_b     = (const float*)d_in[11];
    const float* mlp2_W     = (const float*)d_in[12];
    const float* mlp2_b     = (const float*)d_in[13];
    const int*   lengths    = (const int*)d_in[14];

    float* out = (float*)d_out;
    float* passedZ = out + BP * 2;   // tuple order: final[256,2] then passed_Z[N,512]

    float *xw, *flat;
    cudaGetSymbolAddress((void**)&xw, g_xW);
    cudaGetSymbolAddress((void**)&flat, g_flat);

    // 1. init states/offsets
    k_init<<<(BP * HH + 255) / 256, 256>>>(lengths);

    // 2. xW = X @ W_ih^T + b_ih + b_hh   [65408 x 2048]
    sgemm_nt<<<dim3(GG / 128, NN / 128), 256>>>(lstm_input, W_ih, b_ih, b_hh, xw, GG, DD);

    // 3. sequential LSTM recurrence
    for (int t = 0; t < TT; t++)
        k_lstm_step<<<dim3(BP / 32, HH / 32), 256>>>(W_hh, lengths, t);

    // 4. passed_Z = flat @ fc1_W^T + fc1_b  -> straight into d_out
    sgemm_nt<<<dim3(DD / 128, NN / 128), 256>>>(flat, fc1_W, fc1_b, nullptr, passedZ, DD, HH);

    // 5. attention gate per flat row
    k_att<<<(NN * 32 + 255) / 256, 256>>>(passedZ, fc2_W, fc2_b, eps_u);

    // 6. gated per-person segment sum
    k_seg<<<BP, HH>>>(lengths);

    // 7. final MLP -> out[0:512]
    k_final<<<BP, 512>>>(mlp1_W, mlp1_b, mlp2_W, mlp2_b, out);
}

// round 6
// speedup vs baseline: 1.8882x; 1.1203x over previous
#include <cuda_runtime.h>
#include <cuda.h>
#include <math.h>
#include <stdint.h>

// Problem constants (fixed by the dataset: B=256, D=H=512, lengths=128..383)
#define NN 65408      // total flat timesteps
#define BP 256        // persons
#define DD 512        // input dim
#define HH 512        // hidden dim
#define GG 2048       // 4*H gate dim
#define TT 383        // max sequence length
#define KK 512        // K of both big GEMMs

// ---------------- device scratch (static: no allocation in kernel_launch) ---
__device__ __align__(16) float g_xW[(size_t)NN * GG];   // input contribution to gates
__device__ __align__(16) float g_flat[(size_t)NN * HH]; // flat valid LSTM outputs
__device__ __align__(16) float g_h[BP * HH];
__device__ __align__(16) float g_c[BP * HH];
__device__ __align__(16) float g_att[NN];
__device__ __align__(16) float g_seg[BP * HH];
__device__ int   g_off[BP];

__device__ __forceinline__ float sigf(float x) { return 1.0f / (1.0f + expf(-x)); }

__device__ __forceinline__ uint32_t f2tf32(float f) {
    uint32_t r; asm("cvt.rna.tf32.f32 %0, %1;" : "=r"(r) : "f"(f)); return r;
}
__device__ __forceinline__ void mma_tf32(float& c0, float& c1, float& c2, float& c3,
                                         uint32_t a0, uint32_t a1, uint32_t a2, uint32_t a3,
                                         uint32_t b0, uint32_t b1) {
    asm volatile("mma.sync.aligned.m16n8k8.row.col.f32.tf32.tf32.f32 "
        "{%0,%1,%2,%3}, {%4,%5,%6,%7}, {%8,%9}, {%0,%1,%2,%3};"
        : "+f"(c0), "+f"(c1), "+f"(c2), "+f"(c3)
        : "r"(a0), "r"(a1), "r"(a2), "r"(a3), "r"(b0), "r"(b1));
}

// =================== tf32 mma.sync NT GEMM: C = A @ B^T + bias ==============
// A:[M,512] row-major, B:[Ncols,512] row-major. CTA tile 128x128, 8 warps 2x4,
// warp tile 64x32 (m16n8k8 frags: 4 M-frag x 4 N-frag). K-chunk 32, dbl-buffer.
#define GPITCH 36
#define STAGE_F (128 * GPITCH)                    // floats per operand stage
#define GEMM_SMEM (4 * STAGE_F * 4)               // 73728 bytes dynamic

__global__ void __launch_bounds__(256)
tgemm_mma(const float* __restrict__ A, const float* __restrict__ Bm,
          const float* __restrict__ bias1, const float* __restrict__ bias2,
          float* __restrict__ C, int Ncols) {
    extern __shared__ __align__(16) float sm[];
    float* As[2] = { sm,               sm + 2 * STAGE_F };
    float* Bs[2] = { sm + STAGE_F,     sm + 3 * STAGE_F };

    const int tid = threadIdx.x;
    const int wid = tid >> 5, lane = tid & 31;
    const int grp = lane >> 2, tig = lane & 3;     // mma thread mapping
    const int warpM = wid >> 2, warpN = wid & 3;   // 2 x 4 warp grid
    const size_t m0 = (size_t)blockIdx.y * 128;
    const int    n0 = blockIdx.x * 128;

    // global->smem mapping: 2 threads/row, 4 float4 each (32 floats per row)
    const int lrow = tid >> 1;
    const int lcb  = (tid & 1) * 16;
    const float* Ag = A  + (m0 + lrow) * KK;
    const float* Bg = Bm + (size_t)(n0 + lrow) * KK;

    float4 ar[4], br[4];
    auto ldchunk = [&](int c) {
#pragma unroll
        for (int q = 0; q < 4; q++) {
            ar[q] = *(const float4*)&Ag[c * 32 + lcb + q * 4];
            br[q] = *(const float4*)&Bg[c * 32 + lcb + q * 4];
        }
    };
    auto stchunk = [&](int s) {
        float* a = As[s] + lrow * GPITCH + lcb;
        float* b = Bs[s] + lrow * GPITCH + lcb;
#pragma unroll
        for (int q = 0; q < 4; q++) {
            *(float4*)&a[q * 4] = ar[q];
            *(float4*)&b[q * 4] = br[q];
        }
    };

    float acc[4][4][4];   // [mf][nf][c0..c3]
#pragma unroll
    for (int i = 0; i < 4; i++)
#pragma unroll
        for (int j = 0; j < 4; j++)
#pragma unroll
            for (int k = 0; k < 4; k++) acc[i][j][k] = 0.f;

    ldchunk(0); stchunk(0);
    __syncthreads();

    for (int c = 0; c < KK / 32; c++) {
        const int s = c & 1;
        if (c + 1 < KK / 32) ldchunk(c + 1);   // prefetch to regs, overlaps mma

        const float* Aw = As[s] + (warpM * 64 + grp) * GPITCH;
        const float* Bw = Bs[s] + (warpN * 32 + grp) * GPITCH;
#pragma unroll
        for (int k0 = 0; k0 < 32; k0 += 8) {
            uint32_t af[4][4], bf[4][2];
#pragma unroll
            for (int mf = 0; mf < 4; mf++) {
                const float* p = Aw + mf * 16 * GPITCH + k0;
                af[mf][0] = f2tf32(p[tig]);
                af[mf][1] = f2tf32(p[8 * GPITCH + tig]);
                af[mf][2] = f2tf32(p[tig + 4]);
                af[mf][3] = f2tf32(p[8 * GPITCH + tig + 4]);
            }
#pragma unroll
            for (int nf = 0; nf < 4; nf++) {
                const float* p = Bw + nf * 8 * GPITCH + k0;
                bf[nf][0] = f2tf32(p[tig]);
                bf[nf][1] = f2tf32(p[tig + 4]);
            }
#pragma unroll
            for (int mf = 0; mf < 4; mf++)
#pragma unroll
                for (int nf = 0; nf < 4; nf++)
                    mma_tf32(acc[mf][nf][0], acc[mf][nf][1], acc[mf][nf][2], acc[mf][nf][3],
                             af[mf][0], af[mf][1], af[mf][2], af[mf][3],
                             bf[nf][0], bf[nf][1]);
        }
        __syncthreads();
        if (c + 1 < KK / 32) { stchunk((c + 1) & 1); __syncthreads(); }
    }

    // epilogue with bias
#pragma unroll
    for (int mf = 0; mf < 4; mf++) {
        size_t r0 = m0 + warpM * 64 + mf * 16 + grp;
#pragma unroll
        for (int nf = 0; nf < 4; nf++) {
            int col = n0 + warpN * 32 + nf * 8 + 2 * tig;
            float b0 = bias1[col], b1 = bias1[col + 1];
            if (bias2) { b0 += bias2[col]; b1 += bias2[col + 1]; }
            float2 v0 = { acc[mf][nf][0] + b0, acc[mf][nf][1] + b1 };
            float2 v1 = { acc[mf][nf][2] + b0, acc[mf][nf][3] + b1 };
            *(float2*)&C[r0 * (size_t)Ncols + col] = v0;
            *(float2*)&C[(r0 + 8) * (size_t)Ncols + col] = v1;
        }
    }
}

// ---------------- init: zero states + exclusive-scan offsets ----------------
__global__ void k_init(const int* __restrict__ lengths) {
    int tid = blockIdx.x * blockDim.x + threadIdx.x;
    if (tid < BP * HH) { g_h[tid] = 0.f; g_c[tid] = 0.f; g_seg[tid] = 0.f; }
    if (blockIdx.x == 0 && threadIdx.x == 0) {
        int acc = 0;
        for (int b = 0; b < BP; b++) { g_off[b] = acc; acc += lengths[b]; }
    }
}

// ---------------- fused LSTM step: register-blocked 32x128 tile -------------
__global__ void __launch_bounds__(256)
k_lstm_step(const float* __restrict__ W_hh, const int* __restrict__ lengths, int t) {
    __shared__ unsigned s_mask;
    __shared__ __align__(16) float Hs[32][36];
    __shared__ __align__(16) float Ws[32][132];

    const int tid = threadIdx.x;
    const int p0  = blockIdx.x * 32;
    const int hc0 = blockIdx.y * 32;

    if (tid < 32) {
        bool act = (t < lengths[p0 + tid]);
        unsigned m = __ballot_sync(0xffffffffu, act);
        if (tid == 0) s_mask = m;
    }
    __syncthreads();
    const unsigned mask = s_mask;
    if (mask == 0) return;

    const int lkq = tid & 7;
    const int lp  = tid >> 3;
    int wrow[4];
#pragma unroll
    for (int r = 0; r < 4; r++) {
        int c = lp + 32 * r;
        wrow[r] = (c >> 5) * HH + hc0 + (c & 31);
    }
    const int ty = tid >> 5;
    const int tx = tid & 31;

    float acc[4][4];
#pragma unroll
    for (int i = 0; i < 4; i++)
#pragma unroll
        for (int j = 0; j < 4; j++) acc[i][j] = 0.f;

    float4 hreg = *(const float4*)&g_h[(size_t)(p0 + lp) * HH + lkq * 4];
    float4 wreg[4];
#pragma unroll
    for (int r = 0; r < 4; r++)
        wreg[r] = *(const float4*)&W_hh[(size_t)wrow[r] * HH + lkq * 4];

    for (int chunk = 0; chunk < HH / 32; chunk++) {
        __syncthreads();
        Hs[lkq * 4 + 0][lp] = hreg.x;
        Hs[lkq * 4 + 1][lp] = hreg.y;
        Hs[lkq * 4 + 2][lp] = hreg.z;
        Hs[lkq * 4 + 3][lp] = hreg.w;
#pragma unroll
        for (int r = 0; r < 4; r++) {
            int c = lp + 32 * r;
            Ws[lkq * 4 + 0][c] = wreg[r].x;
            Ws[lkq * 4 + 1][c] = wreg[r].y;
            Ws[lkq * 4 + 2][c] = wreg[r].z;
            Ws[lkq * 4 + 3][c] = wreg[r].w;
        }
        __syncthreads();
        if (chunk + 1 < HH / 32) {
            int k0 = (chunk + 1) * 32;
            hreg = *(const float4*)&g_h[(size_t)(p0 + lp) * HH + k0 + lkq * 4];
#pragma unroll
            for (int r = 0; r < 4; r++)
                wreg[r] = *(const float4*)&W_hh[(size_t)wrow[r] * HH + k0 + lkq * 4];
        }
#pragma unroll
        for (int k = 0; k < 32; k++) {
            float4 a = *(const float4*)&Hs[k][ty * 4];
            float4 b = *(const float4*)&Ws[k][tx * 4];
            acc[0][0] += a.x * b.x; acc[0][1] += a.x * b.y; acc[0][2] += a.x * b.z; acc[0][3] += a.x * b.w;
            acc[1][0] += a.y * b.x; acc[1][1] += a.y * b.y; acc[1][2] += a.y * b.z; acc[1][3] += a.y * b.w;
            acc[2][0] += a.z * b.x; acc[2][1] += a.z * b.y; acc[2][2] += a.z * b.z; acc[2][3] += a.z * b.w;
            acc[3][0] += a.w * b.x; acc[3][1] += a.w * b.y; acc[3][2] += a.w * b.z; acc[3][3] += a.w * b.w;
        }
    }

    __syncthreads();
#pragma unroll
    for (int i = 0; i < 4; i++)
#pragma unroll
        for (int j = 0; j < 4; j++)
            Ws[ty * 4 + i][tx * 4 + j] = acc[i][j];
    __syncthreads();

#pragma unroll
    for (int q = tid; q < 32 * 32; q += 256) {
        int p  = q >> 5;
        int hc = q & 31;
        if (!((mask >> p) & 1u)) continue;
        int pg = p0 + p;
        size_t fi = (size_t)(g_off[pg] + t);
        size_t xb = fi * GG + hc0 + hc;

        float gi = Ws[p][0 * 32 + hc] + g_xW[xb + 0 * HH];
        float gf = Ws[p][1 * 32 + hc] + g_xW[xb + 1 * HH];
        float gg = Ws[p][2 * 32 + hc] + g_xW[xb + 2 * HH];
        float go = Ws[p][3 * 32 + hc] + g_xW[xb + 3 * HH];

        size_t si = (size_t)pg * HH + hc0 + hc;
        float cv = g_c[si];
        float cn = sigf(gf) * cv + sigf(gi) * tanhf(gg);
        float hn = sigf(go) * tanhf(cn);
        g_c[si] = cn;
        g_h[si] = hn;
        g_flat[fi * HH + hc0 + hc] = hn;
    }
}

// ---------------- attention logits + concrete-relaxation gate ---------------
__global__ void k_att(const float* __restrict__ passedZ,
                      const float* __restrict__ fc2_W, const float* __restrict__ fc2_b,
                      const float* __restrict__ eps_u) {
    int gwarp = (blockIdx.x * blockDim.x + threadIdx.x) >> 5;
    int lane = threadIdx.x & 31;
    if (gwarp >= NN) return;
    const float* row = passedZ + (size_t)gwarp * DD;
    float s = 0.f;
#pragma unroll
    for (int k = lane; k < DD; k += 32) s += row[k] * fc2_W[k];
#pragma unroll
    for (int o = 16; o; o >>= 1) s += __shfl_xor_sync(0xffffffffu, s, o);
    if (lane == 0) {
        float logit = s + fc2_b[0];
        float eu = eps_u[gwarp];
        float eps = (2.0f * 1e-4f - 1.0f) * eu + (1.0f - 1e-4f);
        float gate = logf(eps) - logf(1.0f - eps) + logit;
        g_att[gwarp] = sigf(gate);
    }
}

// ---------------- gated segment sum ------------------------------------------
__global__ void k_seg(const int* __restrict__ lengths) {
    int b = blockIdx.x;
    int col = threadIdx.x;
    int off = g_off[b];
    int L = lengths[b];
    float acc = 0.f;
    for (int r = 0; r < L; r++) {
        int n = off + r;
        acc += g_flat[(size_t)n * HH + col] * g_att[n];
    }
    g_seg[(size_t)b * HH + col] = acc;
}

// ---------------- final tiny MLP ---------------------------------------------
__global__ void k_final(const float* __restrict__ mlp1_W, const float* __restrict__ mlp1_b,
                        const float* __restrict__ mlp2_W, const float* __restrict__ mlp2_b,
                        float* __restrict__ out) {
    __shared__ float hidden[16];
    int b = blockIdx.x;
    int tid = threadIdx.x;
    int w = tid >> 5, lane = tid & 31;
    const float* seg = &g_seg[(size_t)b * HH];
    float s = 0.f;
#pragma unroll
    for (int k = lane; k < HH; k += 32) s += seg[k] * mlp1_W[(size_t)w * HH + k];
#pragma unroll
    for (int o = 16; o; o >>= 1) s += __shfl_xor_sync(0xffffffffu, s, o);
    if (lane == 0) hidden[w] = s + mlp1_b[w];
    __syncthreads();
    if (tid < 2) {
        float o = mlp2_b[tid];
#pragma unroll
        for (int j = 0; j < 16; j++) o += hidden[j] * mlp2_W[tid * 16 + j];
        out[b * 2 + tid] = o;
    }
}

// -----------------------------------------------------------------------------
extern "C" void kernel_launch(void* const* d_in, const int* in_sizes, int n_in,
                              void* d_out, int out_size) {
    const float* lstm_input = (const float*)d_in[0];
    const float* eps_u      = (const float*)d_in[1];
    const float* W_ih       = (const float*)d_in[2];
    const float* W_hh       = (const float*)d_in[3];
    const float* b_ih       = (const float*)d_in[4];
    const float* b_hh       = (const float*)d_in[5];
    const float* fc1_W      = (const float*)d_in[6];
    const float* fc1_b      = (const float*)d_in[7];
    const float* fc2_W      = (const float*)d_in[8];
    const float* fc2_b      = (const float*)d_in[9];
    const float* mlp1_W     = (const float*)d_in[10];
    const float* mlp1_b     = (const float*)d_in[11];
    const float* mlp2_W     = (const float*)d_in[12];
    const float* mlp2_b     = (const float*)d_in[13];
    const int*   lengths    = (const int*)d_in[14];

    float* out = (float*)d_out;
    float* passedZ = out + BP * 2;   // tuple order: final[256,2] then passed_Z[N,512]

    float *xw, *flat;
    cudaGetSymbolAddress((void**)&xw, g_xW);
    cudaGetSymbolAddress((void**)&flat, g_flat);

    cudaFuncSetAttribute(tgemm_mma, cudaFuncAttributeMaxDynamicSharedMemorySize, GEMM_SMEM);

    // 1. init states/offsets
    k_init<<<(BP * HH + 255) / 256, 256>>>(lengths);

    // 2. xW = X @ W_ih^T + b_ih + b_hh   [65408 x 2048]  (tf32 tensor cores)
    tgemm_mma<<<dim3(GG / 128, NN / 128), 256, GEMM_SMEM>>>(lstm_input, W_ih, b_ih, b_hh, xw, GG);

    // 3. sequential LSTM recurrence
    for (int t = 0; t < TT; t++)
        k_lstm_step<<<dim3(BP / 32, HH / 32), 256>>>(W_hh, lengths, t);

    // 4. passed_Z = flat @ fc1_W^T + fc1_b  -> straight into d_out (tf32 TC)
    tgemm_mma<<<dim3(DD / 128, NN / 128), 256, GEMM_SMEM>>>(flat, fc1_W, fc1_b, nullptr, passedZ, DD);

    // 5. attention gate per flat row
    k_att<<<(NN * 32 + 255) / 256, 256>>>(passedZ, fc2_W, fc2_b, eps_u);

    // 6. gated per-person segment sum
    k_seg<<<BP, HH>>>(lengths);

    // 7. final MLP -> out[0:512]
    k_final<<<BP, 512>>>(mlp1_W, mlp1_b, mlp2_W, mlp2_b, out);
}

// round 7
// speedup vs baseline: 2.4688x; 1.3075x over previous
#include <cuda_runtime.h>
#include <cuda.h>
#include <cuda_bf16.h>
#include <math.h>
#include <stdint.h>

// Problem constants (fixed by the dataset: B=256, D=H=512, lengths=128..383)
#define NN 65408
#define BP 256
#define DD 512
#define HH 512
#define GG 2048
#define TT 383
#define KK 512

// ---------------- device scratch ---------------------------------------------
__device__ __align__(16) float g_xW[(size_t)NN * GG];
__device__ __align__(16) float g_flat[(size_t)NN * HH];
__device__ __align__(16) float g_h2[2][BP * HH];   // double-buffered h
__device__ __align__(16) float g_c[BP * HH];
__device__ __align__(16) float g_att[NN];
__device__ __align__(16) float g_seg[BP * HH];
__device__ __align__(16) uint4 g_WP[(size_t)GG * 128];  // W_hh split: {b0,b1,s0,s1} per (n,ks,tig)
__device__ int      g_off[BP];
__device__ unsigned g_bar[8];

__device__ __forceinline__ float sigf(float x) { return 1.0f / (1.0f + expf(-x)); }

__device__ __forceinline__ uint32_t f2tf32(float f) {
    uint32_t r; asm("cvt.rna.tf32.f32 %0, %1;" : "=r"(r) : "f"(f)); return r;
}
__device__ __forceinline__ void mma_tf32(float& c0, float& c1, float& c2, float& c3,
                                         uint32_t a0, uint32_t a1, uint32_t a2, uint32_t a3,
                                         uint32_t b0, uint32_t b1) {
    asm volatile("mma.sync.aligned.m16n8k8.row.col.f32.tf32.tf32.f32 "
        "{%0,%1,%2,%3}, {%4,%5,%6,%7}, {%8,%9}, {%0,%1,%2,%3};"
        : "+f"(c0), "+f"(c1), "+f"(c2), "+f"(c3)
        : "r"(a0), "r"(a1), "r"(a2), "r"(a3), "r"(b0), "r"(b1));
}
__device__ __forceinline__ void mma_bf16(float* c,
                                         uint32_t a0, uint32_t a1, uint32_t a2, uint32_t a3,
                                         uint32_t b0, uint32_t b1) {
    asm volatile("mma.sync.aligned.m16n8k16.row.col.f32.bf16.bf16.f32 "
        "{%0,%1,%2,%3}, {%4,%5,%6,%7}, {%8,%9}, {%0,%1,%2,%3};"
        : "+f"(c[0]), "+f"(c[1]), "+f"(c[2]), "+f"(c[3])
        : "r"(a0), "r"(a1), "r"(a2), "r"(a3), "r"(b0), "r"(b1));
}
__device__ __forceinline__ uint32_t u32of(__nv_bfloat162 v) {
    uint32_t r; memcpy(&r, &v, 4); return r;
}

// =================== tf32 mma.sync NT GEMM (unchanged from R6) ==============
#define GPITCH 36
#define STAGE_F (128 * GPITCH)
#define GEMM_SMEM (4 * STAGE_F * 4)

__global__ void __launch_bounds__(256)
tgemm_mma(const float* __restrict__ A, const float* __restrict__ Bm,
          const float* __restrict__ bias1, const float* __restrict__ bias2,
          float* __restrict__ C, int Ncols) {
    extern __shared__ __align__(16) float sm[];
    float* As[2] = { sm,           sm + 2 * STAGE_F };
    float* Bs[2] = { sm + STAGE_F, sm + 3 * STAGE_F };

    const int tid = threadIdx.x;
    const int wid = tid >> 5, lane = tid & 31;
    const int grp = lane >> 2, tig = lane & 3;
    const int warpM = wid >> 2, warpN = wid & 3;
    const size_t m0 = (size_t)blockIdx.y * 128;
    const int    n0 = blockIdx.x * 128;

    const int lrow = tid >> 1;
    const int lcb  = (tid & 1) * 16;
    const float* Ag = A  + (m0 + lrow) * KK;
    const float* Bg = Bm + (size_t)(n0 + lrow) * KK;

    float4 ar[4], br[4];
    auto ldchunk = [&](int c) {
#pragma unroll
        for (int q = 0; q < 4; q++) {
            ar[q] = *(const float4*)&Ag[c * 32 + lcb + q * 4];
            br[q] = *(const float4*)&Bg[c * 32 + lcb + q * 4];
        }
    };
    auto stchunk = [&](int s) {
        float* a = As[s] + lrow * GPITCH + lcb;
        float* b = Bs[s] + lrow * GPITCH + lcb;
#pragma unroll
        for (int q = 0; q < 4; q++) {
            *(float4*)&a[q * 4] = ar[q];
            *(float4*)&b[q * 4] = br[q];
        }
    };

    float acc[4][4][4];
#pragma unroll
    for (int i = 0; i < 4; i++)
#pragma unroll
        for (int j = 0; j < 4; j++)
#pragma unroll
            for (int k = 0; k < 4; k++) acc[i][j][k] = 0.f;

    ldchunk(0); stchunk(0);
    __syncthreads();

    for (int c = 0; c < KK / 32; c++) {
        const int s = c & 1;
        if (c + 1 < KK / 32) ldchunk(c + 1);

        const float* Aw = As[s] + (warpM * 64 + grp) * GPITCH;
        const float* Bw = Bs[s] + (warpN * 32 + grp) * GPITCH;
#pragma unroll
        for (int k0 = 0; k0 < 32; k0 += 8) {
            uint32_t af[4][4], bf[4][2];
#pragma unroll
            for (int mf = 0; mf < 4; mf++) {
                const float* p = Aw + mf * 16 * GPITCH + k0;
                af[mf][0] = f2tf32(p[tig]);
                af[mf][1] = f2tf32(p[8 * GPITCH + tig]);
                af[mf][2] = f2tf32(p[tig + 4]);
                af[mf][3] = f2tf32(p[8 * GPITCH + tig + 4]);
            }
#pragma unroll
            for (int nf = 0; nf < 4; nf++) {
                const float* p = Bw + nf * 8 * GPITCH + k0;
                bf[nf][0] = f2tf32(p[tig]);
                bf[nf][1] = f2tf32(p[tig + 4]);
            }
#pragma unroll
            for (int mf = 0; mf < 4; mf++)
#pragma unroll
                for (int nf = 0; nf < 4; nf++)
                    mma_tf32(acc[mf][nf][0], acc[mf][nf][1], acc[mf][nf][2], acc[mf][nf][3],
                             af[mf][0], af[mf][1], af[mf][2], af[mf][3],
                             bf[nf][0], bf[nf][1]);
        }
        __syncthreads();
        if (c + 1 < KK / 32) { stchunk((c + 1) & 1); __syncthreads(); }
    }

#pragma unroll
    for (int mf = 0; mf < 4; mf++) {
        size_t r0 = m0 + warpM * 64 + mf * 16 + grp;
#pragma unroll
        for (int nf = 0; nf < 4; nf++) {
            int col = n0 + warpN * 32 + nf * 8 + 2 * tig;
            float b0 = bias1[col], b1 = bias1[col + 1];
            if (bias2) { b0 += bias2[col]; b1 += bias2[col + 1]; }
            float2 v0 = { acc[mf][nf][0] + b0, acc[mf][nf][1] + b1 };
            float2 v1 = { acc[mf][nf][2] + b0, acc[mf][nf][3] + b1 };
            *(float2*)&C[r0 * (size_t)Ncols + col] = v0;
            *(float2*)&C[(r0 + 8) * (size_t)Ncols + col] = v1;
        }
    }
}

// ---------------- init: zero states + offsets + barrier counters ------------
__global__ void k_init(const int* __restrict__ lengths) {
    int tid = blockIdx.x * blockDim.x + threadIdx.x;
    if (tid < 2 * BP * HH) ((float*)g_h2)[tid] = 0.f;
    if (tid < BP * HH) { g_c[tid] = 0.f; g_seg[tid] = 0.f; }
    if (tid < 8) g_bar[tid] = 0u;
    if (tid == 0) {
        int acc = 0;
        for (int b = 0; b < BP; b++) { g_off[b] = acc; acc += lengths[b]; }
    }
}

// ---------------- prep: split W_hh into packed bf16 big+small ---------------
// g_WP[n*128 + ks*4 + tig] = { big(k0,k0+1), big(k0+8,k0+9), small(...), small(...) }
// with k0 = 16*ks + 2*tig.
__global__ void k_prepw(const float* __restrict__ W) {
    int id = blockIdx.x * blockDim.x + threadIdx.x;
    if (id >= GG * 128) return;
    int n = id >> 7;
    int r = id & 127;
    int ks = r >> 2, tig = r & 3;
    const float* wr = W + (size_t)n * KK + 16 * ks;
    float w0 = wr[2 * tig], w1 = wr[2 * tig + 1];
    float w2 = wr[2 * tig + 8], w3 = wr[2 * tig + 9];
    __nv_bfloat162 b0 = __floats2bfloat162_rn(w0, w1);
    __nv_bfloat162 b1 = __floats2bfloat162_rn(w2, w3);
    float r0 = w0 - __bfloat162float(__low2bfloat16(b0));
    float r1 = w1 - __bfloat162float(__high2bfloat16(b0));
    float r2 = w2 - __bfloat162float(__low2bfloat16(b1));
    float r3 = w3 - __bfloat162float(__high2bfloat16(b1));
    __nv_bfloat162 s0 = __floats2bfloat162_rn(r0, r1);
    __nv_bfloat162 s1 = __floats2bfloat162_rn(r2, r3);
    g_WP[id] = make_uint4(u32of(b0), u32of(b1), u32of(s0), u32of(s1));
}

// ---------------- persistent LSTM recurrence --------------------------------
// grid (8 person-groups, 16 hcol-groups) = 128 CTAs, 256 thr.
// CTA tile: 32 persons x 128 gate-cols (warpN = gate). bf16 split 3-term mma.
// Per-person-group barrier (16 CTAs, monotonic counter). h double-buffered.
#define HP_PITCH 129                       // uint4 per person (pad for banks)
#define GT_PITCH 34
#define PSM_BYTES (32 * HP_PITCH * 16 + 4 * 32 * GT_PITCH * 4)

__global__ void __launch_bounds__(256)
k_lstm_persist(const int* __restrict__ lengths) {
    extern __shared__ __align__(16) uint4 smraw[];
    uint4* HP = smraw;                          // [32][HP_PITCH]
    float* GT = (float*)(smraw + 32 * HP_PITCH); // [4][32][GT_PITCH]

    __shared__ int len_s[32];
    __shared__ int off_s[32];
    __shared__ int s_tmax;

    const int tid = threadIdx.x;
    const int pg = blockIdx.x, cg = blockIdx.y;
    const int p0 = pg * 32, hc0 = cg * 32;
    const int wid = tid >> 5, lane = tid & 31;
    const int grp = lane >> 2, tig = lane & 3;
    const int warpM = wid >> 2, warpN = wid & 3;

    if (wid == 0) {
        int L = lengths[p0 + lane];
        len_s[lane] = L;
        off_s[lane] = g_off[p0 + lane];
        int m = L;
#pragma unroll
        for (int o = 16; o; o >>= 1) m = max(m, __shfl_xor_sync(0xffffffffu, m, o));
        if (lane == 0) s_tmax = m;
    }
    __syncthreads();
    const int tmax = s_tmax;

    const int fp   = tid & 31;    // fill: person
    const int fsub = tid >> 5;    // fill: k-slice 0..7

    const int rA = 16 * warpM + grp;

    for (int t = 0; t < tmax; t++) {
        // ---- build h split (big+small bf16 packed) into smem ----
        const float* hsrc = g_h2[t & 1] + (size_t)(p0 + fp) * HH;
#pragma unroll
        for (int i = 0; i < 4; i++) {
            int ks = fsub * 4 + i;
            const float4* hv = (const float4*)(hsrc + 16 * ks);
            float4 v0 = __ldcg(hv + 0), v1 = __ldcg(hv + 1);
            float4 v2 = __ldcg(hv + 2), v3 = __ldcg(hv + 3);
            float lo[4][2] = {{v0.x, v0.y}, {v0.z, v0.w}, {v1.x, v1.y}, {v1.z, v1.w}};
            float hi[4][2] = {{v2.x, v2.y}, {v2.z, v2.w}, {v3.x, v3.y}, {v3.z, v3.w}};
#pragma unroll
            for (int tg = 0; tg < 4; tg++) {
                __nv_bfloat162 bl = __floats2bfloat162_rn(lo[tg][0], lo[tg][1]);
                __nv_bfloat162 bh = __floats2bfloat162_rn(hi[tg][0], hi[tg][1]);
                float rl0 = lo[tg][0] - __bfloat162float(__low2bfloat16(bl));
                float rl1 = lo[tg][1] - __bfloat162float(__high2bfloat16(bl));
                float rh0 = hi[tg][0] - __bfloat162float(__low2bfloat16(bh));
                float rh1 = hi[tg][1] - __bfloat162float(__high2bfloat16(bh));
                __nv_bfloat162 sl = __floats2bfloat162_rn(rl0, rl1);
                __nv_bfloat162 sh = __floats2bfloat162_rn(rh0, rh1);
                HP[fp * HP_PITCH + ks * 4 + tg] =
                    make_uint4(u32of(bl), u32of(bh), u32of(sl), u32of(sh));
            }
        }
        __syncthreads();

        // ---- 32x128x512 gates GEMM: 3-term bf16 split mma ----
        float acc[4][4];
#pragma unroll
        for (int i = 0; i < 4; i++)
#pragma unroll
            for (int j = 0; j < 4; j++) acc[i][j] = 0.f;

#pragma unroll 4
        for (int ks = 0; ks < 32; ks++) {
            uint4 Ea = HP[rA * HP_PITCH + ks * 4 + tig];
            uint4 Eb = HP[(rA + 8) * HP_PITCH + ks * 4 + tig];
#pragma unroll
            for (int nf = 0; nf < 4; nf++) {
                int ng = warpN * HH + hc0 + nf * 8 + grp;
                uint4 Wv = g_WP[(size_t)ng * 128 + ks * 4 + tig];
                mma_bf16(acc[nf], Ea.x, Eb.x, Ea.y, Eb.y, Wv.x, Wv.y);  // hb*Wb
                mma_bf16(acc[nf], Ea.z, Eb.z, Ea.w, Eb.w, Wv.x, Wv.y);  // hs*Wb
                mma_bf16(acc[nf], Ea.x, Eb.x, Ea.y, Eb.y, Wv.z, Wv.w);  // hb*Ws
            }
        }
        __syncthreads();

        // ---- gate exchange to smem (warpN = gate) ----
#pragma unroll
        for (int nf = 0; nf < 4; nf++) {
            int col = nf * 8 + 2 * tig;
            float2 vlo = { acc[nf][0], acc[nf][1] };
            float2 vhi = { acc[nf][2], acc[nf][3] };
            *(float2*)&GT[warpN * (32 * GT_PITCH) + rA * GT_PITCH + col] = vlo;
            *(float2*)&GT[warpN * (32 * GT_PITCH) + (rA + 8) * GT_PITCH + col] = vhi;
        }
        __syncthreads();

        // ---- epilogue: activations + state update ----
#pragma unroll
        for (int q = tid; q < 1024; q += 256) {
            int p = q >> 5, hc = q & 31;
            if (t < len_s[p]) {
                size_t fi = (size_t)(off_s[p] + t);
                size_t xb = fi * GG + hc0 + hc;
                float gi = GT[0 * (32 * GT_PITCH) + p * GT_PITCH + hc] + g_xW[xb + 0 * HH];
                float gf = GT[1 * (32 * GT_PITCH) + p * GT_PITCH + hc] + g_xW[xb + 1 * HH];
                float gg = GT[2 * (32 * GT_PITCH) + p * GT_PITCH + hc] + g_xW[xb + 2 * HH];
                float go = GT[3 * (32 * GT_PITCH) + p * GT_PITCH + hc] + g_xW[xb + 3 * HH];
                size_t si = (size_t)(p0 + p) * HH + hc0 + hc;
                float cv = g_c[si];
                float cn = sigf(gf) * cv + sigf(gi) * tanhf(gg);
                float hn = sigf(go) * tanhf(cn);
                g_c[si] = cn;
                __stcg(&g_h2[(t + 1) & 1][si], hn);
                g_flat[fi * HH + hc0 + hc] = hn;
            }
        }

        // ---- per-group barrier (16 CTAs, monotonic counter) ----
        __syncthreads();
        if (tid == 0) {
            __threadfence();
            atomicAdd(&g_bar[pg], 1u);
            unsigned target = 16u * (unsigned)(t + 1);
            while (*((volatile unsigned*)&g_bar[pg]) < target) __nanosleep(32);
            __threadfence();
        }
        __syncthreads();
    }
}

// ---------------- attention logits + concrete-relaxation gate ---------------
__global__ void k_att(const float* __restrict__ passedZ,
                      const float* __restrict__ fc2_W, const float* __restrict__ fc2_b,
                      const float* __restrict__ eps_u) {
    int gwarp = (blockIdx.x * blockDim.x + threadIdx.x) >> 5;
    int lane = threadIdx.x & 31;
    if (gwarp >= NN) return;
    const float* row = passedZ + (size_t)gwarp * DD;
    float s = 0.f;
#pragma unroll
    for (int k = lane; k < DD; k += 32) s += row[k] * fc2_W[k];
#pragma unroll
    for (int o = 16; o; o >>= 1) s += __shfl_xor_sync(0xffffffffu, s, o);
    if (lane == 0) {
        float logit = s + fc2_b[0];
        float eu = eps_u[gwarp];
        float eps = (2.0f * 1e-4f - 1.0f) * eu + (1.0f - 1e-4f);
        float gate = logf(eps) - logf(1.0f - eps) + logit;
        g_att[gwarp] = sigf(gate);
    }
}

// ---------------- gated segment sum ------------------------------------------
__global__ void k_seg(const int* __restrict__ lengths) {
    int b = blockIdx.x;
    int col = threadIdx.x;
    int off = g_off[b];
    int L = lengths[b];
    float acc = 0.f;
    for (int r = 0; r < L; r++) {
        int n = off + r;
        acc += g_flat[(size_t)n * HH + col] * g_att[n];
    }
    g_seg[(size_t)b * HH + col] = acc;
}

// ---------------- final tiny MLP ---------------------------------------------
__global__ void k_final(const float* __restrict__ mlp1_W, const float* __restrict__ mlp1_b,
                        const float* __restrict__ mlp2_W, const float* __restrict__ mlp2_b,
                        float* __restrict__ out) {
    __shared__ float hidden[16];
    int b = blockIdx.x;
    int tid = threadIdx.x;
    int w = tid >> 5, lane = tid & 31;
    const float* seg = &g_seg[(size_t)b * HH];
    float s = 0.f;
#pragma unroll
    for (int k = lane; k < HH; k += 32) s += seg[k] * mlp1_W[(size_t)w * HH + k];
#pragma unroll
    for (int o = 16; o; o >>= 1) s += __shfl_xor_sync(0xffffffffu, s, o);
    if (lane == 0) hidden[w] = s + mlp1_b[w];
    __syncthreads();
    if (tid < 2) {
        float o = mlp2_b[tid];
#pragma unroll
        for (int j = 0; j < 16; j++) o += hidden[j] * mlp2_W[tid * 16 + j];
        out[b * 2 + tid] = o;
    }
}

// -----------------------------------------------------------------------------
extern "C" void kernel_launch(void* const* d_in, const int* in_sizes, int n_in,
                              void* d_out, int out_size) {
    const float* lstm_input = (const float*)d_in[0];
    const float* eps_u      = (const float*)d_in[1];
    const float* W_ih       = (const float*)d_in[2];
    const float* W_hh       = (const float*)d_in[3];
    const float* b_ih       = (const float*)d_in[4];
    const float* b_hh       = (const float*)d_in[5];
    const float* fc1_W      = (const float*)d_in[6];
    const float* fc1_b      = (const float*)d_in[7];
    const float* fc2_W      = (const float*)d_in[8];
    const float* fc2_b      = (const float*)d_in[9];
    const float* mlp1_W     = (const float*)d_in[10];
    const float* mlp1_b     = (const float*)d_in[11];
    const float* mlp2_W     = (const float*)d_in[12];
    const float* mlp2_b     = (const float*)d_in[13];
    const int*   lengths    = (const int*)d_in[14];

    float* out = (float*)d_out;
    float* passedZ = out + BP * 2;   // tuple order: final[256,2] then passed_Z[N,512]

    float *xw, *flat;
    cudaGetSymbolAddress((void**)&xw, g_xW);
    cudaGetSymbolAddress((void**)&flat, g_flat);

    cudaFuncSetAttribute(tgemm_mma, cudaFuncAttributeMaxDynamicSharedMemorySize, GEMM_SMEM);
    cudaFuncSetAttribute(k_lstm_persist, cudaFuncAttributeMaxDynamicSharedMemorySize, PSM_BYTES);

    // 1. init states/offsets/barriers
    k_init<<<(2 * BP * HH + 255) / 256, 256>>>(lengths);

    // 2. split W_hh into packed bf16 big+small
    k_prepw<<<(GG * 128 + 255) / 256, 256>>>(W_hh);

    // 3. xW = X @ W_ih^T + b_ih + b_hh   (tf32 tensor cores)
    tgemm_mma<<<dim3(GG / 128, NN / 128), 256, GEMM_SMEM>>>(lstm_input, W_ih, b_ih, b_hh, xw, GG);

    // 4. full LSTM recurrence in ONE persistent launch
    k_lstm_persist<<<dim3(8, 16), 256, PSM_BYTES>>>(lengths);

    // 5. passed_Z = flat @ fc1_W^T + fc1_b  -> straight into d_out
    tgemm_mma<<<dim3(DD / 128, NN / 128), 256, GEMM_SMEM>>>(flat, fc1_W, fc1_b, nullptr, passedZ, DD);

    // 6. attention gate per flat row
    k_att<<<(NN * 32 + 255) / 256, 256>>>(passedZ, fc2_W, fc2_b, eps_u);

    // 7. gated per-person segment sum
    k_seg<<<BP, HH>>>(lengths);

    // 8. final MLP -> out[0:512]
    k_final<<<BP, 512>>>(mlp1_W, mlp1_b, mlp2_W, mlp2_b, out);
}

// round 8
// speedup vs baseline: 3.8236x; 1.5488x over previous
#include <cuda_runtime.h>
#include <cuda.h>
#include <math.h>
#include <stdint.h>

// Problem constants (fixed by the dataset: B=256, D=H=512, lengths=128..383)
#define NN 65408
#define BP 256
#define DD 512
#define HH 512
#define GG 2048
#define TT 383
#define KK 512

// ---------------- device scratch ---------------------------------------------
__device__ __align__(16) float g_xW[(size_t)NN * GG];
__device__ __align__(16) float g_flat[(size_t)NN * HH];
__device__ __align__(16) float g_h2[2][BP * HH];   // double-buffered h
__device__ __align__(16) float g_c[BP * HH];
__device__ __align__(16) float g_att[NN];
__device__ __align__(16) float g_seg[BP * HH];
// W_hh packed in tf32 B-fragment order: GW[n*128 + ks2*4 + tig] =
//   { w[n][16ks2+tig], w[n][16ks2+4+tig], w[n][16ks2+8+tig], w[n][16ks2+12+tig] }
__device__ __align__(16) uint4 g_GW[(size_t)GG * 128];
__device__ int      g_off[BP];
__device__ unsigned g_bar[8];

__device__ __forceinline__ float sigf(float x) { return 1.0f / (1.0f + expf(-x)); }

__device__ __forceinline__ uint32_t f2tf32(float f) {
    uint32_t r; asm("cvt.rna.tf32.f32 %0, %1;" : "=r"(r) : "f"(f)); return r;
}
__device__ __forceinline__ void mma_tf32(float* c,
                                         uint32_t a0, uint32_t a1, uint32_t a2, uint32_t a3,
                                         uint32_t b0, uint32_t b1) {
    asm volatile("mma.sync.aligned.m16n8k8.row.col.f32.tf32.tf32.f32 "
        "{%0,%1,%2,%3}, {%4,%5,%6,%7}, {%8,%9}, {%0,%1,%2,%3};"
        : "+f"(c[0]), "+f"(c[1]), "+f"(c[2]), "+f"(c[3])
        : "r"(a0), "r"(a1), "r"(a2), "r"(a3), "r"(b0), "r"(b1));
}

// =================== tf32 mma.sync NT GEMM (cvt moved to smem store) ========
#define GPITCH 36
#define STAGE_F (128 * GPITCH)
#define GEMM_SMEM (4 * STAGE_F * 4)

__global__ void __launch_bounds__(256)
tgemm_mma(const float* __restrict__ A, const float* __restrict__ Bm,
          const float* __restrict__ bias1, const float* __restrict__ bias2,
          float* __restrict__ C, int Ncols) {
    extern __shared__ __align__(16) float sm[];
    float* As[2] = { sm,           sm + 2 * STAGE_F };
    float* Bs[2] = { sm + STAGE_F, sm + 3 * STAGE_F };

    const int tid = threadIdx.x;
    const int wid = tid >> 5, lane = tid & 31;
    const int grp = lane >> 2, tig = lane & 3;
    const int warpM = wid >> 2, warpN = wid & 3;
    const size_t m0 = (size_t)blockIdx.y * 128;
    const int    n0 = blockIdx.x * 128;

    const int lrow = tid >> 1;
    const int lcb  = (tid & 1) * 16;
    const float* Ag = A  + (m0 + lrow) * KK;
    const float* Bg = Bm + (size_t)(n0 + lrow) * KK;

    float4 ar[4], br[4];
    auto ldchunk = [&](int c) {
#pragma unroll
        for (int q = 0; q < 4; q++) {
            ar[q] = *(const float4*)&Ag[c * 32 + lcb + q * 4];
            br[q] = *(const float4*)&Bg[c * 32 + lcb + q * 4];
        }
    };
    auto cvt4 = [](float4 v) {
        return make_uint4(f2tf32(v.x), f2tf32(v.y), f2tf32(v.z), f2tf32(v.w));
    };
    auto stchunk = [&](int s) {
        float* a = As[s] + lrow * GPITCH + lcb;
        float* b = Bs[s] + lrow * GPITCH + lcb;
#pragma unroll
        for (int q = 0; q < 4; q++) {
            *(uint4*)&a[q * 4] = cvt4(ar[q]);
            *(uint4*)&b[q * 4] = cvt4(br[q]);
        }
    };

    float acc[4][4][4];
#pragma unroll
    for (int i = 0; i < 4; i++)
#pragma unroll
        for (int j = 0; j < 4; j++)
#pragma unroll
            for (int k = 0; k < 4; k++) acc[i][j][k] = 0.f;

    ldchunk(0); stchunk(0);
    __syncthreads();

    for (int c = 0; c < KK / 32; c++) {
        const int s = c & 1;
        if (c + 1 < KK / 32) ldchunk(c + 1);

        const float* Aw = As[s] + (warpM * 64 + grp) * GPITCH;
        const float* Bw = Bs[s] + (warpN * 32 + grp) * GPITCH;
#pragma unroll
        for (int k0 = 0; k0 < 32; k0 += 8) {
            uint32_t af[4][4], bf[4][2];
#pragma unroll
            for (int mf = 0; mf < 4; mf++) {
                const float* p = Aw + mf * 16 * GPITCH + k0;
                af[mf][0] = __float_as_uint(p[tig]);
                af[mf][1] = __float_as_uint(p[8 * GPITCH + tig]);
                af[mf][2] = __float_as_uint(p[tig + 4]);
                af[mf][3] = __float_as_uint(p[8 * GPITCH + tig + 4]);
            }
#pragma unroll
            for (int nf = 0; nf < 4; nf++) {
                const float* p = Bw + nf * 8 * GPITCH + k0;
                bf[nf][0] = __float_as_uint(p[tig]);
                bf[nf][1] = __float_as_uint(p[tig + 4]);
            }
#pragma unroll
            for (int mf = 0; mf < 4; mf++)
#pragma unroll
                for (int nf = 0; nf < 4; nf++)
                    mma_tf32(acc[mf][nf],
                             af[mf][0], af[mf][1], af[mf][2], af[mf][3],
                             bf[nf][0], bf[nf][1]);
        }
        __syncthreads();
        if (c + 1 < KK / 32) { stchunk((c + 1) & 1); __syncthreads(); }
    }

#pragma unroll
    for (int mf = 0; mf < 4; mf++) {
        size_t r0 = m0 + warpM * 64 + mf * 16 + grp;
#pragma unroll
        for (int nf = 0; nf < 4; nf++) {
            int col = n0 + warpN * 32 + nf * 8 + 2 * tig;
            float b0 = bias1[col], b1 = bias1[col + 1];
            if (bias2) { b0 += bias2[col]; b1 += bias2[col + 1]; }
            float2 v0 = { acc[mf][nf][0] + b0, acc[mf][nf][1] + b1 };
            float2 v1 = { acc[mf][nf][2] + b0, acc[mf][nf][3] + b1 };
            *(float2*)&C[r0 * (size_t)Ncols + col] = v0;
            *(float2*)&C[(r0 + 8) * (size_t)Ncols + col] = v1;
        }
    }
}

// ---------------- init: zero states + offsets + barrier counters ------------
__global__ void k_init(const int* __restrict__ lengths) {
    int tid = blockIdx.x * blockDim.x + threadIdx.x;
    if (tid < 2 * BP * HH) ((float*)g_h2)[tid] = 0.f;
    if (tid < BP * HH) { g_c[tid] = 0.f; g_seg[tid] = 0.f; }
    if (tid < 8) g_bar[tid] = 0u;
    if (tid == 0) {
        int acc = 0;
        for (int b = 0; b < BP; b++) { g_off[b] = acc; acc += lengths[b]; }
    }
}

// ---------------- prep: pack W_hh into tf32 B-fragment order ----------------
__global__ void k_prepw(const float* __restrict__ W) {
    int id = blockIdx.x * blockDim.x + threadIdx.x;
    if (id >= GG * 128) return;
    int n = id >> 7;
    int r = id & 127;
    int ks2 = r >> 2, tg = r & 3;
    const float* wr = W + (size_t)n * KK + 16 * ks2;
    g_GW[id] = make_uint4(f2tf32(wr[tg]), f2tf32(wr[tg + 4]),
                          f2tf32(wr[tg + 8]), f2tf32(wr[tg + 12]));
}

// ---------------- persistent LSTM recurrence (tf32 mma, 512 thr) ------------
// grid (8 pgroups, 16 cgroups) = 128 CTAs. CTA tile: 32 persons x 128 gatecols.
// 16 warps: warpM = wid>>3 (persons 16*wm..+15), warpN = wid&7 (16 gatecols).
// HA: A-frag-packed h (tf32), XOR-swizzled slots. Per-group spin barrier.
#define HA_U4 (16 * 65 * 4)                    // 4160 uint4 = 66560 B
#define GT_PITCH2 136
#define PSM2 (HA_U4 * 16 + 32 * GT_PITCH2 * 4) // 66560 + 17408 = 83968 B

__global__ void __launch_bounds__(512)
k_lstm_persist(const int* __restrict__ lengths) {
    extern __shared__ __align__(16) uint4 smraw[];
    uint4* HA = smraw;                             // [(m*8+grp)*65 + ks]*4 + slot
    float* GT = (float*)(smraw + HA_U4);           // [32][GT_PITCH2]

    __shared__ int len_s[32];
    __shared__ int off_s[32];
    __shared__ int s_tmax;

    const int tid = threadIdx.x;
    const int pg = blockIdx.x, cg = blockIdx.y;
    const int p0 = pg * 32, hc0 = cg * 32;
    const int wid = tid >> 5, lane = tid & 31;
    const int grp = lane >> 2, tig = lane & 3;
    const int warpM = wid >> 3, warpN = wid & 7;

    if (wid == 0) {
        int L = lengths[p0 + lane];
        len_s[lane] = L;
        off_s[lane] = g_off[p0 + lane];
        int m = L;
#pragma unroll
        for (int o = 16; o; o >>= 1) m = max(m, __shfl_xor_sync(0xffffffffu, m, o));
        if (lane == 0) s_tmax = m;
    }
    __syncthreads();
    const int tmax = s_tmax;

    // W row indices for the two 8-col N-fragments of this warp
    const int gate = warpN >> 1;
    const int hcb  = (warpN & 1) * 16;
    const int nrow0 = gate * HH + hc0 + hcb + grp;
    const int nrow1 = nrow0 + 8;

    const int rA = 16 * warpM + grp;                   // person row (and +8)
    const uint4* HAa = HA + (size_t)(warpM * 8 + grp) * 65 * 4;

    for (int t = 0; t < tmax; t++) {
        // ---- fill HA: h -> tf32, A-fragment layout, 2 tasks/thread ----
        const float* hbuf = g_h2[t & 1];
#pragma unroll
        for (int s = 0; s < 2; s++) {
            int id = tid + s * 512;                    // 0..1023
            int ks = id & 63, g8 = (id >> 6) & 7, m = id >> 9;
            int pa = p0 + 16 * m + g8, pb = pa + 8;
            const float4* Ap = (const float4*)(hbuf + (size_t)pa * HH + 8 * ks);
            const float4* Bp = (const float4*)(hbuf + (size_t)pb * HH + 8 * ks);
            float4 va0 = __ldcg(Ap), va1 = __ldcg(Ap + 1);
            float4 vb0 = __ldcg(Bp), vb1 = __ldcg(Bp + 1);
            uint4* dst = HA + ((size_t)(m * 8 + g8) * 65 + ks) * 4;
            int c = ks & 3;
            dst[0 ^ c] = make_uint4(f2tf32(va0.x), f2tf32(vb0.x), f2tf32(va1.x), f2tf32(vb1.x));
            dst[1 ^ c] = make_uint4(f2tf32(va0.y), f2tf32(vb0.y), f2tf32(va1.y), f2tf32(vb1.y));
            dst[2 ^ c] = make_uint4(f2tf32(va0.z), f2tf32(vb0.z), f2tf32(va1.z), f2tf32(vb1.z));
            dst[3 ^ c] = make_uint4(f2tf32(va0.w), f2tf32(vb0.w), f2tf32(va1.w), f2tf32(vb1.w));
        }
        __syncthreads();

        // ---- 32x128x512 gates GEMM: single-term tf32 mma ----
        float acc[2][4];
#pragma unroll
        for (int i = 0; i < 2; i++)
#pragma unroll
            for (int j = 0; j < 4; j++) acc[i][j] = 0.f;

#pragma unroll 8
        for (int ks2 = 0; ks2 < 32; ks2++) {
            const int ks0 = 2 * ks2, ks1 = ks0 + 1;
            uint4 A0 = HAa[ks0 * 4 + (tig ^ (ks0 & 3))];
            uint4 A1 = HAa[ks1 * 4 + (tig ^ (ks1 & 3))];
            uint4 W0 = g_GW[(size_t)nrow0 * 128 + ks2 * 4 + tig];
            uint4 W1 = g_GW[(size_t)nrow1 * 128 + ks2 * 4 + tig];
            mma_tf32(acc[0], A0.x, A0.y, A0.z, A0.w, W0.x, W0.y);
            mma_tf32(acc[0], A1.x, A1.y, A1.z, A1.w, W0.z, W0.w);
            mma_tf32(acc[1], A0.x, A0.y, A0.z, A0.w, W1.x, W1.y);
            mma_tf32(acc[1], A1.x, A1.y, A1.z, A1.w, W1.z, W1.w);
        }

        // ---- gate exchange to smem ----
#pragma unroll
        for (int nf = 0; nf < 2; nf++) {
            int cb = warpN * 16 + nf * 8 + 2 * tig;
            *(float2*)&GT[rA * GT_PITCH2 + cb]       = make_float2(acc[nf][0], acc[nf][1]);
            *(float2*)&GT[(rA + 8) * GT_PITCH2 + cb] = make_float2(acc[nf][2], acc[nf][3]);
        }
        __syncthreads();

        // ---- epilogue: activations + state update (2 outs/thread) ----
#pragma unroll
        for (int s = 0; s < 2; s++) {
            int q = tid + s * 512;
            int p = q >> 5, hc = q & 31;
            if (t < len_s[p]) {
                size_t fi = (size_t)(off_s[p] + t);
                size_t xb = fi * GG + hc0 + hc;
                float gi = GT[p * GT_PITCH2 + 0 * 32 + hc] + g_xW[xb + 0 * HH];
                float gf = GT[p * GT_PITCH2 + 1 * 32 + hc] + g_xW[xb + 1 * HH];
                float gg = GT[p * GT_PITCH2 + 2 * 32 + hc] + g_xW[xb + 2 * HH];
                float go = GT[p * GT_PITCH2 + 3 * 32 + hc] + g_xW[xb + 3 * HH];
                size_t si = (size_t)(p0 + p) * HH + hc0 + hc;
                float cv = g_c[si];
                float cn = sigf(gf) * cv + sigf(gi) * tanhf(gg);
                float hn = sigf(go) * tanhf(cn);
                g_c[si] = cn;
                __stcg(&g_h2[(t + 1) & 1][si], hn);
                g_flat[fi * HH + hc0 + hc] = hn;
            }
        }

        // ---- per-group barrier (16 CTAs, monotonic counter) ----
        __syncthreads();
        if (tid == 0) {
            __threadfence();
            atomicAdd(&g_bar[pg], 1u);
            unsigned target = 16u * (unsigned)(t + 1);
            while (*((volatile unsigned*)&g_bar[pg]) < target) __nanosleep(32);
            __threadfence();
        }
        __syncthreads();
    }
}

// ---------------- attention logits + concrete-relaxation gate ---------------
__global__ void k_att(const float* __restrict__ passedZ,
                      const float* __restrict__ fc2_W, const float* __restrict__ fc2_b,
                      const float* __restrict__ eps_u) {
    int gwarp = (blockIdx.x * blockDim.x + threadIdx.x) >> 5;
    int lane = threadIdx.x & 31;
    if (gwarp >= NN) return;
    const float* row = passedZ + (size_t)gwarp * DD;
    float s = 0.f;
#pragma unroll
    for (int k = lane; k < DD; k += 32) s += row[k] * fc2_W[k];
#pragma unroll
    for (int o = 16; o; o >>= 1) s += __shfl_xor_sync(0xffffffffu, s, o);
    if (lane == 0) {
        float logit = s + fc2_b[0];
        float eu = eps_u[gwarp];
        float eps = (2.0f * 1e-4f - 1.0f) * eu + (1.0f - 1e-4f);
        float gate = logf(eps) - logf(1.0f - eps) + logit;
        g_att[gwarp] = sigf(gate);
    }
}

// ---------------- gated segment sum ------------------------------------------
__global__ void k_seg(const int* __restrict__ lengths) {
    int b = blockIdx.x;
    int col = threadIdx.x;
    int off = g_off[b];
    int L = lengths[b];
    float acc = 0.f;
    for (int r = 0; r < L; r++) {
        int n = off + r;
        acc += g_flat[(size_t)n * HH + col] * g_att[n];
    }
    g_seg[(size_t)b * HH + col] = acc;
}

// ---------------- final tiny MLP ---------------------------------------------
__global__ void k_final(const float* __restrict__ mlp1_W, const float* __restrict__ mlp1_b,
                        const float* __restrict__ mlp2_W, const float* __restrict__ mlp2_b,
                        float* __restrict__ out) {
    __shared__ float hidden[16];
    int b = blockIdx.x;
    int tid = threadIdx.x;
    int w = tid >> 5, lane = tid & 31;
    const float* seg = &g_seg[(size_t)b * HH];
    float s = 0.f;
#pragma unroll
    for (int k = lane; k < HH; k += 32) s += seg[k] * mlp1_W[(size_t)w * HH + k];
#pragma unroll
    for (int o = 16; o; o >>= 1) s += __shfl_xor_sync(0xffffffffu, s, o);
    if (lane == 0) hidden[w] = s + mlp1_b[w];
    __syncthreads();
    if (tid < 2) {
        float o = mlp2_b[tid];
#pragma unroll
        for (int j = 0; j < 16; j++) o += hidden[j] * mlp2_W[tid * 16 + j];
        out[b * 2 + tid] = o;
    }
}

// -----------------------------------------------------------------------------
extern "C" void kernel_launch(void* const* d_in, const int* in_sizes, int n_in,
                              void* d_out, int out_size) {
    const float* lstm_input = (const float*)d_in[0];
    const float* eps_u      = (const float*)d_in[1];
    const float* W_ih       = (const float*)d_in[2];
    const float* W_hh       = (const float*)d_in[3];
    const float* b_ih       = (const float*)d_in[4];
    const float* b_hh       = (const float*)d_in[5];
    const float* fc1_W      = (const float*)d_in[6];
    const float* fc1_b      = (const float*)d_in[7];
    const float* fc2_W      = (const float*)d_in[8];
    const float* fc2_b      = (const float*)d_in[9];
    const float* mlp1_W     = (const float*)d_in[10];
    const float* mlp1_b     = (const float*)d_in[11];
    const float* mlp2_W     = (const float*)d_in[12];
    const float* mlp2_b     = (const float*)d_in[13];
    const int*   lengths    = (const int*)d_in[14];

    float* out = (float*)d_out;
    float* passedZ = out + BP * 2;   // tuple order: final[256,2] then passed_Z[N,512]

    float *xw, *flat;
    cudaGetSymbolAddress((void**)&xw, g_xW);
    cudaGetSymbolAddress((void**)&flat, g_flat);

    cudaFuncSetAttribute(tgemm_mma, cudaFuncAttributeMaxDynamicSharedMemorySize, GEMM_SMEM);
    cudaFuncSetAttribute(k_lstm_persist, cudaFuncAttributeMaxDynamicSharedMemorySize, PSM2);

    // 1. init states/offsets/barriers
    k_init<<<(2 * BP * HH + 255) / 256, 256>>>(lengths);

    // 2. pack W_hh into tf32 fragment order
    k_prepw<<<(GG * 128 + 255) / 256, 256>>>(W_hh);

    // 3. xW = X @ W_ih^T + b_ih + b_hh   (tf32 tensor cores)
    tgemm_mma<<<dim3(GG / 128, NN / 128), 256, GEMM_SMEM>>>(lstm_input, W_ih, b_ih, b_hh, xw, GG);

    // 4. full LSTM recurrence in ONE persistent launch (tf32 mma)
    k_lstm_persist<<<dim3(8, 16), 512, PSM2>>>(lengths);

    // 5. passed_Z = flat @ fc1_W^T + fc1_b  -> straight into d_out
    tgemm_mma<<<dim3(DD / 128, NN / 128), 256, GEMM_SMEM>>>(flat, fc1_W, fc1_b, nullptr, passedZ, DD);

    // 6. attention gate per flat row
    k_att<<<(NN * 32 + 255) / 256, 256>>>(passedZ, fc2_W, fc2_b, eps_u);

    // 7. gated per-person segment sum
    k_seg<<<BP, HH>>>(lengths);

    // 8. final MLP -> out[0:512]
    k_final<<<BP, 512>>>(mlp1_W, mlp1_b, mlp2_W, mlp2_b, out);
}

// round 9
// speedup vs baseline: 3.9483x; 1.0326x over previous
#include <cuda_runtime.h>
#include <cuda.h>
#include <math.h>
#include <stdint.h>

// Problem constants (fixed by the dataset: B=256, D=H=512, lengths=128..383)
#define NN 65408
#define BP 256
#define DD 512
#define HH 512
#define GG 2048
#define TT 383
#define KK 512

// ---------------- device scratch ---------------------------------------------
__device__ __align__(16) float g_xW[(size_t)NN * GG];
__device__ __align__(16) float g_flat[(size_t)NN * HH];
__device__ __align__(16) float g_h2[2][BP * HH];   // double-buffered h
__device__ __align__(16) float g_att[NN];
__device__ __align__(16) float g_seg[BP * HH];
// W_hh packed in tf32 B-fragment order: GW[n*128 + ks2*4 + tig] =
//   { w[n][16ks2+tig], w[n][16ks2+4+tig], w[n][16ks2+8+tig], w[n][16ks2+12+tig] }
__device__ __align__(16) uint4 g_GW[(size_t)GG * 128];
__device__ int      g_off[BP];
__device__ unsigned g_bar[8];

__device__ __forceinline__ float sigf(float x) { return 1.0f / (1.0f + expf(-x)); }

__device__ __forceinline__ uint32_t f2tf32(float f) {
    uint32_t r; asm("cvt.rna.tf32.f32 %0, %1;" : "=r"(r) : "f"(f)); return r;
}
__device__ __forceinline__ void mma_tf32(float* c,
                                         uint32_t a0, uint32_t a1, uint32_t a2, uint32_t a3,
                                         uint32_t b0, uint32_t b1) {
    asm volatile("mma.sync.aligned.m16n8k8.row.col.f32.tf32.tf32.f32 "
        "{%0,%1,%2,%3}, {%4,%5,%6,%7}, {%8,%9}, {%0,%1,%2,%3};"
        : "+f"(c[0]), "+f"(c[1]), "+f"(c[2]), "+f"(c[3])
        : "r"(a0), "r"(a1), "r"(a2), "r"(a3), "r"(b0), "r"(b1));
}

// =================== tf32 mma.sync NT GEMM (unchanged from R8) ==============
#define GPITCH 36
#define STAGE_F (128 * GPITCH)
#define GEMM_SMEM (4 * STAGE_F * 4)

__global__ void __launch_bounds__(256)
tgemm_mma(const float* __restrict__ A, const float* __restrict__ Bm,
          const float* __restrict__ bias1, const float* __restrict__ bias2,
          float* __restrict__ C, int Ncols) {
    extern __shared__ __align__(16) float sm[];
    float* As[2] = { sm,           sm + 2 * STAGE_F };
    float* Bs[2] = { sm + STAGE_F, sm + 3 * STAGE_F };

    const int tid = threadIdx.x;
    const int wid = tid >> 5, lane = tid & 31;
    const int grp = lane >> 2, tig = lane & 3;
    const int warpM = wid >> 2, warpN = wid & 3;
    const size_t m0 = (size_t)blockIdx.y * 128;
    const int    n0 = blockIdx.x * 128;

    const int lrow = tid >> 1;
    const int lcb  = (tid & 1) * 16;
    const float* Ag = A  + (m0 + lrow) * KK;
    const float* Bg = Bm + (size_t)(n0 + lrow) * KK;

    float4 ar[4], br[4];
    auto ldchunk = [&](int c) {
#pragma unroll
        for (int q = 0; q < 4; q++) {
            ar[q] = *(const float4*)&Ag[c * 32 + lcb + q * 4];
            br[q] = *(const float4*)&Bg[c * 32 + lcb + q * 4];
        }
    };
    auto cvt4 = [](float4 v) {
        return make_uint4(f2tf32(v.x), f2tf32(v.y), f2tf32(v.z), f2tf32(v.w));
    };
    auto stchunk = [&](int s) {
        float* a = As[s] + lrow * GPITCH + lcb;
        float* b = Bs[s] + lrow * GPITCH + lcb;
#pragma unroll
        for (int q = 0; q < 4; q++) {
            *(uint4*)&a[q * 4] = cvt4(ar[q]);
            *(uint4*)&b[q * 4] = cvt4(br[q]);
        }
    };

    float acc[4][4][4];
#pragma unroll
    for (int i = 0; i < 4; i++)
#pragma unroll
        for (int j = 0; j < 4; j++)
#pragma unroll
            for (int k = 0; k < 4; k++) acc[i][j][k] = 0.f;

    ldchunk(0); stchunk(0);
    __syncthreads();

    for (int c = 0; c < KK / 32; c++) {
        const int s = c & 1;
        if (c + 1 < KK / 32) ldchunk(c + 1);

        const float* Aw = As[s] + (warpM * 64 + grp) * GPITCH;
        const float* Bw = Bs[s] + (warpN * 32 + grp) * GPITCH;
#pragma unroll
        for (int k0 = 0; k0 < 32; k0 += 8) {
            uint32_t af[4][4], bf[4][2];
#pragma unroll
            for (int mf = 0; mf < 4; mf++) {
                const float* p = Aw + mf * 16 * GPITCH + k0;
                af[mf][0] = __float_as_uint(p[tig]);
                af[mf][1] = __float_as_uint(p[8 * GPITCH + tig]);
                af[mf][2] = __float_as_uint(p[tig + 4]);
                af[mf][3] = __float_as_uint(p[8 * GPITCH + tig + 4]);
            }
#pragma unroll
            for (int nf = 0; nf < 4; nf++) {
                const float* p = Bw + nf * 8 * GPITCH + k0;
                bf[nf][0] = __float_as_uint(p[tig]);
                bf[nf][1] = __float_as_uint(p[tig + 4]);
            }
#pragma unroll
            for (int mf = 0; mf < 4; mf++)
#pragma unroll
                for (int nf = 0; nf < 4; nf++)
                    mma_tf32(acc[mf][nf],
                             af[mf][0], af[mf][1], af[mf][2], af[mf][3],
                             bf[nf][0], bf[nf][1]);
        }
        __syncthreads();
        if (c + 1 < KK / 32) { stchunk((c + 1) & 1); __syncthreads(); }
    }

#pragma unroll
    for (int mf = 0; mf < 4; mf++) {
        size_t r0 = m0 + warpM * 64 + mf * 16 + grp;
#pragma unroll
        for (int nf = 0; nf < 4; nf++) {
            int col = n0 + warpN * 32 + nf * 8 + 2 * tig;
            float b0 = bias1[col], b1 = bias1[col + 1];
            if (bias2) { b0 += bias2[col]; b1 += bias2[col + 1]; }
            float2 v0 = { acc[mf][nf][0] + b0, acc[mf][nf][1] + b1 };
            float2 v1 = { acc[mf][nf][2] + b0, acc[mf][nf][3] + b1 };
            *(float2*)&C[r0 * (size_t)Ncols + col] = v0;
            *(float2*)&C[(r0 + 8) * (size_t)Ncols + col] = v1;
        }
    }
}

// ---------------- init: zero states + offsets + barrier counters ------------
__global__ void k_init(const int* __restrict__ lengths) {
    int tid = blockIdx.x * blockDim.x + threadIdx.x;
    if (tid < 2 * BP * HH) ((float*)g_h2)[tid] = 0.f;
    if (tid < BP * HH) g_seg[tid] = 0.f;
    if (tid < 8) g_bar[tid] = 0u;
    if (tid == 0) {
        int acc = 0;
        for (int b = 0; b < BP; b++) { g_off[b] = acc; acc += lengths[b]; }
    }
}

// ---------------- prep: pack W_hh into tf32 B-fragment order ----------------
__global__ void k_prepw(const float* __restrict__ W) {
    int id = blockIdx.x * blockDim.x + threadIdx.x;
    if (id >= GG * 128) return;
    int n = id >> 7;
    int r = id & 127;
    int ks2 = r >> 2, tg = r & 3;
    const float* wr = W + (size_t)n * KK + 16 * ks2;
    g_GW[id] = make_uint4(f2tf32(wr[tg]), f2tf32(wr[tg + 4]),
                          f2tf32(wr[tg + 8]), f2tf32(wr[tg + 12]));
}

// ---------------- persistent LSTM recurrence (tf32 mma, 512 thr) ------------
// grid (8 pgroups, 16 cgroups). CTA: 32 persons x 128 gatecols.
// NEW: half of W cached in smem once (k-chunks 0..15); c in registers;
// xW prefetched at fill time; flat stores deferred past barrier-arrive.
#define HA_U4 (16 * 65 * 4)                       // 4160 uint4 = 66560 B
#define GT_PITCH2 136
#define GT_BYTES (32 * GT_PITCH2 * 4)             // 17408 B
#define WS_U4 (128 * 65)                          // 8320 uint4 = 133120 B
#define PSM3 (HA_U4 * 16 + GT_BYTES + WS_U4 * 16) // 217088 B

__global__ void __launch_bounds__(512)
k_lstm_persist(const int* __restrict__ lengths) {
    extern __shared__ __align__(16) uint4 smraw[];
    uint4* HA = smraw;                                  // A-frag packed h
    float* GT = (float*)(smraw + HA_U4);                // gate exchange
    uint4* WS = smraw + HA_U4 + GT_BYTES / 16;          // W cache (ks2 0..15)

    __shared__ int len_s[32];
    __shared__ int off_s[32];
    __shared__ int s_tmax;

    const int tid = threadIdx.x;
    const int pg = blockIdx.x, cg = blockIdx.y;
    const int p0 = pg * 32, hc0 = cg * 32;
    const int wid = tid >> 5, lane = tid & 31;
    const int grp = lane >> 2, tig = lane & 3;
    const int warpM = wid >> 3, warpN = wid & 7;

    if (wid == 0) {
        int L = lengths[p0 + lane];
        len_s[lane] = L;
        off_s[lane] = g_off[p0 + lane];
        int m = L;
#pragma unroll
        for (int o = 16; o; o >>= 1) m = max(m, __shfl_xor_sync(0xffffffffu, m, o));
        if (lane == 0) s_tmax = m;
    }

    // ---- preload W cache: ks2 chunks 0..15 for all 128 local rows ----
    // local row lr -> global W row: (lr>>5)*HH + hc0 + (lr&31)
#pragma unroll
    for (int i = 0; i < 16; i++) {
        int idx = tid + i * 512;          // 0..8191
        int lr = idx >> 6, r = idx & 63;
        int nrow = (lr >> 5) * HH + hc0 + (lr & 31);
        WS[lr * 65 + r] = g_GW[(size_t)nrow * 128 + r];
    }
    __syncthreads();
    const int tmax = s_tmax;

    // W rows for this warp
    const int gate = warpN >> 1;
    const int hcb  = (warpN & 1) * 16;
    const int lr0 = gate * 32 + hcb + grp;        // local W-cache row
    const int lr1 = lr0 + 8;
    const int nrow0 = gate * HH + hc0 + hcb + grp; // global W row
    const int nrow1 = nrow0 + 8;

    const int rA = 16 * warpM + grp;
    const uint4* HAa = HA + (size_t)(warpM * 8 + grp) * 65 * 4;

    // epilogue output ownership (fixed across steps) -> c in registers
    const int ep[2] = { tid >> 5, (tid + 512) >> 5 };        // person
    const int eh[2] = { tid & 31, tid & 31 };                // h-col
    float creg[2] = { 0.f, 0.f };

    for (int t = 0; t < tmax; t++) {
        // ---- fill HA: h -> tf32, A-fragment layout ----
        const float* hbuf = g_h2[t & 1];
#pragma unroll
        for (int s = 0; s < 2; s++) {
            int id = tid + s * 512;
            int ks = id & 63, g8 = (id >> 6) & 7, m = id >> 9;
            int pa = p0 + 16 * m + g8, pb = pa + 8;
            const float4* Ap = (const float4*)(hbuf + (size_t)pa * HH + 8 * ks);
            const float4* Bp = (const float4*)(hbuf + (size_t)pb * HH + 8 * ks);
            float4 va0 = __ldcg(Ap), va1 = __ldcg(Ap + 1);
            float4 vb0 = __ldcg(Bp), vb1 = __ldcg(Bp + 1);
            uint4* dst = HA + ((size_t)(m * 8 + g8) * 65 + ks) * 4;
            int c = ks & 3;
            dst[0 ^ c] = make_uint4(f2tf32(va0.x), f2tf32(vb0.x), f2tf32(va1.x), f2tf32(vb1.x));
            dst[1 ^ c] = make_uint4(f2tf32(va0.y), f2tf32(vb0.y), f2tf32(va1.y), f2tf32(vb1.y));
            dst[2 ^ c] = make_uint4(f2tf32(va0.z), f2tf32(vb0.z), f2tf32(va1.z), f2tf32(vb1.z));
            dst[3 ^ c] = make_uint4(f2tf32(va0.w), f2tf32(vb0.w), f2tf32(va1.w), f2tf32(vb1.w));
        }

        // ---- prefetch xW for this step's epilogue (independent of h) ----
        float xg[2][4];
        bool act[2];
        size_t fis[2];
#pragma unroll
        for (int s = 0; s < 2; s++) {
            int p = ep[s], hc = eh[s];
            act[s] = (t < len_s[p]);
            if (act[s]) {
                fis[s] = (size_t)(off_s[p] + t);
                size_t xb = fis[s] * GG + hc0 + hc;
#pragma unroll
                for (int g = 0; g < 4; g++) xg[s][g] = __ldcg(&g_xW[xb + g * HH]);
            } else {
                fis[s] = 0;
                xg[s][0] = xg[s][1] = xg[s][2] = xg[s][3] = 0.f;
            }
        }
        __syncthreads();

        // ---- 32x128x512 gates GEMM ----
        float acc[2][4];
#pragma unroll
        for (int i = 0; i < 2; i++)
#pragma unroll
            for (int j = 0; j < 4; j++) acc[i][j] = 0.f;

        // k-chunks 0..15: W from smem cache
#pragma unroll 8
        for (int ks2 = 0; ks2 < 16; ks2++) {
            const int ks0 = 2 * ks2, ks1 = ks0 + 1;
            uint4 A0 = HAa[ks0 * 4 + (tig ^ (ks0 & 3))];
            uint4 A1 = HAa[ks1 * 4 + (tig ^ (ks1 & 3))];
            uint4 W0 = WS[lr0 * 65 + ks2 * 4 + tig];
            uint4 W1 = WS[lr1 * 65 + ks2 * 4 + tig];
            mma_tf32(acc[0], A0.x, A0.y, A0.z, A0.w, W0.x, W0.y);
            mma_tf32(acc[0], A1.x, A1.y, A1.z, A1.w, W0.z, W0.w);
            mma_tf32(acc[1], A0.x, A0.y, A0.z, A0.w, W1.x, W1.y);
            mma_tf32(acc[1], A1.x, A1.y, A1.z, A1.w, W1.z, W1.w);
        }
        // k-chunks 16..31: W streamed from L2
#pragma unroll 8
        for (int ks2 = 16; ks2 < 32; ks2++) {
            const int ks0 = 2 * ks2, ks1 = ks0 + 1;
            uint4 A0 = HAa[ks0 * 4 + (tig ^ (ks0 & 3))];
            uint4 A1 = HAa[ks1 * 4 + (tig ^ (ks1 & 3))];
            uint4 W0 = g_GW[(size_t)nrow0 * 128 + ks2 * 4 + tig];
            uint4 W1 = g_GW[(size_t)nrow1 * 128 + ks2 * 4 + tig];
            mma_tf32(acc[0], A0.x, A0.y, A0.z, A0.w, W0.x, W0.y);
            mma_tf32(acc[0], A1.x, A1.y, A1.z, A1.w, W0.z, W0.w);
            mma_tf32(acc[1], A0.x, A0.y, A0.z, A0.w, W1.x, W1.y);
            mma_tf32(acc[1], A1.x, A1.y, A1.z, A1.w, W1.z, W1.w);
        }

        // ---- gate exchange to smem ----
#pragma unroll
        for (int nf = 0; nf < 2; nf++) {
            int cb = warpN * 16 + nf * 8 + 2 * tig;
            *(float2*)&GT[rA * GT_PITCH2 + cb]       = make_float2(acc[nf][0], acc[nf][1]);
            *(float2*)&GT[(rA + 8) * GT_PITCH2 + cb] = make_float2(acc[nf][2], acc[nf][3]);
        }
        __syncthreads();

        // ---- epilogue: activations + state update (c in regs) ----
        float hn[2];
#pragma unroll
        for (int s = 0; s < 2; s++) {
            int p = ep[s], hc = eh[s];
            if (act[s]) {
                float gi = GT[p * GT_PITCH2 + 0 * 32 + hc] + xg[s][0];
                float gf = GT[p * GT_PITCH2 + 1 * 32 + hc] + xg[s][1];
                float gg = GT[p * GT_PITCH2 + 2 * 32 + hc] + xg[s][2];
                float go = GT[p * GT_PITCH2 + 3 * 32 + hc] + xg[s][3];
                float cn = sigf(gf) * creg[s] + sigf(gi) * tanhf(gg);
                hn[s] = sigf(go) * tanhf(cn);
                creg[s] = cn;
                __stcg(&g_h2[(t + 1) & 1][(size_t)(p0 + p) * HH + hc0 + hc], hn[s]);
            }
        }

        // ---- barrier arrive ASAP; flat stores overlap the wait ----
        __syncthreads();
        if (tid == 0) {
            __threadfence();
            atomicAdd(&g_bar[pg], 1u);
        }
#pragma unroll
        for (int s = 0; s < 2; s++)
            if (act[s]) g_flat[fis[s] * HH + hc0 + eh[s]] = hn[s];
        if (tid == 0) {
            unsigned target = 16u * (unsigned)(t + 1);
            while (*((volatile unsigned*)&g_bar[pg]) < target) { }
            __threadfence();
        }
        __syncthreads();
    }
}

// ---------------- attention logits + concrete-relaxation gate ---------------
__global__ void k_att(const float* __restrict__ passedZ,
                      const float* __restrict__ fc2_W, const float* __restrict__ fc2_b,
                      const float* __restrict__ eps_u) {
    int gwarp = (blockIdx.x * blockDim.x + threadIdx.x) >> 5;
    int lane = threadIdx.x & 31;
    if (gwarp >= NN) return;
    const float* row = passedZ + (size_t)gwarp * DD;
    float s = 0.f;
#pragma unroll
    for (int k = lane; k < DD; k += 32) s += row[k] * fc2_W[k];
#pragma unroll
    for (int o = 16; o; o >>= 1) s += __shfl_xor_sync(0xffffffffu, s, o);
    if (lane == 0) {
        float logit = s + fc2_b[0];
        float eu = eps_u[gwarp];
        float eps = (2.0f * 1e-4f - 1.0f) * eu + (1.0f - 1e-4f);
        float gate = logf(eps) - logf(1.0f - eps) + logit;
        g_att[gwarp] = sigf(gate);
    }
}

// ---------------- gated segment sum ------------------------------------------
__global__ void k_seg(const int* __restrict__ lengths) {
    int b = blockIdx.x;
    int col = threadIdx.x;
    int off = g_off[b];
    int L = lengths[b];
    float acc = 0.f;
    for (int r = 0; r < L; r++) {
        int n = off + r;
        acc += g_flat[(size_t)n * HH + col] * g_att[n];
    }
    g_seg[(size_t)b * HH + col] = acc;
}

// ---------------- final tiny MLP ---------------------------------------------
__global__ void k_final(const float* __restrict__ mlp1_W, const float* __restrict__ mlp1_b,
                        const float* __restrict__ mlp2_W, const float* __restrict__ mlp2_b,
                        float* __restrict__ out) {
    __shared__ float hidden[16];
    int b = blockIdx.x;
    int tid = threadIdx.x;
    int w = tid >> 5, lane = tid & 31;
    const float* seg = &g_seg[(size_t)b * HH];
    float s = 0.f;
#pragma unroll
    for (int k = lane; k < HH; k += 32) s += seg[k] * mlp1_W[(size_t)w * HH + k];
#pragma unroll
    for (int o = 16; o; o >>= 1) s += __shfl_xor_sync(0xffffffffu, s, o);
    if (lane == 0) hidden[w] = s + mlp1_b[w];
    __syncthreads();
    if (tid < 2) {
        float o = mlp2_b[tid];
#pragma unroll
        for (int j = 0; j < 16; j++) o += hidden[j] * mlp2_W[tid * 16 + j];
        out[b * 2 + tid] = o;
    }
}

// -----------------------------------------------------------------------------
extern "C" void kernel_launch(void* const* d_in, const int* in_sizes, int n_in,
                              void* d_out, int out_size) {
    const float* lstm_input = (const float*)d_in[0];
    const float* eps_u      = (const float*)d_in[1];
    const float* W_ih       = (const float*)d_in[2];
    const float* W_hh       = (const float*)d_in[3];
    const float* b_ih       = (const float*)d_in[4];
    const float* b_hh       = (const float*)d_in[5];
    const float* fc1_W      = (const float*)d_in[6];
    const float* fc1_b      = (const float*)d_in[7];
    const float* fc2_W      = (const float*)d_in[8];
    const float* fc2_b      = (const float*)d_in[9];
    const float* mlp1_W     = (const float*)d_in[10];
    const float* mlp1_b     = (const float*)d_in[11];
    const float* mlp2_W     = (const float*)d_in[12];
    const float* mlp2_b     = (const float*)d_in[13];
    const int*   lengths    = (const int*)d_in[14];

    float* out = (float*)d_out;
    float* passedZ = out + BP * 2;   // tuple order: final[256,2] then passed_Z[N,512]

    float *xw, *flat;
    cudaGetSymbolAddress((void**)&xw, g_xW);
    cudaGetSymbolAddress((void**)&flat, g_flat);

    cudaFuncSetAttribute(tgemm_mma, cudaFuncAttributeMaxDynamicSharedMemorySize, GEMM_SMEM);
    cudaFuncSetAttribute(k_lstm_persist, cudaFuncAttributeMaxDynamicSharedMemorySize, PSM3);

    // 1. init states/offsets/barriers
    k_init<<<(2 * BP * HH + 255) / 256, 256>>>(lengths);

    // 2. pack W_hh into tf32 fragment order
    k_prepw<<<(GG * 128 + 255) / 256, 256>>>(W_hh);

    // 3. xW = X @ W_ih^T + b_ih + b_hh   (tf32 tensor cores)
    tgemm_mma<<<dim3(GG / 128, NN / 128), 256, GEMM_SMEM>>>(lstm_input, W_ih, b_ih, b_hh, xw, GG);

    // 4. full LSTM recurrence in ONE persistent launch (tf32 mma)
    k_lstm_persist<<<dim3(8, 16), 512, PSM3>>>(lengths);

    // 5. passed_Z = flat @ fc1_W^T + fc1_b  -> straight into d_out
    tgemm_mma<<<dim3(DD / 128, NN / 128), 256, GEMM_SMEM>>>(flat, fc1_W, fc1_b, nullptr, passedZ, DD);

    // 6. attention gate per flat row
    k_att<<<(NN * 32 + 255) / 256, 256>>>(passedZ, fc2_W, fc2_b, eps_u);

    // 7. gated per-person segment sum
    k_seg<<<BP, HH>>>(lengths);

    // 8. final MLP -> out[0:512]
    k_final<<<BP, 512>>>(mlp1_W, mlp1_b, mlp2_W, mlp2_b, out);
}

// round 10
// speedup vs baseline: 4.3523x; 1.1023x over previous
#include <cuda_runtime.h>
#include <cuda.h>
#include <math.h>
#include <stdint.h>

// Problem constants (fixed by the dataset: B=256, D=H=512, lengths=128..383)
#define NN 65408
#define BP 256
#define DD 512
#define HH 512
#define GG 2048
#define TT 383
#define KK 512

// ---------------- device scratch ---------------------------------------------
__device__ __align__(16) float g_xW[(size_t)NN * GG];
__device__ __align__(16) float g_flat[(size_t)NN * HH];
__device__ __align__(16) float g_h2[2][BP * HH];   // double-buffered h
__device__ __align__(16) float g_att[NN];
__device__ __align__(16) float g_seg[BP * HH];
// W_hh packed in tf32 B-fragment order
__device__ __align__(16) uint4 g_GW[(size_t)GG * 128];
__device__ int      g_off[BP];
__device__ __align__(128) unsigned g_bar[8 * 128];  // one counter per 512B

__device__ __forceinline__ float sigf(float x) { return 1.0f / (1.0f + expf(-x)); }

__device__ __forceinline__ uint32_t f2tf32(float f) {
    uint32_t r; asm("cvt.rna.tf32.f32 %0, %1;" : "=r"(r) : "f"(f)); return r;
}
__device__ __forceinline__ void mma_tf32(float* c,
                                         uint32_t a0, uint32_t a1, uint32_t a2, uint32_t a3,
                                         uint32_t b0, uint32_t b1) {
    asm volatile("mma.sync.aligned.m16n8k8.row.col.f32.tf32.tf32.f32 "
        "{%0,%1,%2,%3}, {%4,%5,%6,%7}, {%8,%9}, {%0,%1,%2,%3};"
        : "+f"(c[0]), "+f"(c[1]), "+f"(c[2]), "+f"(c[3])
        : "r"(a0), "r"(a1), "r"(a2), "r"(a3), "r"(b0), "r"(b1));
}
__device__ __forceinline__ void bar_arrive(unsigned* p) {
    asm volatile("red.release.gpu.global.add.u32 [%0], 1;" :: "l"(p) : "memory");
}
__device__ __forceinline__ unsigned bar_peek(const unsigned* p) {
    unsigned v;
    asm volatile("ld.acquire.gpu.global.u32 %0, [%1];" : "=r"(v) : "l"(p) : "memory");
    return v;
}

// =================== tf32 mma.sync NT GEMM (unchanged) ======================
#define GPITCH 36
#define STAGE_F (128 * GPITCH)
#define GEMM_SMEM (4 * STAGE_F * 4)

__global__ void __launch_bounds__(256)
tgemm_mma(const float* __restrict__ A, const float* __restrict__ Bm,
          const float* __restrict__ bias1, const float* __restrict__ bias2,
          float* __restrict__ C, int Ncols) {
    extern __shared__ __align__(16) float sm[];
    float* As[2] = { sm,           sm + 2 * STAGE_F };
    float* Bs[2] = { sm + STAGE_F, sm + 3 * STAGE_F };

    const int tid = threadIdx.x;
    const int wid = tid >> 5, lane = tid & 31;
    const int grp = lane >> 2, tig = lane & 3;
    const int warpM = wid >> 2, warpN = wid & 3;
    const size_t m0 = (size_t)blockIdx.y * 128;
    const int    n0 = blockIdx.x * 128;

    const int lrow = tid >> 1;
    const int lcb  = (tid & 1) * 16;
    const float* Ag = A  + (m0 + lrow) * KK;
    const float* Bg = Bm + (size_t)(n0 + lrow) * KK;

    float4 ar[4], br[4];
    auto ldchunk = [&](int c) {
#pragma unroll
        for (int q = 0; q < 4; q++) {
            ar[q] = *(const float4*)&Ag[c * 32 + lcb + q * 4];
            br[q] = *(const float4*)&Bg[c * 32 + lcb + q * 4];
        }
    };
    auto cvt4 = [](float4 v) {
        return make_uint4(f2tf32(v.x), f2tf32(v.y), f2tf32(v.z), f2tf32(v.w));
    };
    auto stchunk = [&](int s) {
        float* a = As[s] + lrow * GPITCH + lcb;
        float* b = Bs[s] + lrow * GPITCH + lcb;
#pragma unroll
        for (int q = 0; q < 4; q++) {
            *(uint4*)&a[q * 4] = cvt4(ar[q]);
            *(uint4*)&b[q * 4] = cvt4(br[q]);
        }
    };

    float acc[4][4][4];
#pragma unroll
    for (int i = 0; i < 4; i++)
#pragma unroll
        for (int j = 0; j < 4; j++)
#pragma unroll
            for (int k = 0; k < 4; k++) acc[i][j][k] = 0.f;

    ldchunk(0); stchunk(0);
    __syncthreads();

    for (int c = 0; c < KK / 32; c++) {
        const int s = c & 1;
        if (c + 1 < KK / 32) ldchunk(c + 1);

        const float* Aw = As[s] + (warpM * 64 + grp) * GPITCH;
        const float* Bw = Bs[s] + (warpN * 32 + grp) * GPITCH;
#pragma unroll
        for (int k0 = 0; k0 < 32; k0 += 8) {
            uint32_t af[4][4], bf[4][2];
#pragma unroll
            for (int mf = 0; mf < 4; mf++) {
                const float* p = Aw + mf * 16 * GPITCH + k0;
                af[mf][0] = __float_as_uint(p[tig]);
                af[mf][1] = __float_as_uint(p[8 * GPITCH + tig]);
                af[mf][2] = __float_as_uint(p[tig + 4]);
                af[mf][3] = __float_as_uint(p[8 * GPITCH + tig + 4]);
            }
#pragma unroll
            for (int nf = 0; nf < 4; nf++) {
                const float* p = Bw + nf * 8 * GPITCH + k0;
                bf[nf][0] = __float_as_uint(p[tig]);
                bf[nf][1] = __float_as_uint(p[tig + 4]);
            }
#pragma unroll
            for (int mf = 0; mf < 4; mf++)
#pragma unroll
                for (int nf = 0; nf < 4; nf++)
                    mma_tf32(acc[mf][nf],
                             af[mf][0], af[mf][1], af[mf][2], af[mf][3],
                             bf[nf][0], bf[nf][1]);
        }
        __syncthreads();
        if (c + 1 < KK / 32) { stchunk((c + 1) & 1); __syncthreads(); }
    }

#pragma unroll
    for (int mf = 0; mf < 4; mf++) {
        size_t r0 = m0 + warpM * 64 + mf * 16 + grp;
#pragma unroll
        for (int nf = 0; nf < 4; nf++) {
            int col = n0 + warpN * 32 + nf * 8 + 2 * tig;
            float b0 = bias1[col], b1 = bias1[col + 1];
            if (bias2) { b0 += bias2[col]; b1 += bias2[col + 1]; }
            float2 v0 = { acc[mf][nf][0] + b0, acc[mf][nf][1] + b1 };
            float2 v1 = { acc[mf][nf][2] + b0, acc[mf][nf][3] + b1 };
            *(float2*)&C[r0 * (size_t)Ncols + col] = v0;
            *(float2*)&C[(r0 + 8) * (size_t)Ncols + col] = v1;
        }
    }
}

// ---------------- init --------------------------------------------------------
__global__ void k_init(const int* __restrict__ lengths) {
    int tid = blockIdx.x * blockDim.x + threadIdx.x;
    if (tid < 2 * BP * HH) ((float*)g_h2)[tid] = 0.f;
    if (tid < BP * HH) g_seg[tid] = 0.f;
    if (tid < 8 * 128) g_bar[tid] = 0u;
    if (tid == 0) {
        int acc = 0;
        for (int b = 0; b < BP; b++) { g_off[b] = acc; acc += lengths[b]; }
    }
}

// ---------------- prep: pack W_hh into tf32 B-fragment order ----------------
__global__ void k_prepw(const float* __restrict__ W) {
    int id = blockIdx.x * blockDim.x + threadIdx.x;
    if (id >= GG * 128) return;
    int n = id >> 7;
    int r = id & 127;
    int ks2 = r >> 2, tg = r & 3;
    const float* wr = W + (size_t)n * KK + 16 * ks2;
    g_GW[id] = make_uint4(f2tf32(wr[tg]), f2tf32(wr[tg + 4]),
                          f2tf32(wr[tg + 8]), f2tf32(wr[tg + 12]));
}

// ---------------- persistent LSTM recurrence (tf32 mma, 512 thr) ------------
#define HA_U4 (16 * 65 * 4)                       // 66560 B
#define GT_PITCH2 136
#define GT_BYTES (32 * GT_PITCH2 * 4)             // 17408 B
#define WPITCH 68                                 // conflict-free W cache pitch
#define WS_U4 (128 * WPITCH)                      // 8704 uint4 = 139264 B
#define PSM3 (HA_U4 * 16 + GT_BYTES + WS_U4 * 16) // 223232 B

__global__ void __launch_bounds__(512)
k_lstm_persist(const int* __restrict__ lengths) {
    extern __shared__ __align__(16) uint4 smraw[];
    uint4* HA = smraw;
    float* GT = (float*)(smraw + HA_U4);
    uint4* WS = smraw + HA_U4 + GT_BYTES / 16;

    __shared__ int len_s[32];
    __shared__ int off_s[32];
    __shared__ int s_tmax;

    const int tid = threadIdx.x;
    const int pg = blockIdx.x, cg = blockIdx.y;
    const int p0 = pg * 32, hc0 = cg * 32;
    const int wid = tid >> 5, lane = tid & 31;
    const int grp = lane >> 2, tig = lane & 3;
    const int warpM = wid >> 3, warpN = wid & 7;
    unsigned* barp = &g_bar[pg * 128];

    if (wid == 0) {
        int L = lengths[p0 + lane];
        len_s[lane] = L;
        off_s[lane] = g_off[p0 + lane];
        int m = L;
#pragma unroll
        for (int o = 16; o; o >>= 1) m = max(m, __shfl_xor_sync(0xffffffffu, m, o));
        if (lane == 0) s_tmax = m;
    }

    // ---- preload W cache: ks2 chunks 0..15 for all 128 local rows ----
#pragma unroll
    for (int i = 0; i < 16; i++) {
        int idx = tid + i * 512;
        int lr = idx >> 6, r = idx & 63;
        int nrow = (lr >> 5) * HH + hc0 + (lr & 31);
        WS[lr * WPITCH + r] = g_GW[(size_t)nrow * 128 + r];
    }
    __syncthreads();
    const int tmax = s_tmax;

    const int gate = warpN >> 1;
    const int hcb  = (warpN & 1) * 16;
    const int lr0 = gate * 32 + hcb + grp;
    const int lr1 = lr0 + 8;
    const int nrow0 = gate * HH + hc0 + hcb + grp;
    const int nrow1 = nrow0 + 8;

    const int rA = 16 * warpM + grp;
    const uint4* HAa = HA + (size_t)(warpM * 8 + grp) * 65 * 4;

    const int ep[2] = { tid >> 5, (tid + 512) >> 5 };
    const int eh = tid & 31;
    float creg[2] = { 0.f, 0.f };

    // xW prefetch state (for step t); prime for t = 0
    float xg[2][4];
    bool  act[2];
    size_t fis[2];
    auto prefetch_xw = [&](int t) {
#pragma unroll
        for (int s = 0; s < 2; s++) {
            int p = ep[s];
            act[s] = (t < len_s[p]);
            if (act[s]) {
                fis[s] = (size_t)(off_s[p] + t);
                size_t xb = fis[s] * GG + hc0 + eh;
#pragma unroll
                for (int g = 0; g < 4; g++) xg[s][g] = __ldcg(&g_xW[xb + g * HH]);
            } else {
                fis[s] = 0;
                xg[s][0] = xg[s][1] = xg[s][2] = xg[s][3] = 0.f;
            }
        }
    };
    prefetch_xw(0);

    for (int t = 0; t < tmax; t++) {
        // ---- fill HA: h -> tf32, A-fragment layout ----
        const float* hbuf = g_h2[t & 1];
#pragma unroll
        for (int s = 0; s < 2; s++) {
            int id = tid + s * 512;
            int ks = id & 63, g8 = (id >> 6) & 7, m = id >> 9;
            int pa = p0 + 16 * m + g8, pb = pa + 8;
            const float4* Ap = (const float4*)(hbuf + (size_t)pa * HH + 8 * ks);
            const float4* Bp = (const float4*)(hbuf + (size_t)pb * HH + 8 * ks);
            float4 va0 = __ldcg(Ap), va1 = __ldcg(Ap + 1);
            float4 vb0 = __ldcg(Bp), vb1 = __ldcg(Bp + 1);
            uint4* dst = HA + ((size_t)(m * 8 + g8) * 65 + ks) * 4;
            int c = ks & 3;
            dst[0 ^ c] = make_uint4(f2tf32(va0.x), f2tf32(vb0.x), f2tf32(va1.x), f2tf32(vb1.x));
            dst[1 ^ c] = make_uint4(f2tf32(va0.y), f2tf32(vb0.y), f2tf32(va1.y), f2tf32(vb1.y));
            dst[2 ^ c] = make_uint4(f2tf32(va0.z), f2tf32(vb0.z), f2tf32(va1.z), f2tf32(vb1.z));
            dst[3 ^ c] = make_uint4(f2tf32(va0.w), f2tf32(vb0.w), f2tf32(va1.w), f2tf32(vb1.w));
        }
        __syncthreads();

        // ---- 32x128x512 gates GEMM ----
        float acc[2][4];
#pragma unroll
        for (int i = 0; i < 2; i++)
#pragma unroll
            for (int j = 0; j < 4; j++) acc[i][j] = 0.f;

#pragma unroll 8
        for (int ks2 = 0; ks2 < 16; ks2++) {
            const int ks0 = 2 * ks2, ks1 = ks0 + 1;
            uint4 A0 = HAa[ks0 * 4 + (tig ^ (ks0 & 3))];
            uint4 A1 = HAa[ks1 * 4 + (tig ^ (ks1 & 3))];
            uint4 W0 = WS[lr0 * WPITCH + ks2 * 4 + tig];
            uint4 W1 = WS[lr1 * WPITCH + ks2 * 4 + tig];
            mma_tf32(acc[0], A0.x, A0.y, A0.z, A0.w, W0.x, W0.y);
            mma_tf32(acc[0], A1.x, A1.y, A1.z, A1.w, W0.z, W0.w);
            mma_tf32(acc[1], A0.x, A0.y, A0.z, A0.w, W1.x, W1.y);
            mma_tf32(acc[1], A1.x, A1.y, A1.z, A1.w, W1.z, W1.w);
        }
#pragma unroll 8
        for (int ks2 = 16; ks2 < 32; ks2++) {
            const int ks0 = 2 * ks2, ks1 = ks0 + 1;
            uint4 A0 = HAa[ks0 * 4 + (tig ^ (ks0 & 3))];
            uint4 A1 = HAa[ks1 * 4 + (tig ^ (ks1 & 3))];
            uint4 W0 = g_GW[(size_t)nrow0 * 128 + ks2 * 4 + tig];
            uint4 W1 = g_GW[(size_t)nrow1 * 128 + ks2 * 4 + tig];
            mma_tf32(acc[0], A0.x, A0.y, A0.z, A0.w, W0.x, W0.y);
            mma_tf32(acc[0], A1.x, A1.y, A1.z, A1.w, W0.z, W0.w);
            mma_tf32(acc[1], A0.x, A0.y, A0.z, A0.w, W1.x, W1.y);
            mma_tf32(acc[1], A1.x, A1.y, A1.z, A1.w, W1.z, W1.w);
        }

        // ---- gate exchange to smem ----
#pragma unroll
        for (int nf = 0; nf < 2; nf++) {
            int cb = warpN * 16 + nf * 8 + 2 * tig;
            *(float2*)&GT[rA * GT_PITCH2 + cb]       = make_float2(acc[nf][0], acc[nf][1]);
            *(float2*)&GT[(rA + 8) * GT_PITCH2 + cb] = make_float2(acc[nf][2], acc[nf][3]);
        }
        __syncthreads();

        // ---- epilogue: activations + state update (c in regs) ----
        float hn[2];
#pragma unroll
        for (int s = 0; s < 2; s++) {
            int p = ep[s];
            if (act[s]) {
                float gi = GT[p * GT_PITCH2 + 0 * 32 + eh] + xg[s][0];
                float gf = GT[p * GT_PITCH2 + 1 * 32 + eh] + xg[s][1];
                float gg = GT[p * GT_PITCH2 + 2 * 32 + eh] + xg[s][2];
                float go = GT[p * GT_PITCH2 + 3 * 32 + eh] + xg[s][3];
                float cn = sigf(gf) * creg[s] + sigf(gi) * tanhf(gg);
                hn[s] = sigf(go) * tanhf(cn);
                creg[s] = cn;
                __stcg(&g_h2[(t + 1) & 1][(size_t)(p0 + p) * HH + hc0 + eh], hn[s]);
            }
        }

        // ---- arrive (release), overlap flat stores + next xW prefetch ----
        __syncthreads();
        if (tid == 0) bar_arrive(barp);
        size_t fsave[2] = { fis[0], fis[1] };
        bool   asave[2] = { act[0], act[1] };
        float  hsave[2] = { hn[0], hn[1] };
        if (t + 1 < tmax) prefetch_xw(t + 1);
#pragma unroll
        for (int s = 0; s < 2; s++)
            if (asave[s]) g_flat[fsave[s] * HH + hc0 + eh] = hsave[s];
        if (tid == 0) {
            unsigned target = 16u * (unsigned)(t + 1);
            while (bar_peek(barp) < target) __nanosleep(32);
        }
        __syncthreads();
    }
}

// ---------------- attention logits + concrete-relaxation gate ---------------
__global__ void k_att(const float* __restrict__ passedZ,
                      const float* __restrict__ fc2_W, const float* __restrict__ fc2_b,
                      const float* __restrict__ eps_u) {
    int gwarp = (blockIdx.x * blockDim.x + threadIdx.x) >> 5;
    int lane = threadIdx.x & 31;
    if (gwarp >= NN) return;
    const float* row = passedZ + (size_t)gwarp * DD;
    float s = 0.f;
#pragma unroll
    for (int k = lane; k < DD; k += 32) s += row[k] * fc2_W[k];
#pragma unroll
    for (int o = 16; o; o >>= 1) s += __shfl_xor_sync(0xffffffffu, s, o);
    if (lane == 0) {
        float logit = s + fc2_b[0];
        float eu = eps_u[gwarp];
        float eps = (2.0f * 1e-4f - 1.0f) * eu + (1.0f - 1e-4f);
        float gate = logf(eps) - logf(1.0f - eps) + logit;
        g_att[gwarp] = sigf(gate);
    }
}

// ---------------- gated segment sum ------------------------------------------
__global__ void k_seg(const int* __restrict__ lengths) {
    int b = blockIdx.x;
    int col = threadIdx.x;
    int off = g_off[b];
    int L = lengths[b];
    float acc = 0.f;
    for (int r = 0; r < L; r++) {
        int n = off + r;
        acc += g_flat[(size_t)n * HH + col] * g_att[n];
    }
    g_seg[(size_t)b * HH + col] = acc;
}

// ---------------- final tiny MLP ---------------------------------------------
__global__ void k_final(const float* __restrict__ mlp1_W, const float* __restrict__ mlp1_b,
                        const float* __restrict__ mlp2_W, const float* __restrict__ mlp2_b,
                        float* __restrict__ out) {
    __shared__ float hidden[16];
    int b = blockIdx.x;
    int tid = threadIdx.x;
    int w = tid >> 5, lane = tid & 31;
    const float* seg = &g_seg[(size_t)b * HH];
    float s = 0.f;
#pragma unroll
    for (int k = lane; k < HH; k += 32) s += seg[k] * mlp1_W[(size_t)w * HH + k];
#pragma unroll
    for (int o = 16; o; o >>= 1) s += __shfl_xor_sync(0xffffffffu, s, o);
    if (lane == 0) hidden[w] = s + mlp1_b[w];
    __syncthreads();
    if (tid < 2) {
        float o = mlp2_b[tid];
#pragma unroll
        for (int j = 0; j < 16; j++) o += hidden[j] * mlp2_W[tid * 16 + j];
        out[b * 2 + tid] = o;
    }
}

// -----------------------------------------------------------------------------
extern "C" void kernel_launch(void* const* d_in, const int* in_sizes, int n_in,
                              void* d_out, int out_size) {
    const float* lstm_input = (const float*)d_in[0];
    const float* eps_u      = (const float*)d_in[1];
    const float* W_ih       = (const float*)d_in[2];
    const float* W_hh       = (const float*)d_in[3];
    const float* b_ih       = (const float*)d_in[4];
    const float* b_hh       = (const float*)d_in[5];
    const float* fc1_W      = (const float*)d_in[6];
    const float* fc1_b      = (const float*)d_in[7];
    const float* fc2_W      = (const float*)d_in[8];
    const float* fc2_b      = (const float*)d_in[9];
    const float* mlp1_W     = (const float*)d_in[10];
    const float* mlp1_b     = (const float*)d_in[11];
    const float* mlp2_W     = (const float*)d_in[12];
    const float* mlp2_b     = (const float*)d_in[13];
    const int*   lengths    = (const int*)d_in[14];

    float* out = (float*)d_out;
    float* passedZ = out + BP * 2;   // tuple order: final[256,2] then passed_Z[N,512]

    float *xw, *flat;
    cudaGetSymbolAddress((void**)&xw, g_xW);
    cudaGetSymbolAddress((void**)&flat, g_flat);

    cudaFuncSetAttribute(tgemm_mma, cudaFuncAttributeMaxDynamicSharedMemorySize, GEMM_SMEM);
    cudaFuncSetAttribute(k_lstm_persist, cudaFuncAttributeMaxDynamicSharedMemorySize, PSM3);

    // 1. init states/offsets/barriers
    k_init<<<(2 * BP * HH + 255) / 256, 256>>>(lengths);

    // 2. pack W_hh into tf32 fragment order
    k_prepw<<<(GG * 128 + 255) / 256, 256>>>(W_hh);

    // 3. xW = X @ W_ih^T + b_ih + b_hh   (tf32 tensor cores)
    tgemm_mma<<<dim3(GG / 128, NN / 128), 256, GEMM_SMEM>>>(lstm_input, W_ih, b_ih, b_hh, xw, GG);

    // 4. full LSTM recurrence in ONE persistent launch (tf32 mma)
    k_lstm_persist<<<dim3(8, 16), 512, PSM3>>>(lengths);

    // 5. passed_Z = flat @ fc1_W^T + fc1_b  -> straight into d_out
    tgemm_mma<<<dim3(DD / 128, NN / 128), 256, GEMM_SMEM>>>(flat, fc1_W, fc1_b, nullptr, passedZ, DD);

    // 6. attention gate per flat row
    k_att<<<(NN * 32 + 255) / 256, 256>>>(passedZ, fc2_W, fc2_b, eps_u);

    // 7. gated per-person segment sum
    k_seg<<<BP, HH>>>(lengths);

    // 8. final MLP -> out[0:512]
    k_final<<<BP, 512>>>(mlp1_W, mlp1_b, mlp2_W, mlp2_b, out);
}

// round 11
// speedup vs baseline: 4.4980x; 1.0335x over previous
#include <cuda_runtime.h>
#include <cuda.h>
#include <math.h>
#include <stdint.h>

// Problem constants (fixed by the dataset: B=256, D=H=512, lengths=128..383)
#define NN 65408
#define BP 256
#define DD 512
#define HH 512
#define GG 2048
#define TT 383
#define KK 512

// ---------------- device scratch ---------------------------------------------
__device__ __align__(16) float g_xW[(size_t)NN * GG];
__device__ __align__(16) float g_flat[(size_t)NN * HH];
__device__ __align__(16) float g_h2[2][BP * HH];   // double-buffered h
__device__ __align__(16) float g_att[NN];
__device__ __align__(16) float g_seg[BP * HH];
// W_hh packed in tf32 B-fragment order
__device__ __align__(16) uint4 g_GW[(size_t)GG * 128];
__device__ int      g_off[BP];
__device__ __align__(128) unsigned g_bar[8 * 128];  // one counter per 512B

__device__ __forceinline__ float sigf(float x) { return 1.0f / (1.0f + expf(-x)); }

// fast activations: 1 MUFU.TANH each (epilogue of the recurrence only)
__device__ __forceinline__ float tanh_fast(float x) {
    float r; asm("tanh.approx.f32 %0, %1;" : "=f"(r) : "f"(x)); return r;
}
__device__ __forceinline__ float sig_fast(float x) {
    return fmaf(tanh_fast(0.5f * x), 0.5f, 0.5f);
}

__device__ __forceinline__ uint32_t f2tf32(float f) {
    uint32_t r; asm("cvt.rna.tf32.f32 %0, %1;" : "=r"(r) : "f"(f)); return r;
}
__device__ __forceinline__ void mma_tf32(float* c,
                                         uint32_t a0, uint32_t a1, uint32_t a2, uint32_t a3,
                                         uint32_t b0, uint32_t b1) {
    asm volatile("mma.sync.aligned.m16n8k8.row.col.f32.tf32.tf32.f32 "
        "{%0,%1,%2,%3}, {%4,%5,%6,%7}, {%8,%9}, {%0,%1,%2,%3};"
        : "+f"(c[0]), "+f"(c[1]), "+f"(c[2]), "+f"(c[3])
        : "r"(a0), "r"(a1), "r"(a2), "r"(a3), "r"(b0), "r"(b1));
}
__device__ __forceinline__ void bar_arrive(unsigned* p) {
    asm volatile("red.release.gpu.global.add.u32 [%0], 1;" :: "l"(p) : "memory");
}
__device__ __forceinline__ unsigned bar_peek(const unsigned* p) {
    unsigned v;
    asm volatile("ld.acquire.gpu.global.u32 %0, [%1];" : "=r"(v) : "l"(p) : "memory");
    return v;
}

// =================== tf32 mma.sync NT GEMM (unchanged) ======================
#define GPITCH 36
#define STAGE_F (128 * GPITCH)
#define GEMM_SMEM (4 * STAGE_F * 4)

__global__ void __launch_bounds__(256)
tgemm_mma(const float* __restrict__ A, const float* __restrict__ Bm,
          const float* __restrict__ bias1, const float* __restrict__ bias2,
          float* __restrict__ C, int Ncols) {
    extern __shared__ __align__(16) float sm[];
    float* As[2] = { sm,           sm + 2 * STAGE_F };
    float* Bs[2] = { sm + STAGE_F, sm + 3 * STAGE_F };

    const int tid = threadIdx.x;
    const int wid = tid >> 5, lane = tid & 31;
    const int grp = lane >> 2, tig = lane & 3;
    const int warpM = wid >> 2, warpN = wid & 3;
    const size_t m0 = (size_t)blockIdx.y * 128;
    const int    n0 = blockIdx.x * 128;

    const int lrow = tid >> 1;
    const int lcb  = (tid & 1) * 16;
    const float* Ag = A  + (m0 + lrow) * KK;
    const float* Bg = Bm + (size_t)(n0 + lrow) * KK;

    float4 ar[4], br[4];
    auto ldchunk = [&](int c) {
#pragma unroll
        for (int q = 0; q < 4; q++) {
            ar[q] = *(const float4*)&Ag[c * 32 + lcb + q * 4];
            br[q] = *(const float4*)&Bg[c * 32 + lcb + q * 4];
        }
    };
    auto cvt4 = [](float4 v) {
        return make_uint4(f2tf32(v.x), f2tf32(v.y), f2tf32(v.z), f2tf32(v.w));
    };
    auto stchunk = [&](int s) {
        float* a = As[s] + lrow * GPITCH + lcb;
        float* b = Bs[s] + lrow * GPITCH + lcb;
#pragma unroll
        for (int q = 0; q < 4; q++) {
            *(uint4*)&a[q * 4] = cvt4(ar[q]);
            *(uint4*)&b[q * 4] = cvt4(br[q]);
        }
    };

    float acc[4][4][4];
#pragma unroll
    for (int i = 0; i < 4; i++)
#pragma unroll
        for (int j = 0; j < 4; j++)
#pragma unroll
            for (int k = 0; k < 4; k++) acc[i][j][k] = 0.f;

    ldchunk(0); stchunk(0);
    __syncthreads();

    for (int c = 0; c < KK / 32; c++) {
        const int s = c & 1;
        if (c + 1 < KK / 32) ldchunk(c + 1);

        const float* Aw = As[s] + (warpM * 64 + grp) * GPITCH;
        const float* Bw = Bs[s] + (warpN * 32 + grp) * GPITCH;
#pragma unroll
        for (int k0 = 0; k0 < 32; k0 += 8) {
            uint32_t af[4][4], bf[4][2];
#pragma unroll
            for (int mf = 0; mf < 4; mf++) {
                const float* p = Aw + mf * 16 * GPITCH + k0;
                af[mf][0] = __float_as_uint(p[tig]);
                af[mf][1] = __float_as_uint(p[8 * GPITCH + tig]);
                af[mf][2] = __float_as_uint(p[tig + 4]);
                af[mf][3] = __float_as_uint(p[8 * GPITCH + tig + 4]);
            }
#pragma unroll
            for (int nf = 0; nf < 4; nf++) {
                const float* p = Bw + nf * 8 * GPITCH + k0;
                bf[nf][0] = __float_as_uint(p[tig]);
                bf[nf][1] = __float_as_uint(p[tig + 4]);
            }
#pragma unroll
            for (int mf = 0; mf < 4; mf++)
#pragma unroll
                for (int nf = 0; nf < 4; nf++)
                    mma_tf32(acc[mf][nf],
                             af[mf][0], af[mf][1], af[mf][2], af[mf][3],
                             bf[nf][0], bf[nf][1]);
        }
        __syncthreads();
        if (c + 1 < KK / 32) { stchunk((c + 1) & 1); __syncthreads(); }
    }

#pragma unroll
    for (int mf = 0; mf < 4; mf++) {
        size_t r0 = m0 + warpM * 64 + mf * 16 + grp;
#pragma unroll
        for (int nf = 0; nf < 4; nf++) {
            int col = n0 + warpN * 32 + nf * 8 + 2 * tig;
            float b0 = bias1[col], b1 = bias1[col + 1];
            if (bias2) { b0 += bias2[col]; b1 += bias2[col + 1]; }
            float2 v0 = { acc[mf][nf][0] + b0, acc[mf][nf][1] + b1 };
            float2 v1 = { acc[mf][nf][2] + b0, acc[mf][nf][3] + b1 };
            *(float2*)&C[r0 * (size_t)Ncols + col] = v0;
            *(float2*)&C[(r0 + 8) * (size_t)Ncols + col] = v1;
        }
    }
}

// ---------------- init --------------------------------------------------------
__global__ void k_init(const int* __restrict__ lengths) {
    int tid = blockIdx.x * blockDim.x + threadIdx.x;
    if (tid < 2 * BP * HH) ((float*)g_h2)[tid] = 0.f;
    if (tid < BP * HH) g_seg[tid] = 0.f;
    if (tid < 8 * 128) g_bar[tid] = 0u;
    if (tid == 0) {
        int acc = 0;
        for (int b = 0; b < BP; b++) { g_off[b] = acc; acc += lengths[b]; }
    }
}

// ---------------- prep: pack W_hh into tf32 B-fragment order ----------------
__global__ void k_prepw(const float* __restrict__ W) {
    int id = blockIdx.x * blockDim.x + threadIdx.x;
    if (id >= GG * 128) return;
    int n = id >> 7;
    int r = id & 127;
    int ks2 = r >> 2, tg = r & 3;
    const float* wr = W + (size_t)n * KK + 16 * ks2;
    g_GW[id] = make_uint4(f2tf32(wr[tg]), f2tf32(wr[tg + 4]),
                          f2tf32(wr[tg + 8]), f2tf32(wr[tg + 12]));
}

// ---------------- persistent LSTM recurrence (tf32 mma, 512 thr) ------------
#define HA_U4 (16 * 65 * 4)                       // 66560 B
#define GT_PITCH2 136
#define GT_BYTES (32 * GT_PITCH2 * 4)             // 17408 B
#define WPITCH 68                                 // conflict-free W cache pitch
#define WS_U4 (128 * WPITCH)                      // 8704 uint4 = 139264 B
#define PSM3 (HA_U4 * 16 + GT_BYTES + WS_U4 * 16) // 223232 B

__global__ void __launch_bounds__(512)
k_lstm_persist(const int* __restrict__ lengths) {
    extern __shared__ __align__(16) uint4 smraw[];
    uint4* HA = smraw;
    float* GT = (float*)(smraw + HA_U4);
    uint4* WS = smraw + HA_U4 + GT_BYTES / 16;

    __shared__ int len_s[32];
    __shared__ int off_s[32];
    __shared__ int s_tmax;

    const int tid = threadIdx.x;
    const int pg = blockIdx.x, cg = blockIdx.y;
    const int p0 = pg * 32, hc0 = cg * 32;
    const int wid = tid >> 5, lane = tid & 31;
    const int grp = lane >> 2, tig = lane & 3;
    const int warpM = wid >> 3, warpN = wid & 7;
    unsigned* barp = &g_bar[pg * 128];

    if (wid == 0) {
        int L = lengths[p0 + lane];
        len_s[lane] = L;
        off_s[lane] = g_off[p0 + lane];
        int m = L;
#pragma unroll
        for (int o = 16; o; o >>= 1) m = max(m, __shfl_xor_sync(0xffffffffu, m, o));
        if (lane == 0) s_tmax = m;
    }

    // ---- preload W cache: ks2 chunks 0..15 for all 128 local rows ----
#pragma unroll
    for (int i = 0; i < 16; i++) {
        int idx = tid + i * 512;
        int lr = idx >> 6, r = idx & 63;
        int nrow = (lr >> 5) * HH + hc0 + (lr & 31);
        WS[lr * WPITCH + r] = g_GW[(size_t)nrow * 128 + r];
    }
    __syncthreads();
    const int tmax = s_tmax;

    const int gate = warpN >> 1;
    const int hcb  = (warpN & 1) * 16;
    const int lr0 = gate * 32 + hcb + grp;
    const int lr1 = lr0 + 8;
    const int nrow0 = gate * HH + hc0 + hcb + grp;
    const int nrow1 = nrow0 + 8;

    const int rA = 16 * warpM + grp;
    const uint4* HAa = HA + (size_t)(warpM * 8 + grp) * 65 * 4;

    const int ep[2] = { tid >> 5, (tid + 512) >> 5 };
    const int eh = tid & 31;
    float creg[2] = { 0.f, 0.f };

    // xW prefetch state (for step t); prime for t = 0
    float xg[2][4];
    bool  act[2];
    size_t fis[2];
    auto prefetch_xw = [&](int t) {
#pragma unroll
        for (int s = 0; s < 2; s++) {
            int p = ep[s];
            act[s] = (t < len_s[p]);
            if (act[s]) {
                fis[s] = (size_t)(off_s[p] + t);
                size_t xb = fis[s] * GG + hc0 + eh;
#pragma unroll
                for (int g = 0; g < 4; g++) xg[s][g] = __ldcg(&g_xW[xb + g * HH]);
            } else {
                fis[s] = 0;
                xg[s][0] = xg[s][1] = xg[s][2] = xg[s][3] = 0.f;
            }
        }
    };
    prefetch_xw(0);

    for (int t = 0; t < tmax; t++) {
        // ---- fill HA: h -> tf32, A-fragment layout ----
        const float* hbuf = g_h2[t & 1];
#pragma unroll
        for (int s = 0; s < 2; s++) {
            int id = tid + s * 512;
            int ks = id & 63, g8 = (id >> 6) & 7, m = id >> 9;
            int pa = p0 + 16 * m + g8, pb = pa + 8;
            const float4* Ap = (const float4*)(hbuf + (size_t)pa * HH + 8 * ks);
            const float4* Bp = (const float4*)(hbuf + (size_t)pb * HH + 8 * ks);
            float4 va0 = __ldcg(Ap), va1 = __ldcg(Ap + 1);
            float4 vb0 = __ldcg(Bp), vb1 = __ldcg(Bp + 1);
            uint4* dst = HA + ((size_t)(m * 8 + g8) * 65 + ks) * 4;
            int c = ks & 3;
            dst[0 ^ c] = make_uint4(f2tf32(va0.x), f2tf32(vb0.x), f2tf32(va1.x), f2tf32(vb1.x));
            dst[1 ^ c] = make_uint4(f2tf32(va0.y), f2tf32(vb0.y), f2tf32(va1.y), f2tf32(vb1.y));
            dst[2 ^ c] = make_uint4(f2tf32(va0.z), f2tf32(vb0.z), f2tf32(va1.z), f2tf32(vb1.z));
            dst[3 ^ c] = make_uint4(f2tf32(va0.w), f2tf32(vb0.w), f2tf32(va1.w), f2tf32(vb1.w));
        }
        __syncthreads();

        // ---- 32x128x512 gates GEMM ----
        float acc[2][4];
#pragma unroll
        for (int i = 0; i < 2; i++)
#pragma unroll
            for (int j = 0; j < 4; j++) acc[i][j] = 0.f;

#pragma unroll 8
        for (int ks2 = 0; ks2 < 16; ks2++) {
            const int ks0 = 2 * ks2, ks1 = ks0 + 1;
            uint4 A0 = HAa[ks0 * 4 + (tig ^ (ks0 & 3))];
            uint4 A1 = HAa[ks1 * 4 + (tig ^ (ks1 & 3))];
            uint4 W0 = WS[lr0 * WPITCH + ks2 * 4 + tig];
            uint4 W1 = WS[lr1 * WPITCH + ks2 * 4 + tig];
            mma_tf32(acc[0], A0.x, A0.y, A0.z, A0.w, W0.x, W0.y);
            mma_tf32(acc[0], A1.x, A1.y, A1.z, A1.w, W0.z, W0.w);
            mma_tf32(acc[1], A0.x, A0.y, A0.z, A0.w, W1.x, W1.y);
            mma_tf32(acc[1], A1.x, A1.y, A1.z, A1.w, W1.z, W1.w);
        }
#pragma unroll 8
        for (int ks2 = 16; ks2 < 32; ks2++) {
            const int ks0 = 2 * ks2, ks1 = ks0 + 1;
            uint4 A0 = HAa[ks0 * 4 + (tig ^ (ks0 & 3))];
            uint4 A1 = HAa[ks1 * 4 + (tig ^ (ks1 & 3))];
            uint4 W0 = g_GW[(size_t)nrow0 * 128 + ks2 * 4 + tig];
            uint4 W1 = g_GW[(size_t)nrow1 * 128 + ks2 * 4 + tig];
            mma_tf32(acc[0], A0.x, A0.y, A0.z, A0.w, W0.x, W0.y);
            mma_tf32(acc[0], A1.x, A1.y, A1.z, A1.w, W0.z, W0.w);
            mma_tf32(acc[1], A0.x, A0.y, A0.z, A0.w, W1.x, W1.y);
            mma_tf32(acc[1], A1.x, A1.y, A1.z, A1.w, W1.z, W1.w);
        }

        // ---- gate exchange to smem ----
#pragma unroll
        for (int nf = 0; nf < 2; nf++) {
            int cb = warpN * 16 + nf * 8 + 2 * tig;
            *(float2*)&GT[rA * GT_PITCH2 + cb]       = make_float2(acc[nf][0], acc[nf][1]);
            *(float2*)&GT[(rA + 8) * GT_PITCH2 + cb] = make_float2(acc[nf][2], acc[nf][3]);
        }
        __syncthreads();

        // ---- epilogue: fast activations (5 MUFU.TANH per output) ----
        float hn[2];
#pragma unroll
        for (int s = 0; s < 2; s++) {
            int p = ep[s];
            if (act[s]) {
                float gi = GT[p * GT_PITCH2 + 0 * 32 + eh] + xg[s][0];
                float gf = GT[p * GT_PITCH2 + 1 * 32 + eh] + xg[s][1];
                float gg = GT[p * GT_PITCH2 + 2 * 32 + eh] + xg[s][2];
                float go = GT[p * GT_PITCH2 + 3 * 32 + eh] + xg[s][3];
                float cn = sig_fast(gf) * creg[s] + sig_fast(gi) * tanh_fast(gg);
                hn[s] = sig_fast(go) * tanh_fast(cn);
                creg[s] = cn;
                __stcg(&g_h2[(t + 1) & 1][(size_t)(p0 + ep[s]) * HH + hc0 + eh], hn[s]);
            }
        }

        // ---- arrive (release), overlap flat stores + next xW prefetch ----
        __syncthreads();
        if (tid == 0) bar_arrive(barp);
        size_t fsave[2] = { fis[0], fis[1] };
        bool   asave[2] = { act[0], act[1] };
        float  hsave[2] = { hn[0], hn[1] };
        if (t + 1 < tmax) prefetch_xw(t + 1);
#pragma unroll
        for (int s = 0; s < 2; s++)
            if (asave[s]) g_flat[fsave[s] * HH + hc0 + eh] = hsave[s];
        if (tid == 0) {
            unsigned target = 16u * (unsigned)(t + 1);
            while (bar_peek(barp) < target) __nanosleep(32);
        }
        __syncthreads();
    }
}

// ---------------- attention logits + concrete-relaxation gate ---------------
__global__ void k_att(const float* __restrict__ passedZ,
                      const float* __restrict__ fc2_W, const float* __restrict__ fc2_b,
                      const float* __restrict__ eps_u) {
    int gwarp = (blockIdx.x * blockDim.x + threadIdx.x) >> 5;
    int lane = threadIdx.x & 31;
    if (gwarp >= NN) return;
    const float* row = passedZ + (size_t)gwarp * DD;
    float s = 0.f;
#pragma unroll
    for (int k = lane; k < DD; k += 32) s += row[k] * fc2_W[k];
#pragma unroll
    for (int o = 16; o; o >>= 1) s += __shfl_xor_sync(0xffffffffu, s, o);
    if (lane == 0) {
        float logit = s + fc2_b[0];
        float eu = eps_u[gwarp];
        float eps = (2.0f * 1e-4f - 1.0f) * eu + (1.0f - 1e-4f);
        float gate = logf(eps) - logf(1.0f - eps) + logit;
        g_att[gwarp] = sigf(gate);
    }
}

// ---------------- gated segment sum ------------------------------------------
__global__ void k_seg(const int* __restrict__ lengths) {
    int b = blockIdx.x;
    int col = threadIdx.x;
    int off = g_off[b];
    int L = lengths[b];
    float acc = 0.f;
    for (int r = 0; r < L; r++) {
        int n = off + r;
        acc += g_flat[(size_t)n * HH + col] * g_att[n];
    }
    g_seg[(size_t)b * HH + col] = acc;
}

// ---------------- final tiny MLP ---------------------------------------------
__global__ void k_final(const float* __restrict__ mlp1_W, const float* __restrict__ mlp1_b,
                        const float* __restrict__ mlp2_W, const float* __restrict__ mlp2_b,
                        float* __restrict__ out) {
    __shared__ float hidden[16];
    int b = blockIdx.x;
    int tid = threadIdx.x;
    int w = tid >> 5, lane = tid & 31;
    const float* seg = &g_seg[(size_t)b * HH];
    float s = 0.f;
#pragma unroll
    for (int k = lane; k < HH; k += 32) s += seg[k] * mlp1_W[(size_t)w * HH + k];
#pragma unroll
    for (int o = 16; o; o >>= 1) s += __shfl_xor_sync(0xffffffffu, s, o);
    if (lane == 0) hidden[w] = s + mlp1_b[w];
    __syncthreads();
    if (tid < 2) {
        float o = mlp2_b[tid];
#pragma unroll
        for (int j = 0; j < 16; j++) o += hidden[j] * mlp2_W[tid * 16 + j];
        out[b * 2 + tid] = o;
    }
}

// -----------------------------------------------------------------------------
extern "C" void kernel_launch(void* const* d_in, const int* in_sizes, int n_in,
                              void* d_out, int out_size) {
    const float* lstm_input = (const float*)d_in[0];
    const float* eps_u      = (const float*)d_in[1];
    const float* W_ih       = (const float*)d_in[2];
    const float* W_hh       = (const float*)d_in[3];
    const float* b_ih       = (const float*)d_in[4];
    const float* b_hh       = (const float*)d_in[5];
    const float* fc1_W      = (const float*)d_in[6];
    const float* fc1_b      = (const float*)d_in[7];
    const float* fc2_W      = (const float*)d_in[8];
    const float* fc2_b      = (const float*)d_in[9];
    const float* mlp1_W     = (const float*)d_in[10];
    const float* mlp1_b     = (const float*)d_in[11];
    const float* mlp2_W     = (const float*)d_in[12];
    const float* mlp2_b     = (const float*)d_in[13];
    const int*   lengths    = (const int*)d_in[14];

    float* out = (float*)d_out;
    float* passedZ = out + BP * 2;   // tuple order: final[256,2] then passed_Z[N,512]

    float *xw, *flat;
    cudaGetSymbolAddress((void**)&xw, g_xW);
    cudaGetSymbolAddress((void**)&flat, g_flat);

    cudaFuncSetAttribute(tgemm_mma, cudaFuncAttributeMaxDynamicSharedMemorySize, GEMM_SMEM);
    cudaFuncSetAttribute(k_lstm_persist, cudaFuncAttributeMaxDynamicSharedMemorySize, PSM3);

    // 1. init states/offsets/barriers
    k_init<<<(2 * BP * HH + 255) / 256, 256>>>(lengths);

    // 2. pack W_hh into tf32 fragment order
    k_prepw<<<(GG * 128 + 255) / 256, 256>>>(W_hh);

    // 3. xW = X @ W_ih^T + b_ih + b_hh   (tf32 tensor cores)
    tgemm_mma<<<dim3(GG / 128, NN / 128), 256, GEMM_SMEM>>>(lstm_input, W_ih, b_ih, b_hh, xw, GG);

    // 4. full LSTM recurrence in ONE persistent launch (tf32 mma)
    k_lstm_persist<<<dim3(8, 16), 512, PSM3>>>(lengths);

    // 5. passed_Z = flat @ fc1_W^T + fc1_b  -> straight into d_out
    tgemm_mma<<<dim3(DD / 128, NN / 128), 256, GEMM_SMEM>>>(flat, fc1_W, fc1_b, nullptr, passedZ, DD);

    // 6. attention gate per flat row
    k_att<<<(NN * 32 + 255) / 256, 256>>>(passedZ, fc2_W, fc2_b, eps_u);

    // 7. gated per-person segment sum
    k_seg<<<BP, HH>>>(lengths);

    // 8. final MLP -> out[0:512]
    k_final<<<BP, 512>>>(mlp1_W, mlp1_b, mlp2_W, mlp2_b, out);
}

// round 12
// speedup vs baseline: 6.7954x; 1.5108x over previous
#include <cuda_runtime.h>
#include <cuda.h>
#include <cuda_fp16.h>
#include <math.h>
#include <stdint.h>

// Problem constants (fixed by the dataset: B=256, D=H=512, lengths=128..383)
#define NN 65408
#define BP 256
#define DD 512
#define HH 512
#define GG 2048
#define TT 383
#define KK 512

// ---------------- device scratch ---------------------------------------------
__device__ __align__(16) float g_xW[(size_t)NN * GG];
__device__ __align__(16) float g_flat[(size_t)NN * HH];
__device__ __align__(16) float g_att[NN];
__device__ __align__(16) float g_seg[BP * HH];
// h in packed fp16 A-fragment layout, double-buffered:
// [parity][tile(=p/16)][chunk(=k/16)][lane(grp*4+tig)] = uint4 {a0,a1,a2,a3}
__device__ __align__(16) uint4 g_HF[2][16 * 32 * 32];
// W_hh packed fp16 B-fragment order: [(n*32 + c)*4 + tig] = uint2 {b0(k lo pair), b1(k hi pair)}
__device__ __align__(16) uint2 g_GWH[(size_t)GG * 128];
__device__ int      g_off[BP];
__device__ __align__(128) unsigned g_bar[8 * 128];

__device__ __forceinline__ float sigf(float x) { return 1.0f / (1.0f + expf(-x)); }

__device__ __forceinline__ float tanh_fast(float x) {
    float r; asm("tanh.approx.f32 %0, %1;" : "=f"(r) : "f"(x)); return r;
}
__device__ __forceinline__ float sig_fast(float x) {
    return fmaf(tanh_fast(0.5f * x), 0.5f, 0.5f);
}
__device__ __forceinline__ uint32_t f2tf32(float f) {
    uint32_t r; asm("cvt.rna.tf32.f32 %0, %1;" : "=r"(r) : "f"(f)); return r;
}
__device__ __forceinline__ void mma_tf32(float* c,
                                         uint32_t a0, uint32_t a1, uint32_t a2, uint32_t a3,
                                         uint32_t b0, uint32_t b1) {
    asm volatile("mma.sync.aligned.m16n8k8.row.col.f32.tf32.tf32.f32 "
        "{%0,%1,%2,%3}, {%4,%5,%6,%7}, {%8,%9}, {%0,%1,%2,%3};"
        : "+f"(c[0]), "+f"(c[1]), "+f"(c[2]), "+f"(c[3])
        : "r"(a0), "r"(a1), "r"(a2), "r"(a3), "r"(b0), "r"(b1));
}
__device__ __forceinline__ void mma_f16(float* c,
                                        uint32_t a0, uint32_t a1, uint32_t a2, uint32_t a3,
                                        uint32_t b0, uint32_t b1) {
    asm volatile("mma.sync.aligned.m16n8k16.row.col.f32.f16.f16.f32 "
        "{%0,%1,%2,%3}, {%4,%5,%6,%7}, {%8,%9}, {%0,%1,%2,%3};"
        : "+f"(c[0]), "+f"(c[1]), "+f"(c[2]), "+f"(c[3])
        : "r"(a0), "r"(a1), "r"(a2), "r"(a3), "r"(b0), "r"(b1));
}
__device__ __forceinline__ void bar_arrive(unsigned* p) {
    asm volatile("red.release.gpu.global.add.u32 [%0], 1;" :: "l"(p) : "memory");
}
__device__ __forceinline__ unsigned bar_peek(const unsigned* p) {
    unsigned v;
    asm volatile("ld.acquire.gpu.global.u32 %0, [%1];" : "=r"(v) : "l"(p) : "memory");
    return v;
}
__device__ __forceinline__ uint4 ldcg16(const uint4* p) {
    uint4 v;
    asm volatile("ld.global.cg.v4.u32 {%0,%1,%2,%3}, [%4];"
        : "=r"(v.x), "=r"(v.y), "=r"(v.z), "=r"(v.w) : "l"(p));
    return v;
}

// =================== tf32 mma.sync NT GEMM (unchanged) ======================
#define GPITCH 36
#define STAGE_F (128 * GPITCH)
#define GEMM_SMEM (4 * STAGE_F * 4)

__global__ void __launch_bounds__(256)
tgemm_mma(const float* __restrict__ A, const float* __restrict__ Bm,
          const float* __restrict__ bias1, const float* __restrict__ bias2,
          float* __restrict__ C, int Ncols) {
    extern __shared__ __align__(16) float sm[];
    float* As[2] = { sm,           sm + 2 * STAGE_F };
    float* Bs[2] = { sm + STAGE_F, sm + 3 * STAGE_F };

    const int tid = threadIdx.x;
    const int wid = tid >> 5, lane = tid & 31;
    const int grp = lane >> 2, tig = lane & 3;
    const int warpM = wid >> 2, warpN = wid & 3;
    const size_t m0 = (size_t)blockIdx.y * 128;
    const int    n0 = blockIdx.x * 128;

    const int lrow = tid >> 1;
    const int lcb  = (tid & 1) * 16;
    const float* Ag = A  + (m0 + lrow) * KK;
    const float* Bg = Bm + (size_t)(n0 + lrow) * KK;

    float4 ar[4], br[4];
    auto ldchunk = [&](int c) {
#pragma unroll
        for (int q = 0; q < 4; q++) {
            ar[q] = *(const float4*)&Ag[c * 32 + lcb + q * 4];
            br[q] = *(const float4*)&Bg[c * 32 + lcb + q * 4];
        }
    };
    auto cvt4 = [](float4 v) {
        return make_uint4(f2tf32(v.x), f2tf32(v.y), f2tf32(v.z), f2tf32(v.w));
    };
    auto stchunk = [&](int s) {
        float* a = As[s] + lrow * GPITCH + lcb;
        float* b = Bs[s] + lrow * GPITCH + lcb;
#pragma unroll
        for (int q = 0; q < 4; q++) {
            *(uint4*)&a[q * 4] = cvt4(ar[q]);
            *(uint4*)&b[q * 4] = cvt4(br[q]);
        }
    };

    float acc[4][4][4];
#pragma unroll
    for (int i = 0; i < 4; i++)
#pragma unroll
        for (int j = 0; j < 4; j++)
#pragma unroll
            for (int k = 0; k < 4; k++) acc[i][j][k] = 0.f;

    ldchunk(0); stchunk(0);
    __syncthreads();

    for (int c = 0; c < KK / 32; c++) {
        const int s = c & 1;
        if (c + 1 < KK / 32) ldchunk(c + 1);

        const float* Aw = As[s] + (warpM * 64 + grp) * GPITCH;
        const float* Bw = Bs[s] + (warpN * 32 + grp) * GPITCH;
#pragma unroll
        for (int k0 = 0; k0 < 32; k0 += 8) {
            uint32_t af[4][4], bf[4][2];
#pragma unroll
            for (int mf = 0; mf < 4; mf++) {
                const float* p = Aw + mf * 16 * GPITCH + k0;
                af[mf][0] = __float_as_uint(p[tig]);
                af[mf][1] = __float_as_uint(p[8 * GPITCH + tig]);
                af[mf][2] = __float_as_uint(p[tig + 4]);
                af[mf][3] = __float_as_uint(p[8 * GPITCH + tig + 4]);
            }
#pragma unroll
            for (int nf = 0; nf < 4; nf++) {
                const float* p = Bw + nf * 8 * GPITCH + k0;
                bf[nf][0] = __float_as_uint(p[tig]);
                bf[nf][1] = __float_as_uint(p[tig + 4]);
            }
#pragma unroll
            for (int mf = 0; mf < 4; mf++)
#pragma unroll
                for (int nf = 0; nf < 4; nf++)
                    mma_tf32(acc[mf][nf],
                             af[mf][0], af[mf][1], af[mf][2], af[mf][3],
                             bf[nf][0], bf[nf][1]);
        }
        __syncthreads();
        if (c + 1 < KK / 32) { stchunk((c + 1) & 1); __syncthreads(); }
    }

#pragma unroll
    for (int mf = 0; mf < 4; mf++) {
        size_t r0 = m0 + warpM * 64 + mf * 16 + grp;
#pragma unroll
        for (int nf = 0; nf < 4; nf++) {
            int col = n0 + warpN * 32 + nf * 8 + 2 * tig;
            float b0 = bias1[col], b1 = bias1[col + 1];
            if (bias2) { b0 += bias2[col]; b1 += bias2[col + 1]; }
            float2 v0 = { acc[mf][nf][0] + b0, acc[mf][nf][1] + b1 };
            float2 v1 = { acc[mf][nf][2] + b0, acc[mf][nf][3] + b1 };
            *(float2*)&C[r0 * (size_t)Ncols + col] = v0;
            *(float2*)&C[(r0 + 8) * (size_t)Ncols + col] = v1;
        }
    }
}

// ---------------- init --------------------------------------------------------
__global__ void k_init(const int* __restrict__ lengths) {
    int tid = blockIdx.x * blockDim.x + threadIdx.x;
    if (tid < 2 * 16 * 32 * 32 * 4) ((uint32_t*)g_HF)[tid] = 0u;   // h0 = 0 (fp16 zeros)
    if (tid < BP * HH) g_seg[tid] = 0.f;
    if (tid < 8 * 128) g_bar[tid] = 0u;
    if (tid == 0) {
        int acc = 0;
        for (int b = 0; b < BP; b++) { g_off[b] = acc; acc += lengths[b]; }
    }
}

// ---------------- prep: pack W_hh into fp16 B-fragment order ----------------
// g_GWH[(n*32 + c)*4 + tig] = { half2(w[16c+2tig], w[16c+2tig+1]),
//                               half2(w[16c+2tig+8], w[16c+2tig+9]) }
__global__ void k_prepw(const float* __restrict__ W) {
    int id = blockIdx.x * blockDim.x + threadIdx.x;
    if (id >= GG * 128) return;
    int n = id >> 7;
    int r = id & 127;
    int c = r >> 2, tig = r & 3;
    const float* wr = W + (size_t)n * KK + 16 * c;
    __half2 b0 = __floats2half2_rn(wr[2 * tig], wr[2 * tig + 1]);
    __half2 b1 = __floats2half2_rn(wr[2 * tig + 8], wr[2 * tig + 9]);
    uint2 v;
    memcpy(&v.x, &b0, 4); memcpy(&v.y, &b1, 4);
    g_GWH[id] = v;
}

// ---------------- persistent LSTM recurrence (fp16 mma, 512 thr) ------------
// grid (8 pgroups, 16 cgroups). CTA: 32 persons x 128 gatecols.
// FULL W slice resident in smem as fp16 (zero W L2 traffic in the loop).
// h passed between steps in packed fp16 A-fragment global layout.
#define WPITCH16 33                                    // chunk slots per W row (pad)
#define WH_BYTES (128 * WPITCH16 * 32)                 // 135168 B
#define HA_BYTES (2048 * 16)                           // 32768 B  (2 tiles x 32 chunks x 32 lanes)
#define GT_PITCH2 136
#define GT_BYTES (32 * GT_PITCH2 * 4)                  // 17408 B
#define PSM4 (WH_BYTES + HA_BYTES + GT_BYTES)          // 185344 B

__global__ void __launch_bounds__(512)
k_lstm_persist(const int* __restrict__ lengths) {
    extern __shared__ __align__(16) char smraw[];
    uint2* WH = (uint2*)smraw;                         // W fp16 frags
    uint4* HA = (uint4*)(smraw + WH_BYTES);            // h fp16 frags (2 tiles)
    float* GT = (float*)(smraw + WH_BYTES + HA_BYTES); // gate exchange

    __shared__ int len_s[32];
    __shared__ int off_s[32];
    __shared__ int s_tmax;

    const int tid = threadIdx.x;
    const int pg = blockIdx.x, cg = blockIdx.y;
    const int p0 = pg * 32, hc0 = cg * 32;
    const int wid = tid >> 5, lane = tid & 31;
    const int grp = lane >> 2, tig = lane & 3;
    const int warpM = wid >> 3, warpN = wid & 7;
    unsigned* barp = &g_bar[pg * 128];

    if (wid == 0) {
        int L = lengths[p0 + lane];
        len_s[lane] = L;
        off_s[lane] = g_off[p0 + lane];
        int m = L;
#pragma unroll
        for (int o = 16; o; o >>= 1) m = max(m, __shfl_xor_sync(0xffffffffu, m, o));
        if (lane == 0) s_tmax = m;
    }

    // ---- preload FULL W slice (128 rows x 512 k) as fp16 frags ----
    // local row lr -> global W row: (lr>>5)*HH + hc0 + (lr&31)
#pragma unroll
    for (int i = 0; i < 16; i++) {
        int gidx = tid + i * 512;          // 0..8191 uint4 copies
        int lr = gidx >> 6;
        int rem = gidx & 63;
        int c = rem >> 1, hf = rem & 1;
        int n = (lr >> 5) * HH + hc0 + (lr & 31);
        const uint4* src = (const uint4*)g_GWH + ((size_t)(n * 32 + c) * 2 + hf);
        uint4* dst = (uint4*)WH + ((size_t)(lr * WPITCH16 + c) * 2 + hf);
        *dst = *src;
    }
    __syncthreads();
    const int tmax = s_tmax;

    // per-warp W smem pointers (uint2 units)
    const int lr0 = warpN * 16 + grp;
    const int lr1 = lr0 + 8;
    const uint2* W0p = WH + (size_t)lr0 * WPITCH16 * 4 + tig;
    const uint2* W1p = WH + (size_t)lr1 * WPITCH16 * 4 + tig;

    const int rA = 16 * warpM + grp;
    const uint4* HAw = HA + (size_t)warpM * 1024 + lane;   // +32 per chunk

    // epilogue ownership: 2 outputs per thread
    const int ep[2] = { tid >> 5, (tid + 512) >> 5 };      // person (0..31)
    const int eh = tid & 31;
    float creg[2] = { 0.f, 0.f };

    // packed-h store addressing (k-part constant per thread)
    const int kk = hc0 + eh;
    const int kc = kk >> 4, klo = kk & 15;
    const int ktig = (klo & 7) >> 1, ksub = klo & 1, khi = (klo >= 8);
    size_t hoff[2];
#pragma unroll
    for (int s = 0; s < 2; s++) {
        int pl = ep[s];
        int tile_g = pg * 2 + (pl >> 4);
        int r16 = pl & 15;
        int grp8 = r16 & 7, hiM = r16 >> 3;
        int slot = hiM + 2 * khi;
        hoff[s] = ((size_t)(tile_g * 32 + kc) * 32 + grp8 * 4 + ktig) * 16 + slot * 4 + ksub * 2;
    }

    // xW prefetch state
    float xg[2][4];
    bool  act[2];
    size_t fis[2];
    auto prefetch_xw = [&](int t) {
#pragma unroll
        for (int s = 0; s < 2; s++) {
            int p = ep[s];
            act[s] = (t < len_s[p]);
            if (act[s]) {
                fis[s] = (size_t)(off_s[p] + t);
                size_t xb = fis[s] * GG + hc0 + eh;
#pragma unroll
                for (int g = 0; g < 4; g++) xg[s][g] = __ldcg(&g_xW[xb + g * HH]);
            } else {
                fis[s] = 0;
                xg[s][0] = xg[s][1] = xg[s][2] = xg[s][3] = 0.f;
            }
        }
    };
    prefetch_xw(0);

    for (int t = 0; t < tmax; t++) {
        // ---- fill HA: straight coalesced copy of pre-packed fp16 h ----
        const uint4* hsrc = &g_HF[t & 1][(size_t)pg * 2048];
#pragma unroll
        for (int i = 0; i < 4; i++) {
            int idx = tid + i * 512;       // 0..2047
            HA[idx] = ldcg16(hsrc + idx);
        }
        __syncthreads();

        // ---- 32x128x512 gates GEMM: fp16 m16n8k16, fp32 accum ----
        float acc[2][4];
#pragma unroll
        for (int i = 0; i < 2; i++)
#pragma unroll
            for (int j = 0; j < 4; j++) acc[i][j] = 0.f;

#pragma unroll 8
        for (int c = 0; c < 32; c++) {
            uint4 Af = HAw[c * 32];
            uint2 W0 = W0p[c * 4];
            uint2 W1 = W1p[c * 4];
            mma_f16(acc[0], Af.x, Af.y, Af.z, Af.w, W0.x, W0.y);
            mma_f16(acc[1], Af.x, Af.y, Af.z, Af.w, W1.x, W1.y);
        }

        // ---- gate exchange to smem ----
#pragma unroll
        for (int nf = 0; nf < 2; nf++) {
            int cb = warpN * 16 + nf * 8 + 2 * tig;
            *(float2*)&GT[rA * GT_PITCH2 + cb]       = make_float2(acc[nf][0], acc[nf][1]);
            *(float2*)&GT[(rA + 8) * GT_PITCH2 + cb] = make_float2(acc[nf][2], acc[nf][3]);
        }
        __syncthreads();

        // ---- epilogue: fast activations + state update (c in regs) ----
        float hn[2];
        char* hdst = (char*)&g_HF[(t + 1) & 1][0];
#pragma unroll
        for (int s = 0; s < 2; s++) {
            int p = ep[s];
            if (act[s]) {
                float gi = GT[p * GT_PITCH2 + 0 * 32 + eh] + xg[s][0];
                float gf = GT[p * GT_PITCH2 + 1 * 32 + eh] + xg[s][1];
                float gg = GT[p * GT_PITCH2 + 2 * 32 + eh] + xg[s][2];
                float go = GT[p * GT_PITCH2 + 3 * 32 + eh] + xg[s][3];
                float cn = sig_fast(gf) * creg[s] + sig_fast(gi) * tanh_fast(gg);
                hn[s] = sig_fast(go) * tanh_fast(cn);
                creg[s] = cn;
                *(__half*)(hdst + hoff[s]) = __float2half_rn(hn[s]);
            }
        }

        // ---- arrive (release), overlap flat stores + next xW prefetch ----
        __syncthreads();
        if (tid == 0) bar_arrive(barp);
        size_t fsave[2] = { fis[0], fis[1] };
        bool   asave[2] = { act[0], act[1] };
        float  hsave[2] = { hn[0], hn[1] };
        if (t + 1 < tmax) prefetch_xw(t + 1);
#pragma unroll
        for (int s = 0; s < 2; s++)
            if (asave[s]) g_flat[fsave[s] * HH + hc0 + eh] = hsave[s];
        if (tid == 0) {
            unsigned target = 16u * (unsigned)(t + 1);
            while (bar_peek(barp) < target) __nanosleep(32);
        }
        __syncthreads();
    }
}

// ---------------- attention logits + concrete-relaxation gate ---------------
__global__ void k_att(const float* __restrict__ passedZ,
                      const float* __restrict__ fc2_W, const float* __restrict__ fc2_b,
                      const float* __restrict__ eps_u) {
    int gwarp = (blockIdx.x * blockDim.x + threadIdx.x) >> 5;
    int lane = threadIdx.x & 31;
    if (gwarp >= NN) return;
    const float* row = passedZ + (size_t)gwarp * DD;
    float s = 0.f;
#pragma unroll
    for (int k = lane; k < DD; k += 32) s += row[k] * fc2_W[k];
#pragma unroll
    for (int o = 16; o; o >>= 1) s += __shfl_xor_sync(0xffffffffu, s, o);
    if (lane == 0) {
        float logit = s + fc2_b[0];
        float eu = eps_u[gwarp];
        float eps = (2.0f * 1e-4f - 1.0f) * eu + (1.0f - 1e-4f);
        float gate = logf(eps) - logf(1.0f - eps) + logit;
        g_att[gwarp] = sigf(gate);
    }
}

// ---------------- gated segment sum ------------------------------------------
__global__ void k_seg(const int* __restrict__ lengths) {
    int b = blockIdx.x;
    int col = threadIdx.x;
    int off = g_off[b];
    int L = lengths[b];
    float acc = 0.f;
    for (int r = 0; r < L; r++) {
        int n = off + r;
        acc += g_flat[(size_t)n * HH + col] * g_att[n];
    }
    g_seg[(size_t)b * HH + col] = acc;
}

// ---------------- final tiny MLP ---------------------------------------------
__global__ void k_final(const float* __restrict__ mlp1_W, const float* __restrict__ mlp1_b,
                        const float* __restrict__ mlp2_W, const float* __restrict__ mlp2_b,
                        float* __restrict__ out) {
    __shared__ float hidden[16];
    int b = blockIdx.x;
    int tid = threadIdx.x;
    int w = tid >> 5, lane = tid & 31;
    const float* seg = &g_seg[(size_t)b * HH];
    float s = 0.f;
#pragma unroll
    for (int k = lane; k < HH; k += 32) s += seg[k] * mlp1_W[(size_t)w * HH + k];
#pragma unroll
    for (int o = 16; o; o >>= 1) s += __shfl_xor_sync(0xffffffffu, s, o);
    if (lane == 0) hidden[w] = s + mlp1_b[w];
    __syncthreads();
    if (tid < 2) {
        float o = mlp2_b[tid];
#pragma unroll
        for (int j = 0; j < 16; j++) o += hidden[j] * mlp2_W[tid * 16 + j];
        out[b * 2 + tid] = o;
    }
}

// -----------------------------------------------------------------------------
extern "C" void kernel_launch(void* const* d_in, const int* in_sizes, int n_in,
                              void* d_out, int out_size) {
    const float* lstm_input = (const float*)d_in[0];
    const float* eps_u      = (const float*)d_in[1];
    const float* W_ih       = (const float*)d_in[2];
    const float* W_hh       = (const float*)d_in[3];
    const float* b_ih       = (const float*)d_in[4];
    const float* b_hh       = (const float*)d_in[5];
    const float* fc1_W      = (const float*)d_in[6];
    const float* fc1_b      = (const float*)d_in[7];
    const float* fc2_W      = (const float*)d_in[8];
    const float* fc2_b      = (const float*)d_in[9];
    const float* mlp1_W     = (const float*)d_in[10];
    const float* mlp1_b     = (const float*)d_in[11];
    const float* mlp2_W     = (const float*)d_in[12];
    const float* mlp2_b     = (const float*)d_in[13];
    const int*   lengths    = (const int*)d_in[14];

    float* out = (float*)d_out;
    float* passedZ = out + BP * 2;   // tuple order: final[256,2] then passed_Z[N,512]

    float *xw, *flat;
    cudaGetSymbolAddress((void**)&xw, g_xW);
    cudaGetSymbolAddress((void**)&flat, g_flat);

    cudaFuncSetAttribute(tgemm_mma, cudaFuncAttributeMaxDynamicSharedMemorySize, GEMM_SMEM);
    cudaFuncSetAttribute(k_lstm_persist, cudaFuncAttributeMaxDynamicSharedMemorySize, PSM4);

    // 1. init states/offsets/barriers
    k_init<<<(2 * 16 * 32 * 32 * 4 + 255) / 256, 256>>>(lengths);

    // 2. pack W_hh into fp16 fragment order
    k_prepw<<<(GG * 128 + 255) / 256, 256>>>(W_hh);

    // 3. xW = X @ W_ih^T + b_ih + b_hh   (tf32 tensor cores)
    tgemm_mma<<<dim3(GG / 128, NN / 128), 256, GEMM_SMEM>>>(lstm_input, W_ih, b_ih, b_hh, xw, GG);

    // 4. full LSTM recurrence in ONE persistent launch (fp16 mma, W smem-resident)
    k_lstm_persist<<<dim3(8, 16), 512, PSM4>>>(lengths);

    // 5. passed_Z = flat @ fc1_W^T + fc1_b  -> straight into d_out
    tgemm_mma<<<dim3(DD / 128, NN / 128), 256, GEMM_SMEM>>>(flat, fc1_W, fc1_b, nullptr, passedZ, DD);

    // 6. attention gate per flat row
    k_att<<<(NN * 32 + 255) / 256, 256>>>(passedZ, fc2_W, fc2_b, eps_u);

    // 7. gated per-person segment sum
    k_seg<<<BP, HH>>>(lengths);

    // 8. final MLP -> out[0:512]
    k_final<<<BP, 512>>>(mlp1_W, mlp1_b, mlp2_W, mlp2_b, out);
}

// round 13
// speedup vs baseline: 7.6958x; 1.1325x over previous
#include <cuda_runtime.h>
#include <cuda.h>
#include <cuda_fp16.h>
#include <math.h>
#include <stdint.h>

// Problem constants (fixed by the dataset: B=256, D=H=512, lengths=128..383)
#define NN 65408
#define BP 256
#define DD 512
#define HH 512
#define GG 2048
#define TT 383
#define KK 512

// ---------------- device scratch ---------------------------------------------
__device__ __align__(16) float g_xW[(size_t)NN * GG];
__device__ __align__(16) float g_flat[(size_t)NN * HH];
__device__ __align__(16) float g_att[NN];
__device__ __align__(16) float g_seg[BP * HH];
// h in packed fp16 A-fragment layout, double-buffered
__device__ __align__(16) uint4 g_HF[2][16 * 32 * 32];
// W_hh packed fp16 B-fragment order
__device__ __align__(16) uint2 g_GWH[(size_t)GG * 128];
__device__ int      g_off[BP];
__device__ __align__(128) unsigned g_bar[8 * 128];

__device__ __forceinline__ float sigf(float x) { return 1.0f / (1.0f + expf(-x)); }

__device__ __forceinline__ float tanh_fast(float x) {
    float r; asm("tanh.approx.f32 %0, %1;" : "=f"(r) : "f"(x)); return r;
}
__device__ __forceinline__ float sig_fast(float x) {
    return fmaf(tanh_fast(0.5f * x), 0.5f, 0.5f);
}
__device__ __forceinline__ uint32_t packh2(float a, float b) {
    __half2 h = __floats2half2_rn(a, b);
    uint32_t r; memcpy(&r, &h, 4); return r;
}
__device__ __forceinline__ void mma_f16(float* c,
                                        uint32_t a0, uint32_t a1, uint32_t a2, uint32_t a3,
                                        uint32_t b0, uint32_t b1) {
    asm volatile("mma.sync.aligned.m16n8k16.row.col.f32.f16.f16.f32 "
        "{%0,%1,%2,%3}, {%4,%5,%6,%7}, {%8,%9}, {%0,%1,%2,%3};"
        : "+f"(c[0]), "+f"(c[1]), "+f"(c[2]), "+f"(c[3])
        : "r"(a0), "r"(a1), "r"(a2), "r"(a3), "r"(b0), "r"(b1));
}
__device__ __forceinline__ void bar_arrive(unsigned* p) {
    asm volatile("red.release.gpu.global.add.u32 [%0], 1;" :: "l"(p) : "memory");
}
__device__ __forceinline__ unsigned bar_peek(const unsigned* p) {
    unsigned v;
    asm volatile("ld.acquire.gpu.global.u32 %0, [%1];" : "=r"(v) : "l"(p) : "memory");
    return v;
}
__device__ __forceinline__ uint4 ldcg16(const uint4* p) {
    uint4 v;
    asm volatile("ld.global.cg.v4.u32 {%0,%1,%2,%3}, [%4];"
        : "=r"(v.x), "=r"(v.y), "=r"(v.z), "=r"(v.w) : "l"(p));
    return v;
}

// =================== fp16 mma.sync NT GEMM: C = A @ B^T + bias ==============
// A:[M,512] fp32 row-major, B:[Ncols,512] fp32 row-major; operands cvt to fp16
// at smem store. CTA 128x128, warp 64x32, K-chunk 32 double-buffered.
// Stage layout: uint (half2) per (row, kpair), pitch 20 (conflict-free).
#define GP16 20
#define STAGE_U (128 * GP16)
#define GEMM_SMEM (4 * STAGE_U * 4)          // 40960 B

__global__ void __launch_bounds__(256)
tgemm_f16(const float* __restrict__ A, const float* __restrict__ Bm,
          const float* __restrict__ bias1, const float* __restrict__ bias2,
          float* __restrict__ C, int Ncols) {
    extern __shared__ __align__(16) uint32_t smu[];
    uint32_t* As[2] = { smu,           smu + 2 * STAGE_U };
    uint32_t* Bs[2] = { smu + STAGE_U, smu + 3 * STAGE_U };

    const int tid = threadIdx.x;
    const int wid = tid >> 5, lane = tid & 31;
    const int grp = lane >> 2, tig = lane & 3;
    const int warpM = wid >> 2, warpN = wid & 3;
    const size_t m0 = (size_t)blockIdx.y * 128;
    const int    n0 = blockIdx.x * 128;

    const int lrow = tid >> 1;
    const int lcb  = (tid & 1) * 16;            // float offset within 32-float chunk row
    const int jb   = (tid & 1) * 8;             // half2 (uint) offset
    const float* Ag = A  + (m0 + lrow) * KK;
    const float* Bg = Bm + (size_t)(n0 + lrow) * KK;

    float4 ar[4], br[4];
    auto ldchunk = [&](int c) {
#pragma unroll
        for (int q = 0; q < 4; q++) {
            ar[q] = *(const float4*)&Ag[c * 32 + lcb + q * 4];
            br[q] = *(const float4*)&Bg[c * 32 + lcb + q * 4];
        }
    };
    auto stchunk = [&](int s) {
        uint32_t* a = As[s] + lrow * GP16 + jb;
        uint32_t* b = Bs[s] + lrow * GP16 + jb;
        uint4 va0 = make_uint4(packh2(ar[0].x, ar[0].y), packh2(ar[0].z, ar[0].w),
                               packh2(ar[1].x, ar[1].y), packh2(ar[1].z, ar[1].w));
        uint4 va1 = make_uint4(packh2(ar[2].x, ar[2].y), packh2(ar[2].z, ar[2].w),
                               packh2(ar[3].x, ar[3].y), packh2(ar[3].z, ar[3].w));
        uint4 vb0 = make_uint4(packh2(br[0].x, br[0].y), packh2(br[0].z, br[0].w),
                               packh2(br[1].x, br[1].y), packh2(br[1].z, br[1].w));
        uint4 vb1 = make_uint4(packh2(br[2].x, br[2].y), packh2(br[2].z, br[2].w),
                               packh2(br[3].x, br[3].y), packh2(br[3].z, br[3].w));
        *(uint4*)(a + 0) = va0; *(uint4*)(a + 4) = va1;
        *(uint4*)(b + 0) = vb0; *(uint4*)(b + 4) = vb1;
    };

    float acc[4][4][4];
#pragma unroll
    for (int i = 0; i < 4; i++)
#pragma unroll
        for (int j = 0; j < 4; j++)
#pragma unroll
            for (int k = 0; k < 4; k++) acc[i][j][k] = 0.f;

    ldchunk(0); stchunk(0);
    __syncthreads();

    for (int c = 0; c < KK / 32; c++) {
        const int s = c & 1;
        if (c + 1 < KK / 32) ldchunk(c + 1);

        const uint32_t* Aw = As[s] + (warpM * 64 + grp) * GP16;
        const uint32_t* Bw = Bs[s] + (warpN * 32 + grp) * GP16;
#pragma unroll
        for (int j0 = 0; j0 < 16; j0 += 8) {   // two k16 steps per 32-chunk
            uint32_t af[4][4], bf[4][2];
#pragma unroll
            for (int mf = 0; mf < 4; mf++) {
                const uint32_t* p = Aw + mf * 16 * GP16 + j0;
                af[mf][0] = p[tig];
                af[mf][1] = p[8 * GP16 + tig];
                af[mf][2] = p[tig + 4];
                af[mf][3] = p[8 * GP16 + tig + 4];
            }
#pragma unroll
            for (int nf = 0; nf < 4; nf++) {
                const uint32_t* p = Bw + nf * 8 * GP16 + j0;
                bf[nf][0] = p[tig];
                bf[nf][1] = p[tig + 4];
            }
#pragma unroll
            for (int mf = 0; mf < 4; mf++)
#pragma unroll
                for (int nf = 0; nf < 4; nf++)
                    mma_f16(acc[mf][nf],
                            af[mf][0], af[mf][1], af[mf][2], af[mf][3],
                            bf[nf][0], bf[nf][1]);
        }
        __syncthreads();
        if (c + 1 < KK / 32) { stchunk((c + 1) & 1); __syncthreads(); }
    }

#pragma unroll
    for (int mf = 0; mf < 4; mf++) {
        size_t r0 = m0 + warpM * 64 + mf * 16 + grp;
#pragma unroll
        for (int nf = 0; nf < 4; nf++) {
            int col = n0 + warpN * 32 + nf * 8 + 2 * tig;
            float b0 = bias1[col], b1 = bias1[col + 1];
            if (bias2) { b0 += bias2[col]; b1 += bias2[col + 1]; }
            float2 v0 = { acc[mf][nf][0] + b0, acc[mf][nf][1] + b1 };
            float2 v1 = { acc[mf][nf][2] + b0, acc[mf][nf][3] + b1 };
            *(float2*)&C[r0 * (size_t)Ncols + col] = v0;
            *(float2*)&C[(r0 + 8) * (size_t)Ncols + col] = v1;
        }
    }
}

// ---------------- init --------------------------------------------------------
__global__ void k_init(const int* __restrict__ lengths) {
    int tid = blockIdx.x * blockDim.x + threadIdx.x;
    if (tid < 2 * 16 * 32 * 32 * 4) ((uint32_t*)g_HF)[tid] = 0u;
    if (tid < BP * HH) g_seg[tid] = 0.f;
    if (tid < 8 * 128) g_bar[tid] = 0u;
    if (tid == 0) {
        int acc = 0;
        for (int b = 0; b < BP; b++) { g_off[b] = acc; acc += lengths[b]; }
    }
}

// ---------------- prep: pack W_hh into fp16 B-fragment order ----------------
__global__ void k_prepw(const float* __restrict__ W) {
    int id = blockIdx.x * blockDim.x + threadIdx.x;
    if (id >= GG * 128) return;
    int n = id >> 7;
    int r = id & 127;
    int c = r >> 2, tig = r & 3;
    const float* wr = W + (size_t)n * KK + 16 * c;
    uint2 v;
    v.x = packh2(wr[2 * tig], wr[2 * tig + 1]);
    v.y = packh2(wr[2 * tig + 8], wr[2 * tig + 9]);
    g_GWH[id] = v;
}

// ---------------- persistent LSTM recurrence (fp16 mma, 512 thr) ------------
#define WPITCH16 33
#define WH_BYTES (128 * WPITCH16 * 32)
#define HA_BYTES (2048 * 16)
#define GT_PITCH2 136
#define GT_BYTES (32 * GT_PITCH2 * 4)
#define PSM4 (WH_BYTES + HA_BYTES + GT_BYTES)

__global__ void __launch_bounds__(512)
k_lstm_persist(const int* __restrict__ lengths) {
    extern __shared__ __align__(16) char smraw[];
    uint2* WH = (uint2*)smraw;
    uint4* HA = (uint4*)(smraw + WH_BYTES);
    float* GT = (float*)(smraw + WH_BYTES + HA_BYTES);

    __shared__ int len_s[32];
    __shared__ int off_s[32];
    __shared__ int s_tmax;

    const int tid = threadIdx.x;
    const int pg = blockIdx.x, cg = blockIdx.y;
    const int p0 = pg * 32, hc0 = cg * 32;
    const int wid = tid >> 5, lane = tid & 31;
    const int grp = lane >> 2, tig = lane & 3;
    const int warpM = wid >> 3, warpN = wid & 7;
    unsigned* barp = &g_bar[pg * 128];

    if (wid == 0) {
        int L = lengths[p0 + lane];
        len_s[lane] = L;
        off_s[lane] = g_off[p0 + lane];
        int m = L;
#pragma unroll
        for (int o = 16; o; o >>= 1) m = max(m, __shfl_xor_sync(0xffffffffu, m, o));
        if (lane == 0) s_tmax = m;
    }

#pragma unroll
    for (int i = 0; i < 16; i++) {
        int gidx = tid + i * 512;
        int lr = gidx >> 6;
        int rem = gidx & 63;
        int c = rem >> 1, hf = rem & 1;
        int n = (lr >> 5) * HH + hc0 + (lr & 31);
        const uint4* src = (const uint4*)g_GWH + ((size_t)(n * 32 + c) * 2 + hf);
        uint4* dst = (uint4*)WH + ((size_t)(lr * WPITCH16 + c) * 2 + hf);
        *dst = *src;
    }
    __syncthreads();
    const int tmax = s_tmax;

    const int lr0 = warpN * 16 + grp;
    const int lr1 = lr0 + 8;
    const uint2* W0p = WH + (size_t)lr0 * WPITCH16 * 4 + tig;
    const uint2* W1p = WH + (size_t)lr1 * WPITCH16 * 4 + tig;

    const int rA = 16 * warpM + grp;
    const uint4* HAw = HA + (size_t)warpM * 1024 + lane;

    const int ep[2] = { tid >> 5, (tid + 512) >> 5 };
    const int eh = tid & 31;
    float creg[2] = { 0.f, 0.f };

    const int kk = hc0 + eh;
    const int kc = kk >> 4, klo = kk & 15;
    const int ktig = (klo & 7) >> 1, ksub = klo & 1, khi = (klo >= 8);
    size_t hoff[2];
#pragma unroll
    for (int s = 0; s < 2; s++) {
        int pl = ep[s];
        int tile_g = pg * 2 + (pl >> 4);
        int r16 = pl & 15;
        int grp8 = r16 & 7, hiM = r16 >> 3;
        int slot = hiM + 2 * khi;
        hoff[s] = ((size_t)(tile_g * 32 + kc) * 32 + grp8 * 4 + ktig) * 16 + slot * 4 + ksub * 2;
    }

    float xg[2][4];
    bool  act[2];
    size_t fis[2];
    auto prefetch_xw = [&](int t) {
#pragma unroll
        for (int s = 0; s < 2; s++) {
            int p = ep[s];
            act[s] = (t < len_s[p]);
            if (act[s]) {
                fis[s] = (size_t)(off_s[p] + t);
                size_t xb = fis[s] * GG + hc0 + eh;
#pragma unroll
                for (int g = 0; g < 4; g++) xg[s][g] = __ldcg(&g_xW[xb + g * HH]);
            } else {
                fis[s] = 0;
                xg[s][0] = xg[s][1] = xg[s][2] = xg[s][3] = 0.f;
            }
        }
    };
    prefetch_xw(0);

    for (int t = 0; t < tmax; t++) {
        const uint4* hsrc = &g_HF[t & 1][(size_t)pg * 2048];
#pragma unroll
        for (int i = 0; i < 4; i++) {
            int idx = tid + i * 512;
            HA[idx] = ldcg16(hsrc + idx);
        }
        __syncthreads();

        float acc[2][4];
#pragma unroll
        for (int i = 0; i < 2; i++)
#pragma unroll
            for (int j = 0; j < 4; j++) acc[i][j] = 0.f;

#pragma unroll 8
        for (int c = 0; c < 32; c++) {
            uint4 Af = HAw[c * 32];
            uint2 W0 = W0p[c * 4];
            uint2 W1 = W1p[c * 4];
            mma_f16(acc[0], Af.x, Af.y, Af.z, Af.w, W0.x, W0.y);
            mma_f16(acc[1], Af.x, Af.y, Af.z, Af.w, W1.x, W1.y);
        }

#pragma unroll
        for (int nf = 0; nf < 2; nf++) {
            int cb = warpN * 16 + nf * 8 + 2 * tig;
            *(float2*)&GT[rA * GT_PITCH2 + cb]       = make_float2(acc[nf][0], acc[nf][1]);
            *(float2*)&GT[(rA + 8) * GT_PITCH2 + cb] = make_float2(acc[nf][2], acc[nf][3]);
        }
        __syncthreads();

        float hn[2];
        char* hdst = (char*)&g_HF[(t + 1) & 1][0];
#pragma unroll
        for (int s = 0; s < 2; s++) {
            int p = ep[s];
            if (act[s]) {
                float gi = GT[p * GT_PITCH2 + 0 * 32 + eh] + xg[s][0];
                float gf = GT[p * GT_PITCH2 + 1 * 32 + eh] + xg[s][1];
                float gg = GT[p * GT_PITCH2 + 2 * 32 + eh] + xg[s][2];
                float go = GT[p * GT_PITCH2 + 3 * 32 + eh] + xg[s][3];
                float cn = sig_fast(gf) * creg[s] + sig_fast(gi) * tanh_fast(gg);
                hn[s] = sig_fast(go) * tanh_fast(cn);
                creg[s] = cn;
                *(__half*)(hdst + hoff[s]) = __float2half_rn(hn[s]);
            }
        }

        __syncthreads();
        if (tid == 0) bar_arrive(barp);
        size_t fsave[2] = { fis[0], fis[1] };
        bool   asave[2] = { act[0], act[1] };
        float  hsave[2] = { hn[0], hn[1] };
        if (t + 1 < tmax) prefetch_xw(t + 1);
#pragma unroll
        for (int s = 0; s < 2; s++)
            if (asave[s]) g_flat[fsave[s] * HH + hc0 + eh] = hsave[s];
        if (tid == 0) {
            unsigned target = 16u * (unsigned)(t + 1);
            while (bar_peek(barp) < target) __nanosleep(32);
        }
        __syncthreads();
    }
}

// ---------------- attention logits + concrete-relaxation gate ---------------
__global__ void k_att(const float* __restrict__ passedZ,
                      const float* __restrict__ fc2_W, const float* __restrict__ fc2_b,
                      const float* __restrict__ eps_u) {
    int gwarp = (blockIdx.x * blockDim.x + threadIdx.x) >> 5;
    int lane = threadIdx.x & 31;
    if (gwarp >= NN) return;
    const float* row = passedZ + (size_t)gwarp * DD;
    float s = 0.f;
#pragma unroll
    for (int k = lane; k < DD; k += 32) s += row[k] * fc2_W[k];
#pragma unroll
    for (int o = 16; o; o >>= 1) s += __shfl_xor_sync(0xffffffffu, s, o);
    if (lane == 0) {
        float logit = s + fc2_b[0];
        float eu = eps_u[gwarp];
        float eps = (2.0f * 1e-4f - 1.0f) * eu + (1.0f - 1e-4f);
        float gate = logf(eps) - logf(1.0f - eps) + logit;
        g_att[gwarp] = sigf(gate);
    }
}

// ---------------- gated segment sum ------------------------------------------
__global__ void k_seg(const int* __restrict__ lengths) {
    int b = blockIdx.x;
    int col = threadIdx.x;
    int off = g_off[b];
    int L = lengths[b];
    float acc = 0.f;
    for (int r = 0; r < L; r++) {
        int n = off + r;
        acc += g_flat[(size_t)n * HH + col] * g_att[n];
    }
    g_seg[(size_t)b * HH + col] = acc;
}

// ---------------- final tiny MLP ---------------------------------------------
__global__ void k_final(const float* __restrict__ mlp1_W, const float* __restrict__ mlp1_b,
                        const float* __restrict__ mlp2_W, const float* __restrict__ mlp2_b,
                        float* __restrict__ out) {
    __shared__ float hidden[16];
    int b = blockIdx.x;
    int tid = threadIdx.x;
    int w = tid >> 5, lane = tid & 31;
    const float* seg = &g_seg[(size_t)b * HH];
    float s = 0.f;
#pragma unroll
    for (int k = lane; k < HH; k += 32) s += seg[k] * mlp1_W[(size_t)w * HH + k];
#pragma unroll
    for (int o = 16; o; o >>= 1) s += __shfl_xor_sync(0xffffffffu, s, o);
    if (lane == 0) hidden[w] = s + mlp1_b[w];
    __syncthreads();
    if (tid < 2) {
        float o = mlp2_b[tid];
#pragma unroll
        for (int j = 0; j < 16; j++) o += hidden[j] * mlp2_W[tid * 16 + j];
        out[b * 2 + tid] = o;
    }
}

// -----------------------------------------------------------------------------
extern "C" void kernel_launch(void* const* d_in, const int* in_sizes, int n_in,
                              void* d_out, int out_size) {
    const float* lstm_input = (const float*)d_in[0];
    const float* eps_u      = (const float*)d_in[1];
    const float* W_ih       = (const float*)d_in[2];
    const float* W_hh       = (const float*)d_in[3];
    const float* b_ih       = (const float*)d_in[4];
    const float* b_hh       = (const float*)d_in[5];
    const float* fc1_W      = (const float*)d_in[6];
    const float* fc1_b      = (const float*)d_in[7];
    const float* fc2_W      = (const float*)d_in[8];
    const float* fc2_b      = (const float*)d_in[9];
    const float* mlp1_W     = (const float*)d_in[10];
    const float* mlp1_b     = (const float*)d_in[11];
    const float* mlp2_W     = (const float*)d_in[12];
    const float* mlp2_b     = (const float*)d_in[13];
    const int*   lengths    = (const int*)d_in[14];

    float* out = (float*)d_out;
    float* passedZ = out + BP * 2;   // tuple order: final[256,2] then passed_Z[N,512]

    float *xw, *flat;
    cudaGetSymbolAddress((void**)&xw, g_xW);
    cudaGetSymbolAddress((void**)&flat, g_flat);

    cudaFuncSetAttribute(tgemm_f16, cudaFuncAttributeMaxDynamicSharedMemorySize, GEMM_SMEM);
    cudaFuncSetAttribute(k_lstm_persist, cudaFuncAttributeMaxDynamicSharedMemorySize, PSM4);

    // 1. init states/offsets/barriers
    k_init<<<(2 * 16 * 32 * 32 * 4 + 255) / 256, 256>>>(lengths);

    // 2. pack W_hh into fp16 fragment order
    k_prepw<<<(GG * 128 + 255) / 256, 256>>>(W_hh);

    // 3. xW = X @ W_ih^T + b_ih + b_hh   (fp16 tensor cores, fp32 accum)
    tgemm_f16<<<dim3(GG / 128, NN / 128), 256, GEMM_SMEM>>>(lstm_input, W_ih, b_ih, b_hh, xw, GG);

    // 4. full LSTM recurrence in ONE persistent launch (fp16 mma, W smem-resident)
    k_lstm_persist<<<dim3(8, 16), 512, PSM4>>>(lengths);

    // 5. passed_Z = flat @ fc1_W^T + fc1_b  -> straight into d_out
    tgemm_f16<<<dim3(DD / 128, NN / 128), 256, GEMM_SMEM>>>(flat, fc1_W, fc1_b, nullptr, passedZ, DD);

    // 6. attention gate per flat row
    k_att<<<(NN * 32 + 255) / 256, 256>>>(passedZ, fc2_W, fc2_b, eps_u);

    // 7. gated per-person segment sum
    k_seg<<<BP, HH>>>(lengths);

    // 8. final MLP -> out[0:512]
    k_final<<<BP, 512>>>(mlp1_W, mlp1_b, mlp2_W, mlp2_b, out);
}